// round 5
// baseline (speedup 1.0000x reference)
#include <cuda_runtime.h>
#include <cstdint>

// ---------------- problem constants ----------------
#define NT     49
#define DIMC   128
#define HEADS  4
#define HD     32
#define WS     7
#define SCALEF 0.17677669529663687f   // 32^-0.5
#define THREADS 512

// ---------------- smem layout (float offsets) ----------------
#define QKV_STRIDE 396
#define X_STRIDE   132
#define M_STRIDE   53
#define P_STRIDE   66                   // gemm partial row stride
#define C_STRIDE   37                   // attention combine row stride (odd)

#define OFF_QKV  0
#define OFF_X    (NT * QKV_STRIDE)                  // 19404
#define OFF_W    (OFF_X + NT * X_STRIDE)            // 25872  two 64x128 buffers
#define OFF_MASK (OFF_W + 2 * 64 * 128)             // 42256
#define OFF_BT   (OFF_MASK + NT * M_STRIDE)         // 44853
#define OFF_BIAS (OFF_BT + 676)                     // 45529
#define OFF_RELF (OFF_BIAS + 512)                   // 46041
#define OFF_PART (OFF_RELF + 608)                   // 46649
#define SMEM_FLOATS (OFF_PART + 196 * C_STRIDE)     // 53901 (part buf: max(49*66, 196*37))
#define SMEM_BYTES  (SMEM_FLOATS * 4)               // 215604 (<227KB)

// ---------------- packed f32x2 helpers ----------------
__device__ __forceinline__ unsigned long long fma2(unsigned long long a,
                                                   unsigned long long b,
                                                   unsigned long long c) {
    unsigned long long d;
    asm("fma.rn.f32x2 %0, %1, %2, %3;" : "=l"(d) : "l"(a), "l"(b), "l"(c));
    return d;
}
__device__ __forceinline__ unsigned long long mul2(unsigned long long a,
                                                   unsigned long long b) {
    unsigned long long d;
    asm("mul.rn.f32x2 %0, %1, %2;" : "=l"(d) : "l"(a), "l"(b));
    return d;
}
__device__ __forceinline__ unsigned long long pack2(float a, float b) {
    unsigned long long r;
    asm("mov.b64 %0, {%1, %2};" : "=l"(r) : "r"(__float_as_uint(a)), "r"(__float_as_uint(b)));
    return r;
}
__device__ __forceinline__ float2 unpack2(unsigned long long v) {
    unsigned int lo, hi;
    asm("mov.b64 {%0, %1}, %2;" : "=r"(lo), "=r"(hi) : "l"(v));
    return make_float2(__uint_as_float(lo), __uint_as_float(hi));
}

// producer: copy half (32 rows) of one 64x128 weight chunk, xor-swizzled
__device__ __forceinline__ void load_wchunk_half(const float* __restrict__ src,
                                                 float* __restrict__ dst,
                                                 int lane, int half) {
    #pragma unroll
    for (int it = 0; it < 32; ++it) {
        int r = half * 32 + it;
        float4 v = ((const float4*)src)[r * 32 + lane];
        *(float4*)&dst[r * 128 + ((lane ^ (r & 7)) << 2)] = v;
    }
}

// half-K GEMM slice: rows 7*rg..7*rg+6, cols {lane, lane+32}, k4 in [16*kh, 16*kh+16)
__device__ __forceinline__ void mm_half(const float* __restrict__ s_xt,
                                        const float* __restrict__ s_wt,
                                        int rg, int kh, int lane, float res[7][2])
{
    unsigned long long acc[7][2];
    #pragma unroll
    for (int r = 0; r < 7; ++r) { acc[r][0] = 0ULL; acc[r][1] = 0ULL; }
    const int xr = lane & 7;
    const float* xbase = s_xt + (rg * 7) * X_STRIDE;
    const int k0 = kh * 16;
    #pragma unroll 4
    for (int k4 = k0; k4 < k0 + 16; ++k4) {
        const int wk = ((k4 ^ xr) << 2);
        ulonglong2 wv0 = *(const ulonglong2*)&s_wt[lane * 128 + wk];
        ulonglong2 wv1 = *(const ulonglong2*)&s_wt[(lane + 32) * 128 + wk];
        #pragma unroll
        for (int r = 0; r < 7; ++r) {
            ulonglong2 xv = *(const ulonglong2*)&xbase[r * X_STRIDE + (k4 << 2)];
            acc[r][0] = fma2(xv.x, wv0.x, acc[r][0]);
            acc[r][0] = fma2(xv.y, wv0.y, acc[r][0]);
            acc[r][1] = fma2(xv.x, wv1.x, acc[r][1]);
            acc[r][1] = fma2(xv.y, wv1.y, acc[r][1]);
        }
    }
    #pragma unroll
    for (int r = 0; r < 7; ++r)
        #pragma unroll
        for (int c = 0; c < 2; ++c) {
            float2 p = unpack2(acc[r][c]);
            res[r][c] = p.x + p.y;
        }
}

// attention partial over j in [jbeg, jend): fused scores->exp->acc, no e[] array
__device__ __forceinline__ void attn_partial(const float* __restrict__ s_qkv,
                                             const float* __restrict__ s_bt,
                                             const float* __restrict__ s_mask,
                                             const uint8_t* __restrict__ s_rel,
                                             int h, int i, int jbeg, int jend,
                                             float& sumOut, unsigned long long acc[16])
{
    unsigned long long qv[16];
    const unsigned long long SC2 = pack2(SCALEF, SCALEF);
    #pragma unroll
    for (int d = 0; d < 8; ++d) {
        ulonglong2 raw = *(const ulonglong2*)&s_qkv[i * QKV_STRIDE + h * HD + d * 4];
        qv[2 * d]     = mul2(raw.x, SC2);
        qv[2 * d + 1] = mul2(raw.y, SC2);
    }
    #pragma unroll
    for (int t = 0; t < 16; ++t) acc[t] = 0ULL;
    float sum = 0.f;
    const uint8_t* relrow = s_rel + i * NT;
    const float*   mrow   = s_mask + i * M_STRIDE;
    #pragma unroll 1
    for (int j = jbeg; j < jend; ++j) {
        const float* kr = &s_qkv[j * QKV_STRIDE + DIMC + h * HD];
        unsigned long long a0 = 0ULL, a1 = 0ULL, a2 = 0ULL, a3 = 0ULL;
        #pragma unroll
        for (int d = 0; d < 4; ++d) {
            ulonglong2 kv0 = *(const ulonglong2*)&kr[d * 8];
            ulonglong2 kv1 = *(const ulonglong2*)&kr[d * 8 + 4];
            a0 = fma2(qv[4 * d],     kv0.x, a0);
            a1 = fma2(qv[4 * d + 1], kv0.y, a1);
            a2 = fma2(qv[4 * d + 2], kv1.x, a2);
            a3 = fma2(qv[4 * d + 3], kv1.y, a3);
        }
        float2 p0 = unpack2(a0), p1 = unpack2(a1), p2 = unpack2(a2), p3 = unpack2(a3);
        float dot = ((p0.x + p0.y) + (p1.x + p1.y)) + ((p2.x + p2.y) + (p3.x + p3.y));
        float ee = __expf(dot + s_bt[(int)relrow[j] * HEADS + h] + mrow[j]);
        sum += ee;
        unsigned long long sp = pack2(ee, ee);
        const float* vr = &s_qkv[j * QKV_STRIDE + 2 * DIMC + h * HD];
        #pragma unroll
        for (int d = 0; d < 8; ++d) {
            ulonglong2 vv = *(const ulonglong2*)&vr[d * 4];
            acc[2 * d]     = fma2(sp, vv.x, acc[2 * d]);
            acc[2 * d + 1] = fma2(sp, vv.y, acc[2 * d + 1]);
        }
    }
    sumOut = sum;
}

__global__ void __launch_bounds__(THREADS, 1)
winattn_kernel(const float* __restrict__ x,
               const float* __restrict__ mask,
               const float* __restrict__ qkv_w,
               const float* __restrict__ qkv_b,
               const float* __restrict__ proj_w,
               const float* __restrict__ proj_b,
               const float* __restrict__ bt,
               float* __restrict__ out,
               int nwin)
{
    extern __shared__ float sm[];
    float* s_qkv  = sm + OFF_QKV;
    float* s_x    = sm + OFF_X;
    float* s_w0   = sm + OFF_W;
    float* s_w1   = s_w0 + 64 * 128;
    float* s_mask = sm + OFF_MASK;
    float* s_bt   = sm + OFF_BT;
    float* s_bias = sm + OFF_BIAS;
    uint8_t* s_rel = (uint8_t*)(sm + OFF_RELF);
    float* s_part = sm + OFF_PART;   // gemm partials [49][66] / attn combine [196][37]

    const int tid  = threadIdx.x;
    const int wid  = tid >> 5;
    const int lane = tid & 31;
    const int b    = blockIdx.x;

    const float* xg = x + (long long)b * (NT * DIMC);
    const float* mg = mask + (long long)(b % nwin) * (NT * NT);

    // ---------------- prologue ----------------
    for (int idx = tid; idx < NT * 32; idx += THREADS) {
        int r = idx >> 5, c4 = idx & 31;
        float4 v = ((const float4*)xg)[idx];
        *(float4*)&s_x[r * X_STRIDE + c4 * 4] = v;
    }
    for (int idx = tid; idx < NT * NT; idx += THREADS) {
        int i = idx / NT, j = idx - i * NT;
        s_mask[i * M_STRIDE + j] = mg[idx];
        int ia = i / WS, ib = i - ia * WS;
        int ja = j / WS, jb = j - ja * WS;
        s_rel[idx] = (uint8_t)((ia - ja + WS - 1) * (2 * WS - 1) + (ib - jb + WS - 1));
    }
    for (int idx = tid; idx < 676; idx += THREADS) s_bt[idx] = bt[idx];
    for (int idx = tid; idx < 512; idx += THREADS)
        s_bias[idx] = (idx < 3 * DIMC) ? qkv_b[idx] : proj_b[idx - 3 * DIMC];
    for (int idx = tid; idx < 2048; idx += THREADS) {   // qkv chunk 0 -> w0
        int r = idx >> 5, c4 = idx & 31;
        float4 v = ((const float4*)qkv_w)[idx];
        *(float4*)&s_w0[r * 128 + ((c4 ^ (r & 7)) << 2)] = v;
    }
    __syncthreads();

    float* wbuf[2] = { s_w0, s_w1 };
    const int rg = wid % 7;     // row group (compute warps)
    const int kh = wid / 7;     // k half: 0 (finalizer) or 1 (partial-store)

    // ---------------- QKV GEMM: 6 chunks of 64 cols ----------------
    #pragma unroll 1
    for (int t = 0; t < 6; ++t) {
        float res[7][2];
        if (wid >= 14) {
            const float* src = (t < 5) ? (qkv_w + (t + 1) * 64 * 128) : proj_w;
            load_wchunk_half(src, wbuf[(t + 1) & 1], lane, wid - 14);
        } else {
            mm_half(s_x, wbuf[t & 1], rg, kh, lane, res);
            if (kh == 1) {
                #pragma unroll
                for (int r = 0; r < 7; ++r) {
                    int m = rg * 7 + r;
                    s_part[m * P_STRIDE + lane]      = res[r][0];
                    s_part[m * P_STRIDE + 32 + lane] = res[r][1];
                }
            }
        }
        __syncthreads();
        if (wid < 7) {
            #pragma unroll
            for (int r = 0; r < 7; ++r) {
                int m = rg * 7 + r;
                #pragma unroll
                for (int c = 0; c < 2; ++c) {
                    int col = t * 64 + lane + 32 * c;
                    s_qkv[m * QKV_STRIDE + col] =
                        res[r][c] + s_part[m * P_STRIDE + 32 * c + lane] + s_bias[col];
                }
            }
        }
        __syncthreads();
    }
    // buffers now: w0 = proj chunk 0

    // ---------------- attention: 392 threads, j-split pairs ----------------
    float sumA;
    unsigned long long accA[16];
    if (tid < 196) {
        const int h = tid / NT, i = tid - (tid / NT) * NT;
        attn_partial(s_qkv, s_bt, s_mask, s_rel, h, i, 0, 25, sumA, accA);
    } else if (tid < 392) {
        const int t2 = tid - 196;
        const int h = t2 / NT, i = t2 - (t2 / NT) * NT;
        float sumB;
        unsigned long long accB[16];
        attn_partial(s_qkv, s_bt, s_mask, s_rel, h, i, 25, NT, sumB, accB);
        float* row = &s_part[t2 * C_STRIDE];
        #pragma unroll
        for (int d = 0; d < 16; ++d) {
            float2 p = unpack2(accB[d]);
            row[2 * d] = p.x;
            row[2 * d + 1] = p.y;
        }
        row[32] = sumB;
    } else if (wid >= 14) {
        load_wchunk_half(proj_w + 64 * 128, s_w1, lane, wid - 14);
    }
    __syncthreads();
    if (tid < 196) {
        const int h = tid / NT, i = tid - (tid / NT) * NT;
        const float* row = &s_part[tid * C_STRIDE];
        const float inv = 1.0f / (sumA + row[32]);
        #pragma unroll
        for (int d = 0; d < 8; ++d) {
            float2 pa0 = unpack2(accA[2 * d]);
            float2 pa1 = unpack2(accA[2 * d + 1]);
            float4 o;
            o.x = (pa0.x + row[4 * d])     * inv;
            o.y = (pa0.y + row[4 * d + 1]) * inv;
            o.z = (pa1.x + row[4 * d + 2]) * inv;
            o.w = (pa1.y + row[4 * d + 3]) * inv;
            *(float4*)&s_x[i * X_STRIDE + h * HD + d * 4] = o;
        }
    }
    __syncthreads();

    // ---------------- proj GEMM: 2 chunks of 64 cols ----------------
    float* dstbase = out + (long long)b * (NT * DIMC);
    #pragma unroll 1
    for (int p = 0; p < 2; ++p) {
        float res[7][2];
        if (wid < 14) {
            mm_half(s_x, wbuf[p], rg, kh, lane, res);
            if (kh == 1) {
                #pragma unroll
                for (int r = 0; r < 7; ++r) {
                    int m = rg * 7 + r;
                    s_part[m * P_STRIDE + lane]      = res[r][0];
                    s_part[m * P_STRIDE + 32 + lane] = res[r][1];
                }
            }
        }
        __syncthreads();
        if (wid < 7) {
            #pragma unroll
            for (int r = 0; r < 7; ++r) {
                int m = rg * 7 + r;
                #pragma unroll
                for (int c = 0; c < 2; ++c) {
                    int col = p * 64 + lane + 32 * c;
                    dstbase[m * DIMC + col] =
                        res[r][c] + s_part[m * P_STRIDE + 32 * c + lane] + s_bias[3 * DIMC + col];
                }
            }
        }
        if (p == 0) __syncthreads();
    }
}

extern "C" void kernel_launch(void* const* d_in, const int* in_sizes, int n_in,
                              void* d_out, int out_size) {
    const float* x      = (const float*)d_in[0];
    const float* mask   = (const float*)d_in[1];
    const float* qkv_w  = (const float*)d_in[2];
    const float* qkv_b  = (const float*)d_in[3];
    const float* proj_w = (const float*)d_in[4];
    const float* proj_b = (const float*)d_in[5];
    const float* bt     = (const float*)d_in[6];
    float* out = (float*)d_out;

    const int B    = in_sizes[0] / (NT * DIMC);   // 4096
    const int nwin = in_sizes[1] / (NT * NT);     // 64

    cudaFuncSetAttribute(winattn_kernel,
                         cudaFuncAttributeMaxDynamicSharedMemorySize, SMEM_BYTES);
    winattn_kernel<<<B, THREADS, SMEM_BYTES>>>(x, mask, qkv_w, qkv_b, proj_w, proj_b, bt, out, B > 0 ? nwin : 1);
}

// round 6
// speedup vs baseline: 1.1312x; 1.1312x over previous
#include <cuda_runtime.h>
#include <cstdint>

// ---------------- problem constants ----------------
#define NT     49
#define DIMC   128
#define HEADS  4
#define HD     32
#define WS     7
#define SCALEF 0.17677669529663687f   // 32^-0.5
#define THREADS 512

// ---------------- smem layout (float offsets) ----------------
#define QKV_STRIDE 396
#define X_STRIDE   132
#define M_STRIDE   53
#define C_STRIDE   35                  // attention combine row stride (odd)

#define OFF_QKV  0
#define OFF_X    (NT * QKV_STRIDE)                  // 19404
#define OFF_W    (OFF_X + NT * X_STRIDE)            // 25872  ONE 128x128 tile
#define OFF_MASK (OFF_W + 128 * 128)                // 42256
#define OFF_BT   (OFF_MASK + NT * M_STRIDE)         // 44853
#define OFF_BIAS (OFF_BT + 676)                     // 45529
#define OFF_RELF (OFF_BIAS + 512)                   // 46041
#define OFF_COMB (OFF_RELF + 608)                   // 46649
#define SMEM_FLOATS (OFF_COMB + 196 * C_STRIDE)     // 53509
#define SMEM_BYTES  (SMEM_FLOATS * 4)               // 214036

// ---------------- packed f32x2 helpers ----------------
__device__ __forceinline__ unsigned long long fma2(unsigned long long a,
                                                   unsigned long long b,
                                                   unsigned long long c) {
    unsigned long long d;
    asm("fma.rn.f32x2 %0, %1, %2, %3;" : "=l"(d) : "l"(a), "l"(b), "l"(c));
    return d;
}
__device__ __forceinline__ unsigned long long mul2(unsigned long long a,
                                                   unsigned long long b) {
    unsigned long long d;
    asm("mul.rn.f32x2 %0, %1, %2;" : "=l"(d) : "l"(a), "l"(b));
    return d;
}
__device__ __forceinline__ unsigned long long pack2(float a, float b) {
    unsigned long long r;
    asm("mov.b64 %0, {%1, %2};" : "=l"(r) : "r"(__float_as_uint(a)), "r"(__float_as_uint(b)));
    return r;
}
__device__ __forceinline__ float2 unpack2(unsigned long long v) {
    unsigned int lo, hi;
    asm("mov.b64 {%0, %1}, %2;" : "=r"(lo), "=r"(hi) : "l"(v));
    return make_float2(__uint_as_float(lo), __uint_as_float(hi));
}

// cooperative xor-swizzled tile load: 128 rows x 128 floats, all 512 threads
__device__ __forceinline__ void load_tile(const float* __restrict__ src,
                                          float* __restrict__ dst, int tid) {
    #pragma unroll
    for (int it = 0; it < 8; ++it) {
        int idx = tid + it * THREADS;          // 0..4095 float4
        int r = idx >> 5, c4 = idx & 31;
        float4 v = ((const float4*)src)[idx];
        *(float4*)&dst[r * 128 + ((c4 ^ (r & 7)) << 2)] = v;
    }
}

// half-K GEMM over a full 128-col tile: rows 7rg..7rg+6, cols {lane,+32,+64,+96},
// k4 in [16kh, 16kh+16). s_w xor-swizzled; (row&7)==(lane&7) for all 4 cols.
__device__ __forceinline__ void mm_tile(const float* __restrict__ s_xt,
                                        const float* __restrict__ s_wt,
                                        int rg, int kh, int lane, float res[7][4])
{
    unsigned long long acc[7][4];
    #pragma unroll
    for (int r = 0; r < 7; ++r)
        #pragma unroll
        for (int c = 0; c < 4; ++c) acc[r][c] = 0ULL;

    const int xr = lane & 7;
    const float* xbase = s_xt + (rg * 7) * X_STRIDE;
    const int k0 = kh * 16;
    #pragma unroll 4
    for (int k4 = k0; k4 < k0 + 16; ++k4) {
        const int wk = ((k4 ^ xr) << 2);
        ulonglong2 wv[4];
        #pragma unroll
        for (int c = 0; c < 4; ++c)
            wv[c] = *(const ulonglong2*)&s_wt[(lane + 32 * c) * 128 + wk];
        #pragma unroll
        for (int r = 0; r < 7; ++r) {
            ulonglong2 xv = *(const ulonglong2*)&xbase[r * X_STRIDE + (k4 << 2)];
            #pragma unroll
            for (int c = 0; c < 4; ++c) {
                acc[r][c] = fma2(xv.x, wv[c].x, acc[r][c]);
                acc[r][c] = fma2(xv.y, wv[c].y, acc[r][c]);
            }
        }
    }
    #pragma unroll
    for (int r = 0; r < 7; ++r)
        #pragma unroll
        for (int c = 0; c < 4; ++c) {
            float2 p = unpack2(acc[r][c]);
            res[r][c] = p.x + p.y;
        }
}

// attention partial over j in [jbeg, jend): fused scores->exp->acc
__device__ __forceinline__ void attn_partial(const float* __restrict__ s_qkv,
                                             const float* __restrict__ s_bt,
                                             const float* __restrict__ s_mask,
                                             const uint8_t* __restrict__ s_rel,
                                             int h, int i, int jbeg, int jend,
                                             float& sumOut, unsigned long long acc[16])
{
    unsigned long long qv[16];
    const unsigned long long SC2 = pack2(SCALEF, SCALEF);
    #pragma unroll
    for (int d = 0; d < 8; ++d) {
        ulonglong2 raw = *(const ulonglong2*)&s_qkv[i * QKV_STRIDE + h * HD + d * 4];
        qv[2 * d]     = mul2(raw.x, SC2);
        qv[2 * d + 1] = mul2(raw.y, SC2);
    }
    #pragma unroll
    for (int t = 0; t < 16; ++t) acc[t] = 0ULL;
    float sum = 0.f;
    const uint8_t* relrow = s_rel + i * NT;
    const float*   mrow   = s_mask + i * M_STRIDE;
    #pragma unroll 1
    for (int j = jbeg; j < jend; ++j) {
        const float* kr = &s_qkv[j * QKV_STRIDE + DIMC + h * HD];
        unsigned long long a0 = 0ULL, a1 = 0ULL, a2 = 0ULL, a3 = 0ULL;
        #pragma unroll
        for (int d = 0; d < 4; ++d) {
            ulonglong2 kv0 = *(const ulonglong2*)&kr[d * 8];
            ulonglong2 kv1 = *(const ulonglong2*)&kr[d * 8 + 4];
            a0 = fma2(qv[4 * d],     kv0.x, a0);
            a1 = fma2(qv[4 * d + 1], kv0.y, a1);
            a2 = fma2(qv[4 * d + 2], kv1.x, a2);
            a3 = fma2(qv[4 * d + 3], kv1.y, a3);
        }
        float2 p0 = unpack2(a0), p1 = unpack2(a1), p2 = unpack2(a2), p3 = unpack2(a3);
        float dot = ((p0.x + p0.y) + (p1.x + p1.y)) + ((p2.x + p2.y) + (p3.x + p3.y));
        float ee = __expf(dot + s_bt[(int)relrow[j] * HEADS + h] + mrow[j]);
        sum += ee;
        unsigned long long sp = pack2(ee, ee);
        const float* vr = &s_qkv[j * QKV_STRIDE + 2 * DIMC + h * HD];
        #pragma unroll
        for (int d = 0; d < 8; ++d) {
            ulonglong2 vv = *(const ulonglong2*)&vr[d * 4];
            acc[2 * d]     = fma2(sp, vv.x, acc[2 * d]);
            acc[2 * d + 1] = fma2(sp, vv.y, acc[2 * d + 1]);
        }
    }
    sumOut = sum;
}

__global__ void __launch_bounds__(THREADS, 1)
winattn_kernel(const float* __restrict__ x,
               const float* __restrict__ mask,
               const float* __restrict__ qkv_w,
               const float* __restrict__ qkv_b,
               const float* __restrict__ proj_w,
               const float* __restrict__ proj_b,
               const float* __restrict__ bt,
               float* __restrict__ out,
               int nwin)
{
    extern __shared__ float sm[];
    float* s_qkv  = sm + OFF_QKV;   // [49][396] q|k|v; q-region reused as proj staging
    float* s_x    = sm + OFF_X;     // [49][132] x; reused as attn output
    float* s_w    = sm + OFF_W;     // [128][128] xor-swizzled weight tile
    float* s_mask = sm + OFF_MASK;
    float* s_bt   = sm + OFF_BT;
    float* s_bias = sm + OFF_BIAS;  // qkv_b(384)|proj_b(128)
    uint8_t* s_rel = (uint8_t*)(sm + OFF_RELF);
    float* s_comb = sm + OFF_COMB;  // [196][35] attention combine

    const int tid  = threadIdx.x;
    const int wid  = tid >> 5;
    const int lane = tid & 31;
    const int b    = blockIdx.x;

    const float* xg = x + (long long)b * (NT * DIMC);
    const float* mg = mask + (long long)(b % nwin) * (NT * NT);

    // ---------------- prologue ----------------
    for (int idx = tid; idx < NT * 32; idx += THREADS) {
        int r = idx >> 5, c4 = idx & 31;
        float4 v = ((const float4*)xg)[idx];
        *(float4*)&s_x[r * X_STRIDE + c4 * 4] = v;
    }
    for (int idx = tid; idx < NT * NT; idx += THREADS) {
        int i = idx / NT, j = idx - i * NT;
        s_mask[i * M_STRIDE + j] = mg[idx];
        int ia = i / WS, ib = i - ia * WS;
        int ja = j / WS, jb = j - ja * WS;
        s_rel[idx] = (uint8_t)((ia - ja + WS - 1) * (2 * WS - 1) + (ib - jb + WS - 1));
    }
    for (int idx = tid; idx < 676; idx += THREADS) s_bt[idx] = bt[idx];
    for (int idx = tid; idx < 512; idx += THREADS)
        s_bias[idx] = (idx < 3 * DIMC) ? qkv_b[idx] : proj_b[idx - 3 * DIMC];
    load_tile(qkv_w, s_w, tid);    // tile 0 (q)
    __syncthreads();

    const int rg = wid % 7;     // row group for compute warps 0..13
    const int kh = wid / 7;     // k half: 0 finalizes, 1 stores partials

    // ---------------- QKV GEMM: 3 tiles of 128 cols ----------------
    #pragma unroll 1
    for (int t = 0; t < 3; ++t) {
        float res[7][4];
        if (wid < 14) {
            mm_tile(s_x, s_w, rg, kh, lane, res);
            if (kh == 1) {   // raw partials into destination slots
                #pragma unroll
                for (int r = 0; r < 7; ++r) {
                    float* dst = &s_qkv[(rg * 7 + r) * QKV_STRIDE + t * 128];
                    #pragma unroll
                    for (int c = 0; c < 4; ++c) dst[lane + 32 * c] = res[r][c];
                }
            }
        }
        __syncthreads();   // partials visible; compute done -> w reusable
        // overlap: kh==0 finalize while everyone loads next tile
        if (wid < 7) {
            #pragma unroll
            for (int r = 0; r < 7; ++r) {
                float* dst = &s_qkv[(rg * 7 + r) * QKV_STRIDE + t * 128];
                #pragma unroll
                for (int c = 0; c < 4; ++c) {
                    int col = lane + 32 * c;
                    dst[col] = res[r][c] + dst[col] + s_bias[t * 128 + col];
                }
            }
        }
        load_tile((t < 2) ? (qkv_w + (t + 1) * 128 * 128) : proj_w, s_w, tid);
        __syncthreads();
    }
    // s_w now holds proj tile; s_qkv holds q|k|v

    // ---------------- attention: 392 threads, j-split pairs ----------------
    float sumA;
    unsigned long long accA[16];
    if (tid < 196) {
        const int h = tid / NT, i = tid - (tid / NT) * NT;
        attn_partial(s_qkv, s_bt, s_mask, s_rel, h, i, 0, 25, sumA, accA);
    } else if (tid < 392) {
        const int t2 = tid - 196;
        const int h = t2 / NT, i = t2 - (t2 / NT) * NT;
        float sumB;
        unsigned long long accB[16];
        attn_partial(s_qkv, s_bt, s_mask, s_rel, h, i, 25, NT, sumB, accB);
        float* row = &s_comb[t2 * C_STRIDE];
        #pragma unroll
        for (int d = 0; d < 16; ++d) {
            float2 p = unpack2(accB[d]);
            row[2 * d] = p.x;
            row[2 * d + 1] = p.y;
        }
        row[32] = sumB;
    }
    __syncthreads();
    if (tid < 196) {
        const int h = tid / NT, i = tid - (tid / NT) * NT;
        const float* row = &s_comb[tid * C_STRIDE];
        const float inv = 1.0f / (sumA + row[32]);
        #pragma unroll
        for (int d = 0; d < 8; ++d) {
            float2 pa0 = unpack2(accA[2 * d]);
            float2 pa1 = unpack2(accA[2 * d + 1]);
            float4 o;
            o.x = (pa0.x + row[4 * d])     * inv;
            o.y = (pa0.y + row[4 * d + 1]) * inv;
            o.z = (pa1.x + row[4 * d + 2]) * inv;
            o.w = (pa1.y + row[4 * d + 3]) * inv;
            *(float4*)&s_x[i * X_STRIDE + h * HD + d * 4] = o;
        }
    }
    __syncthreads();   // attn-out in s_x; q-region of s_qkv now dead (staging)

    // ---------------- proj GEMM (one 128-col tile) ----------------
    {
        float res[7][4];
        if (wid < 14) {
            mm_tile(s_x, s_w, rg, kh, lane, res);
            if (kh == 1) {   // partials into dead q-region staging
                #pragma unroll
                for (int r = 0; r < 7; ++r) {
                    float* stg = &s_qkv[(rg * 7 + r) * QKV_STRIDE];
                    #pragma unroll
                    for (int c = 0; c < 4; ++c) stg[lane + 32 * c] = res[r][c];
                }
            }
        }
        __syncthreads();
        if (wid < 7) {
            float* dstbase = out + (long long)b * (NT * DIMC);
            #pragma unroll
            for (int r = 0; r < 7; ++r) {
                int m = rg * 7 + r;
                const float* stg = &s_qkv[m * QKV_STRIDE];
                #pragma unroll
                for (int c = 0; c < 4; ++c) {
                    int col = lane + 32 * c;
                    dstbase[m * DIMC + col] = res[r][c] + stg[col] + s_bias[3 * DIMC + col];
                }
            }
        }
    }
}

extern "C" void kernel_launch(void* const* d_in, const int* in_sizes, int n_in,
                              void* d_out, int out_size) {
    const float* x      = (const float*)d_in[0];
    const float* mask   = (const float*)d_in[1];
    const float* qkv_w  = (const float*)d_in[2];
    const float* qkv_b  = (const float*)d_in[3];
    const float* proj_w = (const float*)d_in[4];
    const float* proj_b = (const float*)d_in[5];
    const float* bt     = (const float*)d_in[6];
    float* out = (float*)d_out;

    const int B    = in_sizes[0] / (NT * DIMC);   // 4096
    const int nwin = in_sizes[1] / (NT * NT);     // 64

    cudaFuncSetAttribute(winattn_kernel,
                         cudaFuncAttributeMaxDynamicSharedMemorySize, SMEM_BYTES);
    winattn_kernel<<<B, THREADS, SMEM_BYTES>>>(x, mask, qkv_w, qkv_b, proj_w, proj_b, bt, out, B > 0 ? nwin : 1);
}

// round 8
// speedup vs baseline: 1.9141x; 1.6921x over previous
#include <cuda_runtime.h>
#include <cuda_bf16.h>
#include <cstdint>

// ---------------- problem constants ----------------
#define NT     49
#define DIMC   128
#define HEADS  4
#define HD     32
#define WS     7
#define SCALEF 0.17677669529663687f
#define THREADS 512

// ---------------- smem layout (float offsets) ----------------
#define QKV_STRIDE 396
#define M_STRIDE   53

#define OFF_QKV  0
#define OFF_BIAS (NT * QKV_STRIDE)            // 19404
#define OFF_BT   (OFF_BIAS + 512)             // 19916
#define OFF_MASK (OFF_BT + 676)               // 20592
#define OFF_REL  (OFF_MASK + NT * M_STRIDE)   // 23189 (u8[2401] = 604 floats)
#define OFF_AHI  23808                        // 256B-aligned; 64x128 bf16 = 4096 floats
#define OFF_ALO  (OFF_AHI + 4096)
#define OFF_BHI  (OFF_ALO + 4096)             // 128x128 bf16 = 8192 floats
#define OFF_BLO  (OFF_BHI + 8192)
#define SMEM_FLOATS (OFF_BLO + 8192)          // 48384
#define SMEM_BYTES  (SMEM_FLOATS * 4)         // 193536

static_assert(OFF_REL + 604 <= OFF_AHI, "smem overlap");

// ---------------- helpers ----------------
__device__ __forceinline__ uint32_t smem_u32(const void* p) {
    uint32_t a;
    asm("{ .reg .u64 t; cvta.to.shared.u64 t, %1; cvt.u32.u64 %0, t; }" : "=r"(a) : "l"(p));
    return a;
}

// tile byte offset: row-major bf16, 256B/row, 16B-chunk xor swizzle
__device__ __forceinline__ uint32_t toff(int r, int c) {
    return (uint32_t)(r * 256 + ((((c >> 3) ^ (r & 7))) << 4) + ((c & 7) << 1));
}

__device__ __forceinline__ uint32_t packbf(float lo, float hi) {
    uint32_t r;
    asm("cvt.rn.bf16x2.f32 %0, %1, %2;" : "=r"(r) : "f"(hi), "f"(lo));
    return r;
}
__device__ __forceinline__ float bf_lo(uint32_t p) { return __uint_as_float(p << 16); }
__device__ __forceinline__ float bf_hi(uint32_t p) { return __uint_as_float(p & 0xFFFF0000u); }

// split float4 (4 consecutive cols, col%4==0) into hi/lo bf16 and store (8B each)
__device__ __forceinline__ void split_store(float4 v, char* hbase, char* lbase, uint32_t off) {
    uint32_t h0 = packbf(v.x, v.y), h1 = packbf(v.z, v.w);
    uint32_t l0 = packbf(v.x - bf_lo(h0), v.y - bf_hi(h0));
    uint32_t l1 = packbf(v.z - bf_lo(h1), v.w - bf_hi(h1));
    *(uint2*)(hbase + off) = make_uint2(h0, h1);
    *(uint2*)(lbase + off) = make_uint2(l0, l1);
}

__device__ __forceinline__ void ldsm4(uint32_t r[4], uint32_t addr) {
    asm volatile("ldmatrix.sync.aligned.m8n8.x4.shared.b16 {%0,%1,%2,%3}, [%4];"
                 : "=r"(r[0]), "=r"(r[1]), "=r"(r[2]), "=r"(r[3]) : "r"(addr));
}
__device__ __forceinline__ void mma_bf16(float d[4], const uint32_t a[4],
                                         uint32_t b0, uint32_t b1) {
    asm volatile("mma.sync.aligned.m16n8k16.row.col.f32.bf16.bf16.f32 "
                 "{%0,%1,%2,%3},{%4,%5,%6,%7},{%8,%9},{%0,%1,%2,%3};"
                 : "+f"(d[0]), "+f"(d[1]), "+f"(d[2]), "+f"(d[3])
                 : "r"(a[0]), "r"(a[1]), "r"(a[2]), "r"(a[3]), "r"(b0), "r"(b1));
}

// one 64x128 = A(64x128) @ W(128x128)^T tile, hi/lo split (3 terms).
// warp (rb,cb): D rows rb*16..+15, cols cb*32..+31.
__device__ __forceinline__ void mma_tile(uint32_t ahi, uint32_t alo,
                                         uint32_t bhi, uint32_t blo,
                                         int rb, int cb, int lane, float acc[4][4])
{
    #pragma unroll
    for (int k = 0; k < 4; ++k)
        #pragma unroll
        for (int j = 0; j < 4; ++j) acc[k][j] = 0.f;

    const int arow = rb * 16 + (lane & 15);
    const int achk = lane >> 4;                       // 0/1
    const int bn   = cb * 32 + (lane & 7) + ((lane >> 4) << 3);
    const int bchk = (lane >> 3) & 1;
    const uint32_t axor = (uint32_t)(arow & 7);
    const uint32_t bxor = (uint32_t)(bn & 7);

    #pragma unroll
    for (int kk = 0; kk < 8; ++kk) {
        uint32_t ao  = (uint32_t)arow * 256 + ((((uint32_t)(kk * 2 + achk)) ^ axor) << 4);
        uint32_t bo0 = (uint32_t)bn * 256 + ((((uint32_t)(kk * 2 + bchk)) ^ bxor) << 4);
        uint32_t bo1 = bo0 + 16 * 256;                // (bn+16)&7 == bn&7

        uint32_t ah[4], al[4], bh0[4], bh1[4], bl0[4], bl1[4];
        ldsm4(ah, ahi + ao);
        ldsm4(al, alo + ao);
        ldsm4(bh0, bhi + bo0);
        ldsm4(bh1, bhi + bo1);
        ldsm4(bl0, blo + bo0);
        ldsm4(bl1, blo + bo1);

        // blocks: 0:(bh0[0],bh0[1]) 1:(bh0[2],bh0[3]) 2:(bh1[0],bh1[1]) 3:(bh1[2],bh1[3])
        mma_bf16(acc[0], ah, bh0[0], bh0[1]);
        mma_bf16(acc[1], ah, bh0[2], bh0[3]);
        mma_bf16(acc[2], ah, bh1[0], bh1[1]);
        mma_bf16(acc[3], ah, bh1[2], bh1[3]);
        mma_bf16(acc[0], ah, bl0[0], bl0[1]);
        mma_bf16(acc[1], ah, bl0[2], bl0[3]);
        mma_bf16(acc[2], ah, bl1[0], bl1[1]);
        mma_bf16(acc[3], ah, bl1[2], bl1[3]);
        mma_bf16(acc[0], al, bh0[0], bh0[1]);
        mma_bf16(acc[1], al, bh0[2], bh0[3]);
        mma_bf16(acc[2], al, bh1[0], bh1[1]);
        mma_bf16(acc[3], al, bh1[2], bh1[3]);
    }
}

// ---------------- packed f32x2 helpers (attention) ----------------
__device__ __forceinline__ unsigned long long fma2(unsigned long long a,
                                                   unsigned long long b,
                                                   unsigned long long c) {
    unsigned long long d;
    asm("fma.rn.f32x2 %0, %1, %2, %3;" : "=l"(d) : "l"(a), "l"(b), "l"(c));
    return d;
}
__device__ __forceinline__ unsigned long long add2(unsigned long long a, unsigned long long b) {
    unsigned long long d;
    asm("add.rn.f32x2 %0, %1, %2;" : "=l"(d) : "l"(a), "l"(b));
    return d;
}
__device__ __forceinline__ unsigned long long mul2(unsigned long long a, unsigned long long b) {
    unsigned long long d;
    asm("mul.rn.f32x2 %0, %1, %2;" : "=l"(d) : "l"(a), "l"(b));
    return d;
}
__device__ __forceinline__ unsigned long long pack2(float a, float b) {
    unsigned long long r;
    asm("mov.b64 %0, {%1, %2};" : "=l"(r) : "r"(__float_as_uint(a)), "r"(__float_as_uint(b)));
    return r;
}
__device__ __forceinline__ float2 unpack2(unsigned long long v) {
    unsigned int lo, hi;
    asm("mov.b64 {%0, %1}, %2;" : "=r"(lo), "=r"(hi) : "l"(v));
    return make_float2(__uint_as_float(lo), __uint_as_float(hi));
}

__device__ __forceinline__ void attn_partial(const float* __restrict__ s_qkv,
                                             const float* __restrict__ s_bt,
                                             const float* __restrict__ s_mask,
                                             const uint8_t* __restrict__ s_rel,
                                             int h, int i, int jbeg, int jend,
                                             float& sumOut, unsigned long long acc[16])
{
    unsigned long long qv[16];
    const unsigned long long SC2 = pack2(SCALEF, SCALEF);
    #pragma unroll
    for (int d = 0; d < 8; ++d) {
        ulonglong2 raw = *(const ulonglong2*)&s_qkv[i * QKV_STRIDE + h * HD + d * 4];
        qv[2 * d]     = mul2(raw.x, SC2);
        qv[2 * d + 1] = mul2(raw.y, SC2);
    }
    #pragma unroll
    for (int t = 0; t < 16; ++t) acc[t] = 0ULL;
    float sum = 0.f;
    const uint8_t* relrow = s_rel + i * NT;
    const float*   mrow   = s_mask + i * M_STRIDE;
    #pragma unroll 1
    for (int j = jbeg; j < jend; ++j) {
        const float* kr = &s_qkv[j * QKV_STRIDE + DIMC + h * HD];
        unsigned long long a0 = 0ULL, a1 = 0ULL, a2 = 0ULL, a3 = 0ULL;
        #pragma unroll
        for (int d = 0; d < 4; ++d) {
            ulonglong2 kv0 = *(const ulonglong2*)&kr[d * 8];
            ulonglong2 kv1 = *(const ulonglong2*)&kr[d * 8 + 4];
            a0 = fma2(qv[4 * d],     kv0.x, a0);
            a1 = fma2(qv[4 * d + 1], kv0.y, a1);
            a2 = fma2(qv[4 * d + 2], kv1.x, a2);
            a3 = fma2(qv[4 * d + 3], kv1.y, a3);
        }
        float2 p0 = unpack2(a0), p1 = unpack2(a1), p2 = unpack2(a2), p3 = unpack2(a3);
        float dot = ((p0.x + p0.y) + (p1.x + p1.y)) + ((p2.x + p2.y) + (p3.x + p3.y));
        float ee = __expf(dot + s_bt[(int)relrow[j] * HEADS + h] + mrow[j]);
        sum += ee;
        unsigned long long sp = pack2(ee, ee);
        const float* vr = &s_qkv[j * QKV_STRIDE + 2 * DIMC + h * HD];
        #pragma unroll
        for (int d = 0; d < 8; ++d) {
            ulonglong2 vv = *(const ulonglong2*)&vr[d * 4];
            acc[2 * d]     = fma2(sp, vv.x, acc[2 * d]);
            acc[2 * d + 1] = fma2(sp, vv.y, acc[2 * d + 1]);
        }
    }
    sumOut = sum;
}

__global__ void __launch_bounds__(THREADS, 1)
winattn_kernel(const float* __restrict__ x,
               const float* __restrict__ mask,
               const float* __restrict__ qkv_w,
               const float* __restrict__ qkv_b,
               const float* __restrict__ proj_w,
               const float* __restrict__ proj_b,
               const float* __restrict__ bt,
               float* __restrict__ out,
               int nwin)
{
    extern __shared__ float sm[];
    const uint32_t smem_base = smem_u32(sm);
    float* s_qkv  = sm + OFF_QKV;
    float* s_bias = sm + OFF_BIAS;
    float* s_bt   = sm + OFF_BT;
    float* s_mask = sm + OFF_MASK;
    uint8_t* s_rel = (uint8_t*)(sm + OFF_REL);
    char* ahi = (char*)(sm + OFF_AHI);
    char* alo = (char*)(sm + OFF_ALO);
    char* bhi = (char*)(sm + OFF_BHI);
    char* blo = (char*)(sm + OFF_BLO);
    const uint32_t ahi_a = smem_base + OFF_AHI * 4;
    const uint32_t alo_a = smem_base + OFF_ALO * 4;
    const uint32_t bhi_a = smem_base + OFF_BHI * 4;
    const uint32_t blo_a = smem_base + OFF_BLO * 4;

    const int tid  = threadIdx.x;
    const int wid  = tid >> 5;
    const int lane = tid & 31;
    const int rb   = wid >> 2;     // 0..3 row block
    const int cb   = wid & 3;      // 0..3 col block
    const int b    = blockIdx.x;

    const float* xg = x + (long long)b * (NT * DIMC);
    const float* mg = mask + (long long)(b % nwin) * (NT * NT);

    // ---------------- prologue ----------------
    // x -> A hi/lo (rows 0..48)
    for (int idx = tid; idx < NT * 32; idx += THREADS) {
        int r = idx >> 5, c = (idx & 31) << 2;
        split_store(((const float4*)xg)[idx], ahi, alo, toff(r, c));
    }
    // zero A rows 49..63 (both tiles)
    for (int idx = tid; idx < 15 * 32; idx += THREADS) {
        int r = 49 + (idx >> 5), c = (idx & 31) << 2;
        uint32_t off = toff(r, c);
        *(uint2*)(ahi + off) = make_uint2(0u, 0u);
        *(uint2*)(alo + off) = make_uint2(0u, 0u);
    }
    // B tile 0 = q weights
    #pragma unroll
    for (int it = 0; it < 8; ++it) {
        int idx = tid + it * THREADS;
        int r = idx >> 5, c = (idx & 31) << 2;
        split_store(((const float4*)qkv_w)[idx], bhi, blo, toff(r, c));
    }
    for (int idx = tid; idx < NT * NT; idx += THREADS) {
        int i = idx / NT, j = idx - i * NT;
        s_mask[i * M_STRIDE + j] = mg[idx];
        int ia = i / WS, ib = i - ia * WS;
        int ja = j / WS, jb = j - ja * WS;
        s_rel[idx] = (uint8_t)((ia - ja + WS - 1) * (2 * WS - 1) + (ib - jb + WS - 1));
    }
    for (int idx = tid; idx < 676; idx += THREADS) s_bt[idx] = bt[idx];
    for (int idx = tid; idx < 512; idx += THREADS)
        s_bias[idx] = (idx < 3 * DIMC) ? qkv_b[idx] : proj_b[idx - 3 * DIMC];
    __syncthreads();

    // ---------------- QKV GEMM: tiles t=0(q),1(k),2(v) ----------------
    #pragma unroll 1
    for (int t = 0; t < 3; ++t) {
        // prefetch next weight tile into registers
        const float* nsrc = (t == 0) ? (qkv_w + 16384)
                          : (t == 1) ? (qkv_w + 32768) : proj_w;
        float4 pf[8];
        #pragma unroll
        for (int it = 0; it < 8; ++it)
            pf[it] = ((const float4*)nsrc)[tid + it * THREADS];

        float acc[4][4];
        mma_tile(ahi_a, alo_a, bhi_a, blo_a, rb, cb, lane, acc);

        // epilogue -> s_qkv cols [t*128, t*128+128)
        #pragma unroll
        for (int blk = 0; blk < 4; ++blk) {
            int n0 = cb * 32 + blk * 8 + (lane & 3) * 2;
            int r0 = rb * 16 + (lane >> 2);
            const float b0 = s_bias[t * 128 + n0];
            const float b1 = s_bias[t * 128 + n0 + 1];
            if (r0 < NT) {
                float* p = &s_qkv[r0 * QKV_STRIDE + t * 128 + n0];
                p[0] = acc[blk][0] + b0;
                p[1] = acc[blk][1] + b1;
            }
            int r1 = r0 + 8;
            if (r1 < NT) {
                float* p = &s_qkv[r1 * QKV_STRIDE + t * 128 + n0];
                p[0] = acc[blk][2] + b0;
                p[1] = acc[blk][3] + b1;
            }
        }
        __syncthreads();   // mma + epilogue done -> B buffer reusable

        #pragma unroll
        for (int it = 0; it < 8; ++it) {
            int idx = tid + it * THREADS;
            split_store(pf[it], bhi, blo, toff(idx >> 5, (idx & 31) << 2));
        }
        __syncthreads();
    }
    // B tiles now hold proj weights; s_qkv holds q|k|v

    // ---------------- attention: 392 threads, pair j-split ----------------
    if (tid < 392) {
        const int slot = tid >> 1;
        const int half = tid & 1;
        const int h = slot / NT;
        const int i = slot - h * NT;
        float sum;
        unsigned long long acc[16];
        attn_partial(s_qkv, s_bt, s_mask, s_rel, h, i,
                     half ? 25 : 0, half ? NT : 25, sum, acc);
        const unsigned mact = __activemask();
        sum += __shfl_xor_sync(mact, sum, 1);
        #pragma unroll
        for (int d = 0; d < 16; ++d)
            acc[d] = add2(acc[d], __shfl_xor_sync(mact, acc[d], 1));
        if (half == 0) {
            const float inv = 1.0f / sum;
            #pragma unroll
            for (int d = 0; d < 8; ++d) {
                float2 p0 = unpack2(acc[2 * d]);
                float2 p1 = unpack2(acc[2 * d + 1]);
                float4 o = make_float4(p0.x * inv, p0.y * inv, p1.x * inv, p1.y * inv);
                split_store(o, ahi, alo, toff(i, h * HD + d * 4));
            }
        }
    }
    __syncthreads();   // attn output in A tiles (rows 49-63 still zero)

    // ---------------- proj GEMM -> global ----------------
    {
        float acc[4][4];
        mma_tile(ahi_a, alo_a, bhi_a, blo_a, rb, cb, lane, acc);

        float* dstbase = out + (long long)b * (NT * DIMC);
        #pragma unroll
        for (int blk = 0; blk < 4; ++blk) {
            int n0 = cb * 32 + blk * 8 + (lane & 3) * 2;
            int r0 = rb * 16 + (lane >> 2);
            const float b0 = s_bias[3 * DIMC + n0];
            const float b1 = s_bias[3 * DIMC + n0 + 1];
            if (r0 < NT) {
                float* p = dstbase + r0 * DIMC + n0;
                p[0] = acc[blk][0] + b0;
                p[1] = acc[blk][1] + b1;
            }
            int r1 = r0 + 8;
            if (r1 < NT) {
                float* p = dstbase + r1 * DIMC + n0;
                p[0] = acc[blk][2] + b0;
                p[1] = acc[blk][3] + b1;
            }
        }
    }
}

extern "C" void kernel_launch(void* const* d_in, const int* in_sizes, int n_in,
                              void* d_out, int out_size) {
    const float* x      = (const float*)d_in[0];
    const float* mask   = (const float*)d_in[1];
    const float* qkv_w  = (const float*)d_in[2];
    const float* qkv_b  = (const float*)d_in[3];
    const float* proj_w = (const float*)d_in[4];
    const float* proj_b = (const float*)d_in[5];
    const float* bt     = (const float*)d_in[6];
    float* out = (float*)d_out;

    const int B    = in_sizes[0] / (NT * DIMC);   // 4096
    const int nwin = in_sizes[1] / (NT * NT);     // 64

    cudaFuncSetAttribute(winattn_kernel,
                         cudaFuncAttributeMaxDynamicSharedMemorySize, SMEM_BYTES);
    winattn_kernel<<<B, THREADS, SMEM_BYTES>>>(x, mask, qkv_w, qkv_b, proj_w, proj_b, bt, out, B > 0 ? nwin : 1);
}

// round 9
// speedup vs baseline: 2.2681x; 1.1849x over previous
#include <cuda_runtime.h>
#include <cuda_bf16.h>
#include <cstdint>

// ---------------- problem constants ----------------
#define NT     49
#define DIMC   128
#define HEADS  4
#define HD     32
#define WS     7
#define SCALEF 0.17677669529663687f
#define THREADS 512

// ---------------- smem layout (float offsets) ----------------
#define M_STRIDE 53
#define OFF_BIAS 0                     // 512
#define OFF_BT   512                   // 676
#define OFF_MASK 1188                  // 49*53 = 2597
#define OFF_REL  3785                  // u8[2401] -> 601 floats
#define OFF_XHI  4608                  // 64x128 bf16 tiles, 4096 floats each
#define OFF_XLO  (OFF_XHI + 4096)
#define OFF_QHI  (OFF_XLO + 4096)
#define OFF_QLO  (OFF_QHI + 4096)
#define OFF_KHI  (OFF_QLO + 4096)
#define OFF_KLO  (OFF_KHI + 4096)
#define OFF_VHI  (OFF_KLO + 4096)
#define OFF_VLO  (OFF_VHI + 4096)
#define OFF_BHI  (OFF_VLO + 4096)      // 128x128 bf16: 8192 floats
#define OFF_BLO  (OFF_BHI + 8192)
#define SMEM_FLOATS (OFF_BLO + 8192)   // 53760
#define SMEM_BYTES  (SMEM_FLOATS * 4)  // 215040
// P tiles (64x256 bf16, 512B rows) overlay dead buffers:
#define OFF_PHI  OFF_XHI               // x dead after qkv GEMMs
#define OFF_PLO  OFF_QHI               // Q dead after scores MMA

static_assert(OFF_REL + 601 <= OFF_XHI, "smem overlap");

// ---------------- helpers ----------------
__device__ __forceinline__ uint32_t smem_u32(const void* p) {
    uint32_t a;
    asm("{ .reg .u64 t; cvta.to.shared.u64 t, %1; cvt.u32.u64 %0, t; }" : "=r"(a) : "l"(p));
    return a;
}
// 256B-row tile offset (64/128 rows x 128 bf16 cols), 16B-chunk xor swizzle
__device__ __forceinline__ uint32_t toff(int r, int c) {
    return (uint32_t)(r * 256 + ((((c >> 3) ^ (r & 7))) << 4) + ((c & 7) << 1));
}
// 512B-row tile offset (P: 64 rows x 256 bf16 cols)
__device__ __forceinline__ uint32_t poff(int r, int c) {
    return (uint32_t)(r * 512 + ((((c >> 3) ^ (r & 7))) << 4) + ((c & 7) << 1));
}
__device__ __forceinline__ uint32_t packbf(float lo, float hi) {
    uint32_t r;
    asm("cvt.rn.bf16x2.f32 %0, %1, %2;" : "=r"(r) : "f"(hi), "f"(lo));
    return r;
}
__device__ __forceinline__ float bf_lo(uint32_t p) { return __uint_as_float(p << 16); }
__device__ __forceinline__ float bf_hi(uint32_t p) { return __uint_as_float(p & 0xFFFF0000u); }

__device__ __forceinline__ void split_store4(float4 v, char* hb, char* lb, uint32_t off) {
    uint32_t h0 = packbf(v.x, v.y), h1 = packbf(v.z, v.w);
    uint32_t l0 = packbf(v.x - bf_lo(h0), v.y - bf_hi(h0));
    uint32_t l1 = packbf(v.z - bf_lo(h1), v.w - bf_hi(h1));
    *(uint2*)(hb + off) = make_uint2(h0, h1);
    *(uint2*)(lb + off) = make_uint2(l0, l1);
}
__device__ __forceinline__ void split_store2(float a, float b, char* hb, char* lb, uint32_t off) {
    uint32_t h = packbf(a, b);
    uint32_t l = packbf(a - bf_lo(h), b - bf_hi(h));
    *(uint32_t*)(hb + off) = h;
    *(uint32_t*)(lb + off) = l;
}

__device__ __forceinline__ void ldsm4(uint32_t r[4], uint32_t addr) {
    asm volatile("ldmatrix.sync.aligned.m8n8.x4.shared.b16 {%0,%1,%2,%3}, [%4];"
                 : "=r"(r[0]), "=r"(r[1]), "=r"(r[2]), "=r"(r[3]) : "r"(addr));
}
__device__ __forceinline__ void ldsm4t(uint32_t r[4], uint32_t addr) {
    asm volatile("ldmatrix.sync.aligned.m8n8.x4.trans.shared.b16 {%0,%1,%2,%3}, [%4];"
                 : "=r"(r[0]), "=r"(r[1]), "=r"(r[2]), "=r"(r[3]) : "r"(addr));
}
__device__ __forceinline__ void mma_bf16(float d[4], const uint32_t a[4],
                                         uint32_t b0, uint32_t b1) {
    asm volatile("mma.sync.aligned.m16n8k16.row.col.f32.bf16.bf16.f32 "
                 "{%0,%1,%2,%3},{%4,%5,%6,%7},{%8,%9},{%0,%1,%2,%3};"
                 : "+f"(d[0]), "+f"(d[1]), "+f"(d[2]), "+f"(d[3])
                 : "r"(a[0]), "r"(a[1]), "r"(a[2]), "r"(a[3]), "r"(b0), "r"(b1));
}

// 64x128 @ (128x128)^T, hi/lo 3-term; warp (rb,cb): rows rb*16..+15, cols cb*32..+31
__device__ __forceinline__ void mma_tile(uint32_t ahi, uint32_t alo,
                                         uint32_t bhi, uint32_t blo,
                                         int rb, int cb, int lane, float acc[4][4])
{
    #pragma unroll
    for (int k = 0; k < 4; ++k)
        #pragma unroll
        for (int j = 0; j < 4; ++j) acc[k][j] = 0.f;

    const int arow = rb * 16 + (lane & 15);
    const int achk = lane >> 4;
    const int bn   = cb * 32 + (lane & 7) + ((lane >> 4) << 3);
    const int bchk = (lane >> 3) & 1;
    const uint32_t axor = (uint32_t)(arow & 7);
    const uint32_t bxor = (uint32_t)(bn & 7);

    #pragma unroll
    for (int kk = 0; kk < 8; ++kk) {
        uint32_t ao  = (uint32_t)arow * 256 + ((((uint32_t)(kk * 2 + achk)) ^ axor) << 4);
        uint32_t bo0 = (uint32_t)bn * 256 + ((((uint32_t)(kk * 2 + bchk)) ^ bxor) << 4);
        uint32_t bo1 = bo0 + 16 * 256;
        uint32_t ah[4], al[4], bh0[4], bh1[4], bl0[4], bl1[4];
        ldsm4(ah, ahi + ao);
        ldsm4(al, alo + ao);
        ldsm4(bh0, bhi + bo0);
        ldsm4(bh1, bhi + bo1);
        ldsm4(bl0, blo + bo0);
        ldsm4(bl1, blo + bo1);
        mma_bf16(acc[0], ah, bh0[0], bh0[1]);
        mma_bf16(acc[1], ah, bh0[2], bh0[3]);
        mma_bf16(acc[2], ah, bh1[0], bh1[1]);
        mma_bf16(acc[3], ah, bh1[2], bh1[3]);
        mma_bf16(acc[0], ah, bl0[0], bl0[1]);
        mma_bf16(acc[1], ah, bl0[2], bl0[3]);
        mma_bf16(acc[2], ah, bl1[0], bl1[1]);
        mma_bf16(acc[3], ah, bl1[2], bl1[3]);
        mma_bf16(acc[0], al, bh0[0], bh0[1]);
        mma_bf16(acc[1], al, bh0[2], bh0[3]);
        mma_bf16(acc[2], al, bh1[0], bh1[1]);
        mma_bf16(acc[3], al, bh1[2], bh1[3]);
    }
}

__global__ void __launch_bounds__(THREADS, 1)
winattn_kernel(const float* __restrict__ x,
               const float* __restrict__ mask,
               const float* __restrict__ qkv_w,
               const float* __restrict__ qkv_b,
               const float* __restrict__ proj_w,
               const float* __restrict__ proj_b,
               const float* __restrict__ bt,
               float* __restrict__ out,
               int nwin)
{
    extern __shared__ float sm[];
    const uint32_t smem_base = smem_u32(sm);
    float* s_bias = sm + OFF_BIAS;
    float* s_bt   = sm + OFF_BT;
    float* s_mask = sm + OFF_MASK;
    uint8_t* s_rel = (uint8_t*)(sm + OFF_REL);
    char* base8 = (char*)sm;

    char* xhi = base8 + OFF_XHI * 4;  char* xlo = base8 + OFF_XLO * 4;
    char* qhi = base8 + OFF_QHI * 4;  char* qlo = base8 + OFF_QLO * 4;
    char* khi = base8 + OFF_KHI * 4;  char* klo = base8 + OFF_KLO * 4;
    char* vhi = base8 + OFF_VHI * 4;  char* vlo = base8 + OFF_VLO * 4;
    char* bhi = base8 + OFF_BHI * 4;  char* blo = base8 + OFF_BLO * 4;
    char* phi = base8 + OFF_PHI * 4;  char* plo = base8 + OFF_PLO * 4;

    const uint32_t xhiA = smem_base + OFF_XHI * 4, xloA = smem_base + OFF_XLO * 4;
    const uint32_t qhiA = smem_base + OFF_QHI * 4, qloA = smem_base + OFF_QLO * 4;
    const uint32_t khiA = smem_base + OFF_KHI * 4, kloA = smem_base + OFF_KLO * 4;
    const uint32_t vhiA = smem_base + OFF_VHI * 4, vloA = smem_base + OFF_VLO * 4;
    const uint32_t bhiA = smem_base + OFF_BHI * 4, bloA = smem_base + OFF_BLO * 4;
    const uint32_t phiA = smem_base + OFF_PHI * 4, ploA = smem_base + OFF_PLO * 4;

    const int tid  = threadIdx.x;
    const int wid  = tid >> 5;
    const int lane = tid & 31;
    const int rb   = wid >> 2;     // row block 0..3
    const int cb   = wid & 3;      // col block / head 0..3
    const int b    = blockIdx.x;

    const float* xg = x + (long long)b * (NT * DIMC);
    const float* mg = mask + (long long)(b % nwin) * (NT * NT);

    // ---------------- prologue ----------------
    for (int idx = tid; idx < NT * 32; idx += THREADS) {   // x -> hi/lo (rows 0..48)
        int r = idx >> 5, c = (idx & 31) << 2;
        split_store4(((const float4*)xg)[idx], xhi, xlo, toff(r, c));
    }
    {   // zero pad rows 49-63 of x/q/k/v tiles (contiguous 3840B per tile)
        char* tiles[8] = { xhi, xlo, qhi, qlo, khi, klo, vhi, vlo };
        for (int idx = tid; idx < 8 * 240; idx += THREADS) {
            int tl = idx / 240, rem = idx - tl * 240;
            *(uint4*)(tiles[tl] + 49 * 256 + rem * 16) = make_uint4(0, 0, 0, 0);
        }
    }
    #pragma unroll
    for (int it = 0; it < 8; ++it) {   // B tile 0 = q weights
        int idx = tid + it * THREADS;
        int r = idx >> 5, c = (idx & 31) << 2;
        split_store4(((const float4*)qkv_w)[idx], bhi, blo, toff(r, c));
    }
    for (int idx = tid; idx < NT * NT; idx += THREADS) {
        int i = idx / NT, j = idx - i * NT;
        s_mask[i * M_STRIDE + j] = mg[idx];
        int ia = i / WS, ib = i - ia * WS;
        int ja = j / WS, jb = j - ja * WS;
        s_rel[idx] = (uint8_t)((ia - ja + WS - 1) * (2 * WS - 1) + (ib - jb + WS - 1));
    }
    for (int idx = tid; idx < 676; idx += THREADS) s_bt[idx] = bt[idx];
    for (int idx = tid; idx < 512; idx += THREADS)
        s_bias[idx] = (idx < 3 * DIMC) ? qkv_b[idx] : proj_b[idx - 3 * DIMC];
    __syncthreads();

    // ---------------- QKV GEMM: tiles t=0(q),1(k),2(v) ----------------
    {
        char* dsth[3] = { qhi, khi, vhi };
        char* dstl[3] = { qlo, klo, vlo };
        #pragma unroll 1
        for (int t = 0; t < 3; ++t) {
            const float* nsrc = (t == 0) ? (qkv_w + 16384)
                              : (t == 1) ? (qkv_w + 32768) : proj_w;
            float4 pf[8];
            #pragma unroll
            for (int it = 0; it < 8; ++it)
                pf[it] = ((const float4*)nsrc)[tid + it * THREADS];

            float acc[4][4];
            mma_tile(xhiA, xloA, bhiA, bloA, rb, cb, lane, acc);

            const float sc = (t == 0) ? SCALEF : 1.0f;
            #pragma unroll
            for (int blk = 0; blk < 4; ++blk) {
                int n0 = cb * 32 + blk * 8 + (lane & 3) * 2;
                int r0 = rb * 16 + (lane >> 2);
                const float b0 = s_bias[t * 128 + n0];
                const float b1 = s_bias[t * 128 + n0 + 1];
                if (r0 < NT)
                    split_store2((acc[blk][0] + b0) * sc, (acc[blk][1] + b1) * sc,
                                 dsth[t], dstl[t], toff(r0, n0));
                if (r0 + 8 < NT)
                    split_store2((acc[blk][2] + b0) * sc, (acc[blk][3] + b1) * sc,
                                 dsth[t], dstl[t], toff(r0 + 8, n0));
            }
            __syncthreads();
            #pragma unroll
            for (int it = 0; it < 8; ++it) {
                int idx = tid + it * THREADS;
                split_store4(pf[it], bhi, blo, toff(idx >> 5, (idx & 31) << 2));
            }
            __syncthreads();
        }
    }
    // B holds proj weights; Q/K/V tiles ready (q pre-scaled, biases folded)

    // ---------------- scores: S_h = q_h @ k_h^T  (per-warp: head cb, rows rb*16) ----------------
    const int h = cb;
    const int arow = rb * 16 + (lane & 15);
    const uint32_t axor = (uint32_t)(arow & 7);
    float sacc[7][4];
    #pragma unroll
    for (int bk = 0; bk < 7; ++bk)
        #pragma unroll
        for (int j = 0; j < 4; ++j) sacc[bk][j] = 0.f;

    #pragma unroll
    for (int kk = 0; kk < 2; ++kk) {
        uint32_t achunk = (uint32_t)(h * 4 + kk * 2 + (lane >> 4));
        uint32_t ao = (uint32_t)arow * 256 + ((achunk ^ axor) << 4);
        uint32_t qh_[4], ql_[4];
        ldsm4(qh_, qhiA + ao);
        ldsm4(ql_, qloA + ao);
        #pragma unroll
        for (int g = 0; g < 4; ++g) {
            int bn = g * 16 + (lane & 7) + ((lane >> 4) << 3);
            uint32_t bchunk = (uint32_t)(h * 4 + kk * 2 + ((lane >> 3) & 1));
            uint32_t bo = (uint32_t)bn * 256 + ((bchunk ^ (uint32_t)(bn & 7)) << 4);
            uint32_t kh_[4], kl_[4];
            ldsm4(kh_, khiA + bo);
            ldsm4(kl_, kloA + bo);
            mma_bf16(sacc[2 * g], qh_, kh_[0], kh_[1]);
            mma_bf16(sacc[2 * g], qh_, kl_[0], kl_[1]);
            mma_bf16(sacc[2 * g], ql_, kh_[0], kh_[1]);
            if (2 * g + 1 < 7) {
                mma_bf16(sacc[2 * g + 1], qh_, kh_[2], kh_[3]);
                mma_bf16(sacc[2 * g + 1], qh_, kl_[2], kl_[3]);
                mma_bf16(sacc[2 * g + 1], ql_, kh_[2], kh_[3]);
            }
        }
    }
    __syncthreads();   // Q/K reads done -> P tiles (over x/Q) writable

    // ---------------- softmax on fragments -> P (bf16 hi/lo) ----------------
    {
        // zero P pad cols 56-63 (all 64 rows, both hi/lo; per head region)
        if (tid < 256) {
            int r = tid & 63, hh = (tid >> 6);
            uint32_t off = poff(r, hh * 64 + 56);
            *(uint4*)(phi + off) = make_uint4(0, 0, 0, 0);
            *(uint4*)(plo + off) = make_uint4(0, 0, 0, 0);
        }
        const int r0 = rb * 16 + (lane >> 2);
        const int r1 = r0 + 8;
        float sum0 = 0.f, sum1 = 0.f;
        #pragma unroll
        for (int bk = 0; bk < 7; ++bk) {
            int j0 = bk * 8 + (lane & 3) * 2;
            float e00 = 0.f, e01 = 0.f, e10 = 0.f, e11 = 0.f;
            if (j0 < NT) {
                e00 = __expf(sacc[bk][0] + s_bt[(int)s_rel[r0 * NT + j0] * HEADS + h]
                             + s_mask[r0 * M_STRIDE + j0]);
                e10 = __expf(sacc[bk][2] + s_bt[(int)s_rel[r1 * NT + j0] * HEADS + h]
                             + s_mask[r1 * M_STRIDE + j0]);
            }
            if (j0 + 1 < NT) {
                e01 = __expf(sacc[bk][1] + s_bt[(int)s_rel[r0 * NT + j0 + 1] * HEADS + h]
                             + s_mask[r0 * M_STRIDE + j0 + 1]);
                e11 = __expf(sacc[bk][3] + s_bt[(int)s_rel[r1 * NT + j0 + 1] * HEADS + h]
                             + s_mask[r1 * M_STRIDE + j0 + 1]);
            }
            sum0 += e00 + e01;
            sum1 += e10 + e11;
            sacc[bk][0] = e00; sacc[bk][1] = e01; sacc[bk][2] = e10; sacc[bk][3] = e11;
        }
        sum0 += __shfl_xor_sync(0xffffffffu, sum0, 1);
        sum0 += __shfl_xor_sync(0xffffffffu, sum0, 2);
        sum1 += __shfl_xor_sync(0xffffffffu, sum1, 1);
        sum1 += __shfl_xor_sync(0xffffffffu, sum1, 2);
        const float inv0 = 1.0f / sum0;
        const float inv1 = 1.0f / sum1;
        #pragma unroll
        for (int bk = 0; bk < 7; ++bk) {
            int j0 = bk * 8 + (lane & 3) * 2;
            split_store2(sacc[bk][0] * inv0, sacc[bk][1] * inv0, phi, plo, poff(r0, h * 64 + j0));
            split_store2(sacc[bk][2] * inv1, sacc[bk][3] * inv1, phi, plo, poff(r1, h * 64 + j0));
        }
    }
    __syncthreads();

    // ---------------- PV: out_h = P_h @ v_h  (V via ldmatrix.trans) ----------------
    {
        float pacc[4][4];
        #pragma unroll
        for (int bk = 0; bk < 4; ++bk)
            #pragma unroll
            for (int j = 0; j < 4; ++j) pacc[bk][j] = 0.f;

        #pragma unroll
        for (int kk = 0; kk < 4; ++kk) {
            uint32_t achunk = (uint32_t)(h * 8 + kk * 2 + (lane >> 4));
            uint32_t ao = (uint32_t)arow * 512 + ((achunk ^ axor) << 4);
            uint32_t ph_[4], pl_[4];
            ldsm4(ph_, phiA + ao);
            ldsm4(pl_, ploA + ao);
            #pragma unroll
            for (int g = 0; g < 2; ++g) {
                int vr = kk * 16 + ((lane >> 3) & 1) * 8 + (lane & 7);
                uint32_t vchunk = (uint32_t)(h * 4 + g * 2 + (lane >> 4));
                uint32_t vo = (uint32_t)vr * 256 + ((vchunk ^ (uint32_t)(vr & 7)) << 4);
                uint32_t vh_[4], vl_[4];
                ldsm4t(vh_, vhiA + vo);
                ldsm4t(vl_, vloA + vo);
                mma_bf16(pacc[2 * g],     ph_, vh_[0], vh_[1]);
                mma_bf16(pacc[2 * g],     ph_, vl_[0], vl_[1]);
                mma_bf16(pacc[2 * g],     pl_, vh_[0], vh_[1]);
                mma_bf16(pacc[2 * g + 1], ph_, vh_[2], vh_[3]);
                mma_bf16(pacc[2 * g + 1], ph_, vl_[2], vl_[3]);
                mma_bf16(pacc[2 * g + 1], pl_, vh_[2], vh_[3]);
            }
        }
        // attn-out -> K tiles (dead), toff layout: rows i, col h*32+d
        const int r0 = rb * 16 + (lane >> 2);
        #pragma unroll
        for (int bk = 0; bk < 4; ++bk) {
            int d0 = bk * 8 + (lane & 3) * 2;
            split_store2(pacc[bk][0], pacc[bk][1], khi, klo, toff(r0, h * HD + d0));
            split_store2(pacc[bk][2], pacc[bk][3], khi, klo, toff(r0 + 8, h * HD + d0));
        }
    }
    __syncthreads();

    // ---------------- proj GEMM (A = attn-out in K tiles, B = proj) -> global ----------------
    {
        float acc[4][4];
        mma_tile(khiA, kloA, bhiA, bloA, rb, cb, lane, acc);
        float* dstbase = out + (long long)b * (NT * DIMC);
        #pragma unroll
        for (int blk = 0; blk < 4; ++blk) {
            int n0 = cb * 32 + blk * 8 + (lane & 3) * 2;
            int r0 = rb * 16 + (lane >> 2);
            const float b0 = s_bias[3 * DIMC + n0];
            const float b1 = s_bias[3 * DIMC + n0 + 1];
            if (r0 < NT) {
                float* p = dstbase + r0 * DIMC + n0;
                p[0] = acc[blk][0] + b0;
                p[1] = acc[blk][1] + b1;
            }
            if (r0 + 8 < NT) {
                float* p = dstbase + (r0 + 8) * DIMC + n0;
                p[0] = acc[blk][2] + b0;
                p[1] = acc[blk][3] + b1;
            }
        }
    }
}

extern "C" void kernel_launch(void* const* d_in, const int* in_sizes, int n_in,
                              void* d_out, int out_size) {
    const float* x      = (const float*)d_in[0];
    const float* mask   = (const float*)d_in[1];
    const float* qkv_w  = (const float*)d_in[2];
    const float* qkv_b  = (const float*)d_in[3];
    const float* proj_w = (const float*)d_in[4];
    const float* proj_b = (const float*)d_in[5];
    const float* bt     = (const float*)d_in[6];
    float* out = (float*)d_out;

    const int B    = in_sizes[0] / (NT * DIMC);   // 4096
    const int nwin = in_sizes[1] / (NT * NT);     // 64

    cudaFuncSetAttribute(winattn_kernel,
                         cudaFuncAttributeMaxDynamicSharedMemorySize, SMEM_BYTES);
    winattn_kernel<<<B, THREADS, SMEM_BYTES>>>(x, mask, qkv_w, qkv_b, proj_w, proj_b, bt, out, B > 0 ? nwin : 1);
}

// round 10
// speedup vs baseline: 2.9635x; 1.3066x over previous
#include <cuda_runtime.h>
#include <cuda_fp16.h>
#include <cstdint>

// ---------------- problem constants ----------------
#define NT     49
#define DIMC   128
#define HEADS  4
#define HD     32
#define WS     7
#define SCALEF 0.17677669529663687f
#define THREADS 512

// ---------------- smem layout (float offsets) ----------------
#define M_STRIDE 53
#define OFF_BIAS 0                     // 512
#define OFF_BT   512                   // 676
#define OFF_MASK 1188                  // 2597
#define OFF_REL  3785                  // u8[2401] -> 601 floats
#define OFF_XHI  4608                  // 64x128 fp16 tiles = 4096 floats each
#define OFF_XLO  (OFF_XHI + 4096)
#define OFF_QHI  (OFF_XLO + 4096)
#define OFF_QLO  (OFF_QHI + 4096)
#define OFF_KHI  (OFF_QLO + 4096)      // k: hi only
#define OFF_VHI  (OFF_KHI + 4096)      // v: hi only
#define OFF_BHI  (OFF_VHI + 4096)      // weights: hi only, 128x128 fp16 = 8192 floats
#define SMEM_FLOATS (OFF_BHI + 8192)   // 37376
#define SMEM_BYTES  (SMEM_FLOATS * 4)  // 149504
// P tiles (64x256 fp16, 512B rows, hi/lo) overlay dead x and q:
#define OFF_PHI  OFF_XHI
#define OFF_PLO  OFF_QHI

static_assert(OFF_REL + 601 <= OFF_XHI, "smem overlap");

// ---------------- helpers ----------------
__device__ __forceinline__ uint32_t smem_u32(const void* p) {
    uint32_t a;
    asm("{ .reg .u64 t; cvta.to.shared.u64 t, %1; cvt.u32.u64 %0, t; }" : "=r"(a) : "l"(p));
    return a;
}
// 256B-row tile offset (rows x 128 fp16 cols), 16B-chunk xor swizzle
__device__ __forceinline__ uint32_t toff(int r, int c) {
    return (uint32_t)(r * 256 + ((((c >> 3) ^ (r & 7))) << 4) + ((c & 7) << 1));
}
// 512B-row tile offset (P: 64 rows x 256 fp16 cols)
__device__ __forceinline__ uint32_t poff(int r, int c) {
    return (uint32_t)(r * 512 + ((((c >> 3) ^ (r & 7))) << 4) + ((c & 7) << 1));
}
__device__ __forceinline__ uint32_t packh2(float a, float b) {   // a->low, b->high
    __half2 h = __floats2half2_rn(a, b);
    return *reinterpret_cast<uint32_t*>(&h);
}
__device__ __forceinline__ float2 h2f2(uint32_t p) {
    __half2 h = *reinterpret_cast<__half2*>(&p);
    return __half22float2(h);
}
__device__ __forceinline__ void split_store2(float a, float b, char* hb, char* lb, uint32_t off) {
    uint32_t h = packh2(a, b);
    float2 hf = h2f2(h);
    uint32_t l = packh2(a - hf.x, b - hf.y);
    *(uint32_t*)(hb + off) = h;
    *(uint32_t*)(lb + off) = l;
}
__device__ __forceinline__ void split_store4(float4 v, char* hb, char* lb, uint32_t off) {
    uint32_t h0 = packh2(v.x, v.y), h1 = packh2(v.z, v.w);
    float2 f0 = h2f2(h0), f1 = h2f2(h1);
    uint32_t l0 = packh2(v.x - f0.x, v.y - f0.y);
    uint32_t l1 = packh2(v.z - f1.x, v.w - f1.y);
    *(uint2*)(hb + off) = make_uint2(h0, h1);
    *(uint2*)(lb + off) = make_uint2(l0, l1);
}
__device__ __forceinline__ void store4(float4 v, char* hb, uint32_t off) {
    *(uint2*)(hb + off) = make_uint2(packh2(v.x, v.y), packh2(v.z, v.w));
}
__device__ __forceinline__ void store2(float a, float b, char* hb, uint32_t off) {
    *(uint32_t*)(hb + off) = packh2(a, b);
}

__device__ __forceinline__ void ldsm4(uint32_t r[4], uint32_t addr) {
    asm volatile("ldmatrix.sync.aligned.m8n8.x4.shared.b16 {%0,%1,%2,%3}, [%4];"
                 : "=r"(r[0]), "=r"(r[1]), "=r"(r[2]), "=r"(r[3]) : "r"(addr));
}
__device__ __forceinline__ void ldsm4t(uint32_t r[4], uint32_t addr) {
    asm volatile("ldmatrix.sync.aligned.m8n8.x4.trans.shared.b16 {%0,%1,%2,%3}, [%4];"
                 : "=r"(r[0]), "=r"(r[1]), "=r"(r[2]), "=r"(r[3]) : "r"(addr));
}
__device__ __forceinline__ void mma_f16(float d[4], const uint32_t a[4],
                                        uint32_t b0, uint32_t b1) {
    asm volatile("mma.sync.aligned.m16n8k16.row.col.f32.f16.f16.f32 "
                 "{%0,%1,%2,%3},{%4,%5,%6,%7},{%8,%9},{%0,%1,%2,%3};"
                 : "+f"(d[0]), "+f"(d[1]), "+f"(d[2]), "+f"(d[3])
                 : "r"(a[0]), "r"(a[1]), "r"(a[2]), "r"(a[3]), "r"(b0), "r"(b1));
}

// 64x128 @ (128x128)^T: A hi/lo 2-term, B hi only.
// warp (rb,cb): rows rb*16..+15, cols cb*32..+31.
__device__ __forceinline__ void mma_tile(uint32_t ahi, uint32_t alo, uint32_t bh,
                                         int rb, int cb, int lane, float acc[4][4])
{
    #pragma unroll
    for (int k = 0; k < 4; ++k)
        #pragma unroll
        for (int j = 0; j < 4; ++j) acc[k][j] = 0.f;

    const int arow = rb * 16 + (lane & 15);
    const int achk = lane >> 4;
    const int bn   = cb * 32 + (lane & 7) + ((lane >> 4) << 3);
    const int bchk = (lane >> 3) & 1;
    const uint32_t axor = (uint32_t)(arow & 7);
    const uint32_t bxor = (uint32_t)(bn & 7);

    #pragma unroll
    for (int kk = 0; kk < 8; ++kk) {
        uint32_t ao  = (uint32_t)arow * 256 + ((((uint32_t)(kk * 2 + achk)) ^ axor) << 4);
        uint32_t bo0 = (uint32_t)bn * 256 + ((((uint32_t)(kk * 2 + bchk)) ^ bxor) << 4);
        uint32_t bo1 = bo0 + 16 * 256;
        uint32_t ah[4], al[4], bh0[4], bh1[4];
        ldsm4(ah, ahi + ao);
        ldsm4(al, alo + ao);
        ldsm4(bh0, bh + bo0);
        ldsm4(bh1, bh + bo1);
        mma_f16(acc[0], ah, bh0[0], bh0[1]);
        mma_f16(acc[1], ah, bh0[2], bh0[3]);
        mma_f16(acc[2], ah, bh1[0], bh1[1]);
        mma_f16(acc[3], ah, bh1[2], bh1[3]);
        mma_f16(acc[0], al, bh0[0], bh0[1]);
        mma_f16(acc[1], al, bh0[2], bh0[3]);
        mma_f16(acc[2], al, bh1[0], bh1[1]);
        mma_f16(acc[3], al, bh1[2], bh1[3]);
    }
}

__global__ void __launch_bounds__(THREADS, 1)
winattn_kernel(const float* __restrict__ x,
               const float* __restrict__ mask,
               const float* __restrict__ qkv_w,
               const float* __restrict__ qkv_b,
               const float* __restrict__ proj_w,
               const float* __restrict__ proj_b,
               const float* __restrict__ bt,
               float* __restrict__ out,
               int nwin)
{
    extern __shared__ float sm[];
    const uint32_t smem_base = smem_u32(sm);
    float* s_bias = sm + OFF_BIAS;
    float* s_bt   = sm + OFF_BT;
    float* s_mask = sm + OFF_MASK;
    uint8_t* s_rel = (uint8_t*)(sm + OFF_REL);
    char* base8 = (char*)sm;

    char* xhi = base8 + OFF_XHI * 4;  char* xlo = base8 + OFF_XLO * 4;
    char* qhi = base8 + OFF_QHI * 4;  char* qlo = base8 + OFF_QLO * 4;
    char* khi = base8 + OFF_KHI * 4;
    char* vhi = base8 + OFF_VHI * 4;
    char* bhi = base8 + OFF_BHI * 4;
    char* phi = base8 + OFF_PHI * 4;  char* plo = base8 + OFF_PLO * 4;

    const uint32_t xhiA = smem_base + OFF_XHI * 4, xloA = smem_base + OFF_XLO * 4;
    const uint32_t qhiA = smem_base + OFF_QHI * 4, qloA = smem_base + OFF_QLO * 4;
    const uint32_t khiA = smem_base + OFF_KHI * 4;
    const uint32_t vhiA = smem_base + OFF_VHI * 4;
    const uint32_t bhiA = smem_base + OFF_BHI * 4;
    const uint32_t phiA = smem_base + OFF_PHI * 4, ploA = smem_base + OFF_PLO * 4;

    const int tid  = threadIdx.x;
    const int wid  = tid >> 5;
    const int lane = tid & 31;
    const int rb   = wid >> 2;
    const int cb   = wid & 3;
    const int b    = blockIdx.x;

    const float* xg = x + (long long)b * (NT * DIMC);
    const float* mg = mask + (long long)(b % nwin) * (NT * NT);

    // ---------------- prologue ----------------
    for (int idx = tid; idx < NT * 32; idx += THREADS) {   // x -> hi/lo
        int r = idx >> 5, c = (idx & 31) << 2;
        split_store4(((const float4*)xg)[idx], xhi, xlo, toff(r, c));
    }
    {   // zero pad rows 49-63 of x(h,l)/q(h,l)/k/v tiles
        char* tiles[6] = { xhi, xlo, qhi, qlo, khi, vhi };
        for (int idx = tid; idx < 6 * 240; idx += THREADS) {
            int tl = idx / 240, rem = idx - tl * 240;
            *(uint4*)(tiles[tl] + 49 * 256 + rem * 16) = make_uint4(0, 0, 0, 0);
        }
    }
    #pragma unroll
    for (int it = 0; it < 8; ++it) {   // B tile 0 = q weights (hi only)
        int idx = tid + it * THREADS;
        int r = idx >> 5, c = (idx & 31) << 2;
        store4(((const float4*)qkv_w)[idx], bhi, toff(r, c));
    }
    for (int idx = tid; idx < NT * NT; idx += THREADS) {
        int i = idx / NT, j = idx - i * NT;
        s_mask[i * M_STRIDE + j] = mg[idx];
        int ia = i / WS, ib = i - ia * WS;
        int ja = j / WS, jb = j - ja * WS;
        s_rel[idx] = (uint8_t)((ia - ja + WS - 1) * (2 * WS - 1) + (ib - jb + WS - 1));
    }
    for (int idx = tid; idx < 676; idx += THREADS) s_bt[idx] = bt[idx];
    for (int idx = tid; idx < 512; idx += THREADS)
        s_bias[idx] = (idx < 3 * DIMC) ? qkv_b[idx] : proj_b[idx - 3 * DIMC];
    __syncthreads();

    // ---------------- QKV GEMM: tiles t=0(q),1(k),2(v) ----------------
    #pragma unroll 1
    for (int t = 0; t < 3; ++t) {
        const float* nsrc = (t == 0) ? (qkv_w + 16384)
                          : (t == 1) ? (qkv_w + 32768) : proj_w;
        float4 pf[8];
        #pragma unroll
        for (int it = 0; it < 8; ++it)
            pf[it] = ((const float4*)nsrc)[tid + it * THREADS];

        float acc[4][4];
        mma_tile(xhiA, xloA, bhiA, rb, cb, lane, acc);

        #pragma unroll
        for (int blk = 0; blk < 4; ++blk) {
            int n0 = cb * 32 + blk * 8 + (lane & 3) * 2;
            int r0 = rb * 16 + (lane >> 2);
            const float b0 = s_bias[t * 128 + n0];
            const float b1 = s_bias[t * 128 + n0 + 1];
            if (t == 0) {        // q: hi/lo, pre-scaled
                if (r0 < NT)
                    split_store2((acc[blk][0] + b0) * SCALEF, (acc[blk][1] + b1) * SCALEF,
                                 qhi, qlo, toff(r0, n0));
                if (r0 + 8 < NT)
                    split_store2((acc[blk][2] + b0) * SCALEF, (acc[blk][3] + b1) * SCALEF,
                                 qhi, qlo, toff(r0 + 8, n0));
            } else {             // k/v: hi only
                char* dst = (t == 1) ? khi : vhi;
                if (r0 < NT)
                    store2(acc[blk][0] + b0, acc[blk][1] + b1, dst, toff(r0, n0));
                if (r0 + 8 < NT)
                    store2(acc[blk][2] + b0, acc[blk][3] + b1, dst, toff(r0 + 8, n0));
            }
        }
        __syncthreads();
        #pragma unroll
        for (int it = 0; it < 8; ++it) {
            int idx = tid + it * THREADS;
            store4(pf[it], bhi, toff(idx >> 5, (idx & 31) << 2));
        }
        __syncthreads();
    }
    // B holds proj weights (hi); q(h/l), k(h), v(h) ready

    // ---------------- scores: S_h = q_h @ k_h^T ----------------
    const int h = cb;
    const int arow = rb * 16 + (lane & 15);
    const uint32_t axor = (uint32_t)(arow & 7);
    float sacc[7][4];
    #pragma unroll
    for (int bk = 0; bk < 7; ++bk)
        #pragma unroll
        for (int j = 0; j < 4; ++j) sacc[bk][j] = 0.f;

    #pragma unroll
    for (int kk = 0; kk < 2; ++kk) {
        uint32_t achunk = (uint32_t)(h * 4 + kk * 2 + (lane >> 4));
        uint32_t ao = (uint32_t)arow * 256 + ((achunk ^ axor) << 4);
        uint32_t qh_[4], ql_[4];
        ldsm4(qh_, qhiA + ao);
        ldsm4(ql_, qloA + ao);
        #pragma unroll
        for (int g = 0; g < 4; ++g) {
            int bn = g * 16 + (lane & 7) + ((lane >> 4) << 3);
            uint32_t bchunk = (uint32_t)(h * 4 + kk * 2 + ((lane >> 3) & 1));
            uint32_t bo = (uint32_t)bn * 256 + ((bchunk ^ (uint32_t)(bn & 7)) << 4);
            uint32_t kh_[4];
            ldsm4(kh_, khiA + bo);
            mma_f16(sacc[2 * g], qh_, kh_[0], kh_[1]);
            mma_f16(sacc[2 * g], ql_, kh_[0], kh_[1]);
            if (2 * g + 1 < 7) {
                mma_f16(sacc[2 * g + 1], qh_, kh_[2], kh_[3]);
                mma_f16(sacc[2 * g + 1], ql_, kh_[2], kh_[3]);
            }
        }
    }
    __syncthreads();   // q/k reads done -> P tiles (over x/q) writable

    // ---------------- softmax on fragments -> P (fp16 hi/lo) ----------------
    {
        if (tid < 256) {   // zero P pad cols 56-63
            int r = tid & 63, hh = (tid >> 6);
            uint32_t off = poff(r, hh * 64 + 56);
            *(uint4*)(phi + off) = make_uint4(0, 0, 0, 0);
            *(uint4*)(plo + off) = make_uint4(0, 0, 0, 0);
        }
        const int r0 = rb * 16 + (lane >> 2);
        const int r1 = r0 + 8;
        float sum0 = 0.f, sum1 = 0.f;
        #pragma unroll
        for (int bk = 0; bk < 7; ++bk) {
            int j0 = bk * 8 + (lane & 3) * 2;
            float e00 = 0.f, e01 = 0.f, e10 = 0.f, e11 = 0.f;
            if (j0 < NT) {
                e00 = __expf(sacc[bk][0] + s_bt[(int)s_rel[r0 * NT + j0] * HEADS + h]
                             + s_mask[r0 * M_STRIDE + j0]);
                e10 = __expf(sacc[bk][2] + s_bt[(int)s_rel[r1 * NT + j0] * HEADS + h]
                             + s_mask[r1 * M_STRIDE + j0]);
            }
            if (j0 + 1 < NT) {
                e01 = __expf(sacc[bk][1] + s_bt[(int)s_rel[r0 * NT + j0 + 1] * HEADS + h]
                             + s_mask[r0 * M_STRIDE + j0 + 1]);
                e11 = __expf(sacc[bk][3] + s_bt[(int)s_rel[r1 * NT + j0 + 1] * HEADS + h]
                             + s_mask[r1 * M_STRIDE + j0 + 1]);
            }
            sum0 += e00 + e01;
            sum1 += e10 + e11;
            sacc[bk][0] = e00; sacc[bk][1] = e01; sacc[bk][2] = e10; sacc[bk][3] = e11;
        }
        sum0 += __shfl_xor_sync(0xffffffffu, sum0, 1);
        sum0 += __shfl_xor_sync(0xffffffffu, sum0, 2);
        sum1 += __shfl_xor_sync(0xffffffffu, sum1, 1);
        sum1 += __shfl_xor_sync(0xffffffffu, sum1, 2);
        const float inv0 = 1.0f / sum0;
        const float inv1 = 1.0f / sum1;
        #pragma unroll
        for (int bk = 0; bk < 7; ++bk) {
            int j0 = bk * 8 + (lane & 3) * 2;
            split_store2(sacc[bk][0] * inv0, sacc[bk][1] * inv0, phi, plo, poff(r0, h * 64 + j0));
            split_store2(sacc[bk][2] * inv1, sacc[bk][3] * inv1, phi, plo, poff(r1, h * 64 + j0));
        }
    }
    __syncthreads();

    // ---------------- PV: out_h = P_h @ v_h (V via ldmatrix.trans) ----------------
    float pacc[4][4];
    {
        #pragma unroll
        for (int bk = 0; bk < 4; ++bk)
            #pragma unroll
            for (int j = 0; j < 4; ++j) pacc[bk][j] = 0.f;

        #pragma unroll
        for (int kk = 0; kk < 4; ++kk) {
            uint32_t achunk = (uint32_t)(h * 8 + kk * 2 + (lane >> 4));
            uint32_t ao = (uint32_t)arow * 512 + ((achunk ^ axor) << 4);
            uint32_t ph_[4], pl_[4];
            ldsm4(ph_, phiA + ao);
            ldsm4(pl_, ploA + ao);
            #pragma unroll
            for (int g = 0; g < 2; ++g) {
                int vr = kk * 16 + ((lane >> 3) & 1) * 8 + (lane & 7);
                uint32_t vchunk = (uint32_t)(h * 4 + g * 2 + (lane >> 4));
                uint32_t vo = (uint32_t)vr * 256 + ((vchunk ^ (uint32_t)(vr & 7)) << 4);
                uint32_t vh_[4];
                ldsm4t(vh_, vhiA + vo);
                mma_f16(pacc[2 * g],     ph_, vh_[0], vh_[1]);
                mma_f16(pacc[2 * g],     pl_, vh_[0], vh_[1]);
                mma_f16(pacc[2 * g + 1], ph_, vh_[2], vh_[3]);
                mma_f16(pacc[2 * g + 1], pl_, vh_[2], vh_[3]);
            }
        }
    }
    __syncthreads();   // all PV v-reads done -> k/v tiles reusable for attn-out

    // attn-out -> hi in khi, lo in vhi (A-side of proj)
    {
        const int r0 = rb * 16 + (lane >> 2);
        #pragma unroll
        for (int bk = 0; bk < 4; ++bk) {
            int d0 = bk * 8 + (lane & 3) * 2;
            split_store2(pacc[bk][0], pacc[bk][1], khi, vhi, toff(r0, h * HD + d0));
            split_store2(pacc[bk][2], pacc[bk][3], khi, vhi, toff(r0 + 8, h * HD + d0));
        }
    }
    __syncthreads();

    // ---------------- proj GEMM -> global ----------------
    {
        float acc[4][4];
        mma_tile(khiA, vhiA, bhiA, rb, cb, lane, acc);
        float* dstbase = out + (long long)b * (NT * DIMC);
        #pragma unroll
        for (int blk = 0; blk < 4; ++blk) {
            int n0 = cb * 32 + blk * 8 + (lane & 3) * 2;
            int r0 = rb * 16 + (lane >> 2);
            const float b0 = s_bias[3 * DIMC + n0];
            const float b1 = s_bias[3 * DIMC + n0 + 1];
            if (r0 < NT) {
                float* p = dstbase + r0 * DIMC + n0;
                p[0] = acc[blk][0] + b0;
                p[1] = acc[blk][1] + b1;
            }
            if (r0 + 8 < NT) {
                float* p = dstbase + (r0 + 8) * DIMC + n0;
                p[0] = acc[blk][2] + b0;
                p[1] = acc[blk][3] + b1;
            }
        }
    }
}

extern "C" void kernel_launch(void* const* d_in, const int* in_sizes, int n_in,
                              void* d_out, int out_size) {
    const float* x      = (const float*)d_in[0];
    const float* mask   = (const float*)d_in[1];
    const float* qkv_w  = (const float*)d_in[2];
    const float* qkv_b  = (const float*)d_in[3];
    const float* proj_w = (const float*)d_in[4];
    const float* proj_b = (const float*)d_in[5];
    const float* bt     = (const float*)d_in[6];
    float* out = (float*)d_out;

    const int B    = in_sizes[0] / (NT * DIMC);   // 4096
    const int nwin = in_sizes[1] / (NT * NT);     // 64

    cudaFuncSetAttribute(winattn_kernel,
                         cudaFuncAttributeMaxDynamicSharedMemorySize, SMEM_BYTES);
    winattn_kernel<<<B, THREADS, SMEM_BYTES>>>(x, mask, qkv_w, qkv_b, proj_w, proj_b, bt, out, B > 0 ? nwin : 1);
}

// round 11
// speedup vs baseline: 3.3308x; 1.1240x over previous
#include <cuda_runtime.h>
#include <cuda_fp16.h>
#include <cstdint>

// ---------------- problem constants ----------------
#define NT     49
#define DIMC   128
#define HEADS  4
#define HD     32
#define WS     7
#define SCALEF 0.17677669529663687f
#define THREADS 512

// ---------------- smem layout (float offsets) ----------------
#define M_STRIDE 53
#define OFF_BIAS 0                     // 512
#define OFF_BT   512                   // 676
#define OFF_MASK 1188                  // 2597
#define OFF_REL  3785                  // u8[2401] -> 601 floats
#define OFF_XHI  4608                  // 64x128 fp16 tiles = 4096 floats each
#define OFF_QHI  (OFF_XHI + 4096)
#define OFF_KHI  (OFF_QHI + 4096)
#define OFF_VHI  (OFF_KHI + 4096)
#define OFF_B0   (OFF_VHI + 4096)      // 128x128 fp16 = 8192 floats
#define OFF_B1   (OFF_B0 + 8192)
#define SMEM_FLOATS (OFF_B1 + 8192)    // 37376
#define SMEM_BYTES  (SMEM_FLOATS * 4)  // 149504
// P tile (64x256 fp16, 512B rows) overlays dead x+q (contiguous 32KB):
#define OFF_PHI  OFF_XHI

static_assert(OFF_REL + 601 <= OFF_XHI, "smem overlap");
static_assert(OFF_QHI == OFF_XHI + 4096, "P overlay needs x,q contiguous");

// ---------------- helpers ----------------
__device__ __forceinline__ uint32_t smem_u32(const void* p) {
    uint32_t a;
    asm("{ .reg .u64 t; cvta.to.shared.u64 t, %1; cvt.u32.u64 %0, t; }" : "=r"(a) : "l"(p));
    return a;
}
// 256B-row tile offset (rows x 128 fp16 cols), 16B-chunk xor swizzle
__device__ __forceinline__ uint32_t toff(int r, int c) {
    return (uint32_t)(r * 256 + ((((c >> 3) ^ (r & 7))) << 4) + ((c & 7) << 1));
}
// 512B-row tile offset (P: 64 rows x 256 fp16 cols)
__device__ __forceinline__ uint32_t poff(int r, int c) {
    return (uint32_t)(r * 512 + ((((c >> 3) ^ (r & 7))) << 4) + ((c & 7) << 1));
}
__device__ __forceinline__ uint32_t packh2(float a, float b) {   // a->low, b->high
    __half2 h = __floats2half2_rn(a, b);
    return *reinterpret_cast<uint32_t*>(&h);
}
__device__ __forceinline__ float2 h2f2(uint32_t p) {
    __half2 h = *reinterpret_cast<__half2*>(&p);
    return __half22float2(h);
}
__device__ __forceinline__ void split_store2(float a, float b, char* hb, char* lb, uint32_t off) {
    uint32_t h = packh2(a, b);
    float2 hf = h2f2(h);
    uint32_t l = packh2(a - hf.x, b - hf.y);
    *(uint32_t*)(hb + off) = h;
    *(uint32_t*)(lb + off) = l;
}
__device__ __forceinline__ void store4(float4 v, char* hb, uint32_t off) {
    *(uint2*)(hb + off) = make_uint2(packh2(v.x, v.y), packh2(v.z, v.w));
}
__device__ __forceinline__ void store2(float a, float b, char* hb, uint32_t off) {
    *(uint32_t*)(hb + off) = packh2(a, b);
}

__device__ __forceinline__ void ldsm4(uint32_t r[4], uint32_t addr) {
    asm volatile("ldmatrix.sync.aligned.m8n8.x4.shared.b16 {%0,%1,%2,%3}, [%4];"
                 : "=r"(r[0]), "=r"(r[1]), "=r"(r[2]), "=r"(r[3]) : "r"(addr));
}
__device__ __forceinline__ void ldsm4t(uint32_t r[4], uint32_t addr) {
    asm volatile("ldmatrix.sync.aligned.m8n8.x4.trans.shared.b16 {%0,%1,%2,%3}, [%4];"
                 : "=r"(r[0]), "=r"(r[1]), "=r"(r[2]), "=r"(r[3]) : "r"(addr));
}
__device__ __forceinline__ void mma_f16(float d[4], const uint32_t a[4],
                                        uint32_t b0, uint32_t b1) {
    asm volatile("mma.sync.aligned.m16n8k16.row.col.f32.f16.f16.f32 "
                 "{%0,%1,%2,%3},{%4,%5,%6,%7},{%8,%9},{%0,%1,%2,%3};"
                 : "+f"(d[0]), "+f"(d[1]), "+f"(d[2]), "+f"(d[3])
                 : "r"(a[0]), "r"(a[1]), "r"(a[2]), "r"(a[3]), "r"(b0), "r"(b1));
}

// 64x128 @ (128x128)^T, single-term A. warp (rb,cb): rows rb*16..+15, cols cb*32..+31.
__device__ __forceinline__ void mma_tile_1t(uint32_t aA, uint32_t bA,
                                            int rb, int cb, int lane, float acc[4][4])
{
    #pragma unroll
    for (int k = 0; k < 4; ++k)
        #pragma unroll
        for (int j = 0; j < 4; ++j) acc[k][j] = 0.f;

    const int arow = rb * 16 + (lane & 15);
    const int achk = lane >> 4;
    const int bn   = cb * 32 + (lane & 7) + ((lane >> 4) << 3);
    const int bchk = (lane >> 3) & 1;
    const uint32_t axor = (uint32_t)(arow & 7);
    const uint32_t bxor = (uint32_t)(bn & 7);

    #pragma unroll
    for (int kk = 0; kk < 8; ++kk) {
        uint32_t ao  = (uint32_t)arow * 256 + ((((uint32_t)(kk * 2 + achk)) ^ axor) << 4);
        uint32_t bo0 = (uint32_t)bn * 256 + ((((uint32_t)(kk * 2 + bchk)) ^ bxor) << 4);
        uint32_t bo1 = bo0 + 16 * 256;
        uint32_t ah[4], bh0[4], bh1[4];
        ldsm4(ah, aA + ao);
        ldsm4(bh0, bA + bo0);
        ldsm4(bh1, bA + bo1);
        mma_f16(acc[0], ah, bh0[0], bh0[1]);
        mma_f16(acc[1], ah, bh0[2], bh0[3]);
        mma_f16(acc[2], ah, bh1[0], bh1[1]);
        mma_f16(acc[3], ah, bh1[2], bh1[3]);
    }
}

// 2-term A (hi/lo) version, for the final proj GEMM
__device__ __forceinline__ void mma_tile_2t(uint32_t ahi, uint32_t alo, uint32_t bA,
                                            int rb, int cb, int lane, float acc[4][4])
{
    #pragma unroll
    for (int k = 0; k < 4; ++k)
        #pragma unroll
        for (int j = 0; j < 4; ++j) acc[k][j] = 0.f;

    const int arow = rb * 16 + (lane & 15);
    const int achk = lane >> 4;
    const int bn   = cb * 32 + (lane & 7) + ((lane >> 4) << 3);
    const int bchk = (lane >> 3) & 1;
    const uint32_t axor = (uint32_t)(arow & 7);
    const uint32_t bxor = (uint32_t)(bn & 7);

    #pragma unroll
    for (int kk = 0; kk < 8; ++kk) {
        uint32_t ao  = (uint32_t)arow * 256 + ((((uint32_t)(kk * 2 + achk)) ^ axor) << 4);
        uint32_t bo0 = (uint32_t)bn * 256 + ((((uint32_t)(kk * 2 + bchk)) ^ bxor) << 4);
        uint32_t bo1 = bo0 + 16 * 256;
        uint32_t ah[4], al[4], bh0[4], bh1[4];
        ldsm4(ah, ahi + ao);
        ldsm4(al, alo + ao);
        ldsm4(bh0, bA + bo0);
        ldsm4(bh1, bA + bo1);
        mma_f16(acc[0], ah, bh0[0], bh0[1]);
        mma_f16(acc[1], ah, bh0[2], bh0[3]);
        mma_f16(acc[2], ah, bh1[0], bh1[1]);
        mma_f16(acc[3], ah, bh1[2], bh1[3]);
        mma_f16(acc[0], al, bh0[0], bh0[1]);
        mma_f16(acc[1], al, bh0[2], bh0[3]);
        mma_f16(acc[2], al, bh1[0], bh1[1]);
        mma_f16(acc[3], al, bh1[2], bh1[3]);
    }
}

__global__ void __launch_bounds__(THREADS, 1)
winattn_kernel(const float* __restrict__ x,
               const float* __restrict__ mask,
               const float* __restrict__ qkv_w,
               const float* __restrict__ qkv_b,
               const float* __restrict__ proj_w,
               const float* __restrict__ proj_b,
               const float* __restrict__ bt,
               float* __restrict__ out,
               int nwin)
{
    extern __shared__ float sm[];
    const uint32_t smem_base = smem_u32(sm);
    float* s_bias = sm + OFF_BIAS;
    float* s_bt   = sm + OFF_BT;
    float* s_mask = sm + OFF_MASK;
    uint8_t* s_rel = (uint8_t*)(sm + OFF_REL);
    char* base8 = (char*)sm;

    char* xhi = base8 + OFF_XHI * 4;
    char* qhi = base8 + OFF_QHI * 4;
    char* khi = base8 + OFF_KHI * 4;
    char* vhi = base8 + OFF_VHI * 4;
    char* b0  = base8 + OFF_B0 * 4;
    char* b1  = base8 + OFF_B1 * 4;
    char* phi = base8 + OFF_PHI * 4;

    const uint32_t xhiA = smem_base + OFF_XHI * 4;
    const uint32_t qhiA = smem_base + OFF_QHI * 4;
    const uint32_t khiA = smem_base + OFF_KHI * 4;
    const uint32_t vhiA = smem_base + OFF_VHI * 4;
    const uint32_t b0A  = smem_base + OFF_B0 * 4;
    const uint32_t b1A  = smem_base + OFF_B1 * 4;
    const uint32_t phiA = smem_base + OFF_PHI * 4;

    const int tid  = threadIdx.x;
    const int wid  = tid >> 5;
    const int lane = tid & 31;
    const int rb   = wid >> 2;
    const int cb   = wid & 3;
    const int b    = blockIdx.x;

    const float* xg = x + (long long)b * (NT * DIMC);
    const float* mg = mask + (long long)(b % nwin) * (NT * NT);

    // ---------------- prologue ----------------
    for (int idx = tid; idx < NT * 32; idx += THREADS) {   // x -> fp16 hi
        int r = idx >> 5, c = (idx & 31) << 2;
        store4(((const float4*)xg)[idx], xhi, toff(r, c));
    }
    {   // zero pad rows 49-63 of k/v (v mandatory: 0 * NaN hazard in PV k-dim)
        char* tiles[2] = { khi, vhi };
        for (int idx = tid; idx < 2 * 240; idx += THREADS) {
            int tl = idx / 240, rem = idx - tl * 240;
            *(uint4*)(tiles[tl] + 49 * 256 + rem * 16) = make_uint4(0, 0, 0, 0);
        }
    }
    #pragma unroll
    for (int it = 0; it < 8; ++it) {   // B buf0 = q weights
        int idx = tid + it * THREADS;
        int r = idx >> 5, c = (idx & 31) << 2;
        store4(((const float4*)qkv_w)[idx], b0, toff(r, c));
    }
    for (int idx = tid; idx < NT * NT; idx += THREADS) {
        int i = idx / NT, j = idx - i * NT;
        s_mask[i * M_STRIDE + j] = mg[idx];
        int ia = i / WS, ib = i - ia * WS;
        int ja = j / WS, jb = j - ja * WS;
        s_rel[idx] = (uint8_t)((ia - ja + WS - 1) * (2 * WS - 1) + (ib - jb + WS - 1));
    }
    for (int idx = tid; idx < 676; idx += THREADS) s_bt[idx] = bt[idx];
    for (int idx = tid; idx < 512; idx += THREADS)
        s_bias[idx] = (idx < 3 * DIMC) ? qkv_b[idx] : proj_b[idx - 3 * DIMC];
    __syncthreads();

    // ---------------- QKV GEMM: tiles t=0(q),1(k),2(v), double-buffered B ----------------
    {
        const uint32_t bufA[2] = { b0A, b1A };
        char* bufP[2] = { b0, b1 };
        #pragma unroll 1
        for (int t = 0; t < 3; ++t) {
            const float* nsrc = (t == 0) ? (qkv_w + 16384)
                              : (t == 1) ? (qkv_w + 32768) : proj_w;
            float4 pf[8];
            #pragma unroll
            for (int it = 0; it < 8; ++it)
                pf[it] = ((const float4*)nsrc)[tid + it * THREADS];

            float acc[4][4];
            mma_tile_1t(xhiA, bufA[t & 1], rb, cb, lane, acc);

            // store next weight tile into the other buffer (no sync needed)
            #pragma unroll
            for (int it = 0; it < 8; ++it) {
                int idx = tid + it * THREADS;
                store4(pf[it], bufP[(t + 1) & 1], toff(idx >> 5, (idx & 31) << 2));
            }

            // epilogue
            #pragma unroll
            for (int blk = 0; blk < 4; ++blk) {
                int n0 = cb * 32 + blk * 8 + (lane & 3) * 2;
                int r0 = rb * 16 + (lane >> 2);
                const float bb0 = s_bias[t * 128 + n0];
                const float bb1 = s_bias[t * 128 + n0 + 1];
                if (t == 0) {    // q: pre-scaled, hi only
                    if (r0 < NT)
                        store2((acc[blk][0] + bb0) * SCALEF, (acc[blk][1] + bb1) * SCALEF,
                               qhi, toff(r0, n0));
                    if (r0 + 8 < NT)
                        store2((acc[blk][2] + bb0) * SCALEF, (acc[blk][3] + bb1) * SCALEF,
                               qhi, toff(r0 + 8, n0));
                } else {
                    char* dst = (t == 1) ? khi : vhi;
                    if (r0 < NT)
                        store2(acc[blk][0] + bb0, acc[blk][1] + bb1, dst, toff(r0, n0));
                    if (r0 + 8 < NT)
                        store2(acc[blk][2] + bb0, acc[blk][3] + bb1, dst, toff(r0 + 8, n0));
                }
            }
            __syncthreads();
        }
    }
    // b1 holds proj weights; q/k/v ready

    // ---------------- scores: S_h = q_h @ k_h^T (fp16 single-term) ----------------
    const int h = cb;
    const int arow = rb * 16 + (lane & 15);
    const uint32_t axor = (uint32_t)(arow & 7);
    float sacc[7][4];
    #pragma unroll
    for (int bk = 0; bk < 7; ++bk)
        #pragma unroll
        for (int j = 0; j < 4; ++j) sacc[bk][j] = 0.f;

    #pragma unroll
    for (int kk = 0; kk < 2; ++kk) {
        uint32_t achunk = (uint32_t)(h * 4 + kk * 2 + (lane >> 4));
        uint32_t ao = (uint32_t)arow * 256 + ((achunk ^ axor) << 4);
        uint32_t qh_[4];
        ldsm4(qh_, qhiA + ao);
        #pragma unroll
        for (int g = 0; g < 4; ++g) {
            int bn = g * 16 + (lane & 7) + ((lane >> 4) << 3);
            uint32_t bchunk = (uint32_t)(h * 4 + kk * 2 + ((lane >> 3) & 1));
            uint32_t bo = (uint32_t)bn * 256 + ((bchunk ^ (uint32_t)(bn & 7)) << 4);
            uint32_t kh_[4];
            ldsm4(kh_, khiA + bo);
            mma_f16(sacc[2 * g], qh_, kh_[0], kh_[1]);
            if (2 * g + 1 < 7)
                mma_f16(sacc[2 * g + 1], qh_, kh_[2], kh_[3]);
        }
    }
    __syncthreads();   // q/k reads done -> P tile (over x+q) writable

    // ---------------- softmax on fragments -> P (fp16 hi only) ----------------
    {
        if (tid < 256) {   // zero P pad cols 56-63
            int r = tid & 63, hh = (tid >> 6);
            *(uint4*)(phi + poff(r, hh * 64 + 56)) = make_uint4(0, 0, 0, 0);
        }
        const int r0 = rb * 16 + (lane >> 2);
        const int r1 = r0 + 8;
        float sum0 = 0.f, sum1 = 0.f;
        #pragma unroll
        for (int bk = 0; bk < 7; ++bk) {
            int j0 = bk * 8 + (lane & 3) * 2;
            float e00 = 0.f, e01 = 0.f, e10 = 0.f, e11 = 0.f;
            if (j0 < NT) {
                e00 = __expf(sacc[bk][0] + s_bt[(int)s_rel[r0 * NT + j0] * HEADS + h]
                             + s_mask[r0 * M_STRIDE + j0]);
                e10 = __expf(sacc[bk][2] + s_bt[(int)s_rel[r1 * NT + j0] * HEADS + h]
                             + s_mask[r1 * M_STRIDE + j0]);
            }
            if (j0 + 1 < NT) {
                e01 = __expf(sacc[bk][1] + s_bt[(int)s_rel[r0 * NT + j0 + 1] * HEADS + h]
                             + s_mask[r0 * M_STRIDE + j0 + 1]);
                e11 = __expf(sacc[bk][3] + s_bt[(int)s_rel[r1 * NT + j0 + 1] * HEADS + h]
                             + s_mask[r1 * M_STRIDE + j0 + 1]);
            }
            sum0 += e00 + e01;
            sum1 += e10 + e11;
            sacc[bk][0] = e00; sacc[bk][1] = e01; sacc[bk][2] = e10; sacc[bk][3] = e11;
        }
        sum0 += __shfl_xor_sync(0xffffffffu, sum0, 1);
        sum0 += __shfl_xor_sync(0xffffffffu, sum0, 2);
        sum1 += __shfl_xor_sync(0xffffffffu, sum1, 1);
        sum1 += __shfl_xor_sync(0xffffffffu, sum1, 2);
        const float inv0 = 1.0f / sum0;
        const float inv1 = 1.0f / sum1;
        #pragma unroll
        for (int bk = 0; bk < 7; ++bk) {
            int j0 = bk * 8 + (lane & 3) * 2;
            store2(sacc[bk][0] * inv0, sacc[bk][1] * inv0, phi, poff(r0, h * 64 + j0));
            store2(sacc[bk][2] * inv1, sacc[bk][3] * inv1, phi, poff(r1, h * 64 + j0));
        }
    }
    __syncthreads();

    // ---------------- PV: out_h = P_h @ v_h (P single-term, V via ldmatrix.trans) ----------------
    float pacc[4][4];
    {
        #pragma unroll
        for (int bk = 0; bk < 4; ++bk)
            #pragma unroll
            for (int j = 0; j < 4; ++j) pacc[bk][j] = 0.f;

        #pragma unroll
        for (int kk = 0; kk < 4; ++kk) {
            uint32_t achunk = (uint32_t)(h * 8 + kk * 2 + (lane >> 4));
            uint32_t ao = (uint32_t)arow * 512 + ((achunk ^ axor) << 4);
            uint32_t ph_[4];
            ldsm4(ph_, phiA + ao);
            #pragma unroll
            for (int g = 0; g < 2; ++g) {
                int vr = kk * 16 + ((lane >> 3) & 1) * 8 + (lane & 7);
                uint32_t vchunk = (uint32_t)(h * 4 + g * 2 + (lane >> 4));
                uint32_t vo = (uint32_t)vr * 256 + ((vchunk ^ (uint32_t)(vr & 7)) << 4);
                uint32_t vh_[4];
                ldsm4t(vh_, vhiA + vo);
                mma_f16(pacc[2 * g],     ph_, vh_[0], vh_[1]);
                mma_f16(pacc[2 * g + 1], ph_, vh_[2], vh_[3]);
            }
        }
    }
    __syncthreads();   // PV v-reads done -> k/v tiles reusable for attn-out

    // attn-out -> hi in khi, lo in vhi (A-side of proj, 2-term for precision)
    {
        const int r0 = rb * 16 + (lane >> 2);
        #pragma unroll
        for (int bk = 0; bk < 4; ++bk) {
            int d0 = bk * 8 + (lane & 3) * 2;
            split_store2(pacc[bk][0], pacc[bk][1], khi, vhi, toff(r0, h * HD + d0));
            split_store2(pacc[bk][2], pacc[bk][3], khi, vhi, toff(r0 + 8, h * HD + d0));
        }
    }
    __syncthreads();

    // ---------------- proj GEMM (A = attn-out hi/lo, B = b1) -> global ----------------
    {
        float acc[4][4];
        mma_tile_2t(khiA, vhiA, b1A, rb, cb, lane, acc);
        float* dstbase = out + (long long)b * (NT * DIMC);
        #pragma unroll
        for (int blk = 0; blk < 4; ++blk) {
            int n0 = cb * 32 + blk * 8 + (lane & 3) * 2;
            int r0 = rb * 16 + (lane >> 2);
            const float bb0 = s_bias[3 * DIMC + n0];
            const float bb1 = s_bias[3 * DIMC + n0 + 1];
            if (r0 < NT) {
                float* p = dstbase + r0 * DIMC + n0;
                p[0] = acc[blk][0] + bb0;
                p[1] = acc[blk][1] + bb1;
            }
            if (r0 + 8 < NT) {
                float* p = dstbase + (r0 + 8) * DIMC + n0;
                p[0] = acc[blk][2] + bb0;
                p[1] = acc[blk][3] + bb1;
            }
        }
    }
}

extern "C" void kernel_launch(void* const* d_in, const int* in_sizes, int n_in,
                              void* d_out, int out_size) {
    const float* x      = (const float*)d_in[0];
    const float* mask   = (const float*)d_in[1];
    const float* qkv_w  = (const float*)d_in[2];
    const float* qkv_b  = (const float*)d_in[3];
    const float* proj_w = (const float*)d_in[4];
    const float* proj_b = (const float*)d_in[5];
    const float* bt     = (const float*)d_in[6];
    float* out = (float*)d_out;

    const int B    = in_sizes[0] / (NT * DIMC);   // 4096
    const int nwin = in_sizes[1] / (NT * NT);     // 64

    cudaFuncSetAttribute(winattn_kernel,
                         cudaFuncAttributeMaxDynamicSharedMemorySize, SMEM_BYTES);
    winattn_kernel<<<B, THREADS, SMEM_BYTES>>>(x, mask, qkv_w, qkv_b, proj_w, proj_b, bt, out, B > 0 ? nwin : 1);
}

// round 12
// speedup vs baseline: 3.9361x; 1.1817x over previous
#include <cuda_runtime.h>
#include <cuda_fp16.h>
#include <cstdint>

// ---------------- problem constants ----------------
#define NT     49
#define DIMC   128
#define HEADS  4
#define HD     32
#define WS     7
#define SCALEF 0.17677669529663687f
#define THREADS 256

// ---------------- smem layout (float offsets) ----------------
#define M_STRIDE 54                    // halves; even -> aligned __half2 loads
#define OFF_BIAS  0                    // 512
#define OFF_BT    512                  // 676
#define OFF_MASKH 1188                 // fp16[49][54] = 2646 halves -> 1324 floats
#define OFF_REL   2512                 // u8[2401] -> 601 floats
#define OFF_XHI   3136                 // 64x128 fp16 tiles = 4096 floats each
#define OFF_QHI   (OFF_XHI + 4096)
#define OFF_KHI   (OFF_QHI + 4096)
#define OFF_VHI   (OFF_KHI + 4096)
#define OFF_B0    (OFF_VHI + 4096)     // 128x128 fp16 = 8192 floats
#define SMEM_FLOATS (OFF_B0 + 8192)    // 27712
#define SMEM_BYTES  (SMEM_FLOATS * 4)  // 110848 (x2 CTAs = 216.6KB <= 228KB)
// P tile (64x256 fp16, 512B rows) overlays dead x+q (contiguous 32KB):
#define OFF_PHI  OFF_XHI

static_assert(OFF_REL + 601 <= OFF_XHI, "smem overlap");
static_assert(OFF_QHI == OFF_XHI + 4096, "P overlay needs x,q contiguous");

// ---------------- helpers ----------------
__device__ __forceinline__ uint32_t smem_u32(const void* p) {
    uint32_t a;
    asm("{ .reg .u64 t; cvta.to.shared.u64 t, %1; cvt.u32.u64 %0, t; }" : "=r"(a) : "l"(p));
    return a;
}
__device__ __forceinline__ uint32_t toff(int r, int c) {       // 256B rows
    return (uint32_t)(r * 256 + ((((c >> 3) ^ (r & 7))) << 4) + ((c & 7) << 1));
}
__device__ __forceinline__ uint32_t poff(int r, int c) {       // 512B rows (P)
    return (uint32_t)(r * 512 + ((((c >> 3) ^ (r & 7))) << 4) + ((c & 7) << 1));
}
__device__ __forceinline__ uint32_t packh2(float a, float b) { // a->low, b->high
    __half2 h = __floats2half2_rn(a, b);
    return *reinterpret_cast<uint32_t*>(&h);
}
__device__ __forceinline__ float2 h2f2(uint32_t p) {
    __half2 h = *reinterpret_cast<__half2*>(&p);
    return __half22float2(h);
}
__device__ __forceinline__ void split_store2(float a, float b, char* hb, char* lb, uint32_t off) {
    uint32_t h = packh2(a, b);
    float2 hf = h2f2(h);
    uint32_t l = packh2(a - hf.x, b - hf.y);
    *(uint32_t*)(hb + off) = h;
    *(uint32_t*)(lb + off) = l;
}
__device__ __forceinline__ void store4(float4 v, char* hb, uint32_t off) {
    *(uint2*)(hb + off) = make_uint2(packh2(v.x, v.y), packh2(v.z, v.w));
}
__device__ __forceinline__ void store2(float a, float b, char* hb, uint32_t off) {
    *(uint32_t*)(hb + off) = packh2(a, b);
}
__device__ __forceinline__ void ldsm4(uint32_t r[4], uint32_t addr) {
    asm volatile("ldmatrix.sync.aligned.m8n8.x4.shared.b16 {%0,%1,%2,%3}, [%4];"
                 : "=r"(r[0]), "=r"(r[1]), "=r"(r[2]), "=r"(r[3]) : "r"(addr));
}
__device__ __forceinline__ void ldsm4t(uint32_t r[4], uint32_t addr) {
    asm volatile("ldmatrix.sync.aligned.m8n8.x4.trans.shared.b16 {%0,%1,%2,%3}, [%4];"
                 : "=r"(r[0]), "=r"(r[1]), "=r"(r[2]), "=r"(r[3]) : "r"(addr));
}
__device__ __forceinline__ void mma_f16(float d[4], const uint32_t a[4],
                                        uint32_t b0, uint32_t b1) {
    asm volatile("mma.sync.aligned.m16n8k16.row.col.f32.f16.f16.f32 "
                 "{%0,%1,%2,%3},{%4,%5,%6,%7},{%8,%9},{%0,%1,%2,%3};"
                 : "+f"(d[0]), "+f"(d[1]), "+f"(d[2]), "+f"(d[3])
                 : "r"(a[0]), "r"(a[1]), "r"(a[2]), "r"(a[3]), "r"(b0), "r"(b1));
}

// 64x128 @ (128x128)^T, single-term A, 2 col-blocks per warp.
// warp (rb,cp): rows rb*16..+15, cols cp*64..+63.
__device__ __forceinline__ void mma_tile_1t(uint32_t aA, uint32_t bA,
                                            int rb, int cp, int lane, float acc[2][4][4])
{
    #pragma unroll
    for (int c = 0; c < 2; ++c)
        #pragma unroll
        for (int k = 0; k < 4; ++k)
            #pragma unroll
            for (int j = 0; j < 4; ++j) acc[c][k][j] = 0.f;

    const int arow = rb * 16 + (lane & 15);
    const int achk = lane >> 4;
    const uint32_t axor = (uint32_t)(arow & 7);
    const int bn0  = cp * 64 + (lane & 7) + ((lane >> 4) << 3);
    const int bchk = (lane >> 3) & 1;
    const uint32_t bxor = (uint32_t)(bn0 & 7);

    #pragma unroll
    for (int kk = 0; kk < 8; ++kk) {
        uint32_t ao = (uint32_t)arow * 256 + ((((uint32_t)(kk * 2 + achk)) ^ axor) << 4);
        uint32_t ah[4];
        ldsm4(ah, aA + ao);
        #pragma unroll
        for (int c = 0; c < 2; ++c) {
            uint32_t bo0 = (uint32_t)(bn0 + 32 * c) * 256
                         + ((((uint32_t)(kk * 2 + bchk)) ^ bxor) << 4);
            uint32_t bo1 = bo0 + 16 * 256;
            uint32_t bh0[4], bh1[4];
            ldsm4(bh0, bA + bo0);
            ldsm4(bh1, bA + bo1);
            mma_f16(acc[c][0], ah, bh0[0], bh0[1]);
            mma_f16(acc[c][1], ah, bh0[2], bh0[3]);
            mma_f16(acc[c][2], ah, bh1[0], bh1[1]);
            mma_f16(acc[c][3], ah, bh1[2], bh1[3]);
        }
    }
}

// 2-term A (hi/lo), 2 col-blocks per warp (final proj GEMM)
__device__ __forceinline__ void mma_tile_2t(uint32_t ahi, uint32_t alo, uint32_t bA,
                                            int rb, int cp, int lane, float acc[2][4][4])
{
    #pragma unroll
    for (int c = 0; c < 2; ++c)
        #pragma unroll
        for (int k = 0; k < 4; ++k)
            #pragma unroll
            for (int j = 0; j < 4; ++j) acc[c][k][j] = 0.f;

    const int arow = rb * 16 + (lane & 15);
    const int achk = lane >> 4;
    const uint32_t axor = (uint32_t)(arow & 7);
    const int bn0  = cp * 64 + (lane & 7) + ((lane >> 4) << 3);
    const int bchk = (lane >> 3) & 1;
    const uint32_t bxor = (uint32_t)(bn0 & 7);

    #pragma unroll
    for (int kk = 0; kk < 8; ++kk) {
        uint32_t ao = (uint32_t)arow * 256 + ((((uint32_t)(kk * 2 + achk)) ^ axor) << 4);
        uint32_t ah[4], al[4];
        ldsm4(ah, ahi + ao);
        ldsm4(al, alo + ao);
        #pragma unroll
        for (int c = 0; c < 2; ++c) {
            uint32_t bo0 = (uint32_t)(bn0 + 32 * c) * 256
                         + ((((uint32_t)(kk * 2 + bchk)) ^ bxor) << 4);
            uint32_t bo1 = bo0 + 16 * 256;
            uint32_t bh0[4], bh1[4];
            ldsm4(bh0, bA + bo0);
            ldsm4(bh1, bA + bo1);
            mma_f16(acc[c][0], ah, bh0[0], bh0[1]);
            mma_f16(acc[c][1], ah, bh0[2], bh0[3]);
            mma_f16(acc[c][2], ah, bh1[0], bh1[1]);
            mma_f16(acc[c][3], ah, bh1[2], bh1[3]);
            mma_f16(acc[c][0], al, bh0[0], bh0[1]);
            mma_f16(acc[c][1], al, bh0[2], bh0[3]);
            mma_f16(acc[c][2], al, bh1[0], bh1[1]);
            mma_f16(acc[c][3], al, bh1[2], bh1[3]);
        }
    }
}

__global__ void __launch_bounds__(THREADS, 2)
winattn_kernel(const float* __restrict__ x,
               const float* __restrict__ mask,
               const float* __restrict__ qkv_w,
               const float* __restrict__ qkv_b,
               const float* __restrict__ proj_w,
               const float* __restrict__ proj_b,
               const float* __restrict__ bt,
               float* __restrict__ out,
               int nwin)
{
    extern __shared__ float sm[];
    const uint32_t smem_base = smem_u32(sm);
    float* s_bias = sm + OFF_BIAS;
    float* s_bt   = sm + OFF_BT;
    __half* s_maskh = (__half*)(sm + OFF_MASKH);
    uint8_t* s_rel = (uint8_t*)(sm + OFF_REL);
    char* base8 = (char*)sm;

    char* xhi = base8 + OFF_XHI * 4;
    char* qhi = base8 + OFF_QHI * 4;
    char* khi = base8 + OFF_KHI * 4;
    char* vhi = base8 + OFF_VHI * 4;
    char* b0  = base8 + OFF_B0 * 4;
    char* phi = base8 + OFF_PHI * 4;

    const uint32_t xhiA = smem_base + OFF_XHI * 4;
    const uint32_t qhiA = smem_base + OFF_QHI * 4;
    const uint32_t khiA = smem_base + OFF_KHI * 4;
    const uint32_t vhiA = smem_base + OFF_VHI * 4;
    const uint32_t b0A  = smem_base + OFF_B0 * 4;
    const uint32_t phiA = smem_base + OFF_PHI * 4;

    const int tid  = threadIdx.x;
    const int wid  = tid >> 5;
    const int lane = tid & 31;
    const int rb   = wid & 3;     // row block 0..3
    const int cp   = wid >> 2;    // col pair 0..1 (cols cp*64..+63 / heads cp*2,cp*2+1)
    const int b    = blockIdx.x;

    const float* xg = x + (long long)b * (NT * DIMC);
    const float* mg = mask + (long long)(b % nwin) * (NT * NT);

    // ---------------- prologue ----------------
    for (int idx = tid; idx < NT * 32; idx += THREADS) {   // x -> fp16
        int r = idx >> 5, c = (idx & 31) << 2;
        store4(((const float4*)xg)[idx], xhi, toff(r, c));
    }
    for (int idx = tid; idx < 240; idx += THREADS)         // zero v pad rows 49-63
        *(uint4*)(vhi + 49 * 256 + idx * 16) = make_uint4(0, 0, 0, 0);
    #pragma unroll
    for (int it = 0; it < 16; ++it) {                      // B = q weights
        int idx = tid + it * THREADS;
        int r = idx >> 5, c = (idx & 31) << 2;
        store4(((const float4*)qkv_w)[idx], b0, toff(r, c));
    }
    for (int idx = tid; idx < NT * NT; idx += THREADS) {
        int i = idx / NT, j = idx - i * NT;
        s_maskh[i * M_STRIDE + j] = __float2half(mg[idx]);
        int ia = i / WS, ib = i - ia * WS;
        int ja = j / WS, jb = j - ja * WS;
        s_rel[idx] = (uint8_t)((ia - ja + WS - 1) * (2 * WS - 1) + (ib - jb + WS - 1));
    }
    for (int idx = tid; idx < 676; idx += THREADS) s_bt[idx] = bt[idx];
    for (int idx = tid; idx < 512; idx += THREADS)
        s_bias[idx] = (idx < 3 * DIMC) ? qkv_b[idx] : proj_b[idx - 3 * DIMC];
    __syncthreads();

    // ---------------- QKV GEMM: tiles t=0(q),1(k),2(v), single B buffer ----------------
    #pragma unroll 1
    for (int t = 0; t < 3; ++t) {
        const float* nsrc = (t == 0) ? (qkv_w + 16384)
                          : (t == 1) ? (qkv_w + 32768) : proj_w;
        uint2 pf[16];
        #pragma unroll
        for (int it = 0; it < 16; ++it) {
            float4 v = ((const float4*)nsrc)[tid + it * THREADS];
            pf[it] = make_uint2(packh2(v.x, v.y), packh2(v.z, v.w));
        }

        float acc[2][4][4];
        mma_tile_1t(xhiA, b0A, rb, cp, lane, acc);

        #pragma unroll
        for (int c = 0; c < 2; ++c) {
            #pragma unroll
            for (int blk = 0; blk < 4; ++blk) {
                int n0 = (cp * 2 + c) * 32 + blk * 8 + (lane & 3) * 2;
                int r0 = rb * 16 + (lane >> 2);
                const float bb0 = s_bias[t * 128 + n0];
                const float bb1 = s_bias[t * 128 + n0 + 1];
                if (t == 0) {
                    if (r0 < NT)
                        store2((acc[c][blk][0] + bb0) * SCALEF, (acc[c][blk][1] + bb1) * SCALEF,
                               qhi, toff(r0, n0));
                    if (r0 + 8 < NT)
                        store2((acc[c][blk][2] + bb0) * SCALEF, (acc[c][blk][3] + bb1) * SCALEF,
                               qhi, toff(r0 + 8, n0));
                } else {
                    char* dst = (t == 1) ? khi : vhi;
                    if (r0 < NT)
                        store2(acc[c][blk][0] + bb0, acc[c][blk][1] + bb1, dst, toff(r0, n0));
                    if (r0 + 8 < NT)
                        store2(acc[c][blk][2] + bb0, acc[c][blk][3] + bb1, dst, toff(r0 + 8, n0));
                }
            }
        }
        __syncthreads();    // all B reads done
        #pragma unroll
        for (int it = 0; it < 16; ++it) {
            int idx = tid + it * THREADS;
            *(uint2*)(b0 + toff(idx >> 5, (idx & 31) << 2)) = pf[it];
        }
        __syncthreads();    // B refilled
    }
    // b0 holds proj weights; q/k/v ready

    // ---------------- scores: S_h = q_h @ k_h^T for h in {cp*2, cp*2+1} ----------------
    const int arow = rb * 16 + (lane & 15);
    const uint32_t axor = (uint32_t)(arow & 7);
    float sacc[2][7][4];
    #pragma unroll
    for (int h2 = 0; h2 < 2; ++h2)
        #pragma unroll
        for (int bk = 0; bk < 7; ++bk)
            #pragma unroll
            for (int j = 0; j < 4; ++j) sacc[h2][bk][j] = 0.f;

    #pragma unroll
    for (int h2 = 0; h2 < 2; ++h2) {
        const int h = cp * 2 + h2;
        #pragma unroll
        for (int kk = 0; kk < 2; ++kk) {
            uint32_t achunk = (uint32_t)(h * 4 + kk * 2 + (lane >> 4));
            uint32_t ao = (uint32_t)arow * 256 + ((achunk ^ axor) << 4);
            uint32_t qh_[4];
            ldsm4(qh_, qhiA + ao);
            #pragma unroll
            for (int g = 0; g < 4; ++g) {
                int bn = g * 16 + (lane & 7) + ((lane >> 4) << 3);
                uint32_t bchunk = (uint32_t)(h * 4 + kk * 2 + ((lane >> 3) & 1));
                uint32_t bo = (uint32_t)bn * 256 + ((bchunk ^ (uint32_t)(bn & 7)) << 4);
                uint32_t kh_[4];
                ldsm4(kh_, khiA + bo);
                mma_f16(sacc[h2][2 * g], qh_, kh_[0], kh_[1]);
                if (2 * g + 1 < 7)
                    mma_f16(sacc[h2][2 * g + 1], qh_, kh_[2], kh_[3]);
            }
        }
    }
    __syncthreads();   // q/k reads done -> P tile (over x+q) writable

    // ---------------- softmax on fragments -> P (fp16) ----------------
    {
        {   // zero P pad cols 56-63 (256 threads cover 64 rows x 4 heads)
            int r = tid & 63, hh = tid >> 6;
            *(uint4*)(phi + poff(r, hh * 64 + 56)) = make_uint4(0, 0, 0, 0);
        }
        const int r0 = rb * 16 + (lane >> 2);
        const int r1 = r0 + 8;
        #pragma unroll
        for (int h2 = 0; h2 < 2; ++h2) {
            const int h = cp * 2 + h2;
            float sum0 = 0.f, sum1 = 0.f;
            #pragma unroll
            for (int bk = 0; bk < 7; ++bk) {
                int j0 = bk * 8 + (lane & 3) * 2;
                float e00 = 0.f, e01 = 0.f, e10 = 0.f, e11 = 0.f;
                if (j0 < NT) {
                    float2 m0 = __half22float2(*(const __half2*)&s_maskh[r0 * M_STRIDE + j0]);
                    float2 m1 = __half22float2(*(const __half2*)&s_maskh[r1 * M_STRIDE + j0]);
                    e00 = __expf(sacc[h2][bk][0] + s_bt[(int)s_rel[r0 * NT + j0] * HEADS + h] + m0.x);
                    e10 = __expf(sacc[h2][bk][2] + s_bt[(int)s_rel[r1 * NT + j0] * HEADS + h] + m1.x);
                    if (j0 + 1 < NT) {
                        e01 = __expf(sacc[h2][bk][1] + s_bt[(int)s_rel[r0 * NT + j0 + 1] * HEADS + h] + m0.y);
                        e11 = __expf(sacc[h2][bk][3] + s_bt[(int)s_rel[r1 * NT + j0 + 1] * HEADS + h] + m1.y);
                    }
                }
                sum0 += e00 + e01;
                sum1 += e10 + e11;
                sacc[h2][bk][0] = e00; sacc[h2][bk][1] = e01;
                sacc[h2][bk][2] = e10; sacc[h2][bk][3] = e11;
            }
            sum0 += __shfl_xor_sync(0xffffffffu, sum0, 1);
            sum0 += __shfl_xor_sync(0xffffffffu, sum0, 2);
            sum1 += __shfl_xor_sync(0xffffffffu, sum1, 1);
            sum1 += __shfl_xor_sync(0xffffffffu, sum1, 2);
            const float inv0 = 1.0f / sum0;
            const float inv1 = 1.0f / sum1;
            #pragma unroll
            for (int bk = 0; bk < 7; ++bk) {
                int j0 = bk * 8 + (lane & 3) * 2;
                store2(sacc[h2][bk][0] * inv0, sacc[h2][bk][1] * inv0, phi, poff(r0, h * 64 + j0));
                store2(sacc[h2][bk][2] * inv1, sacc[h2][bk][3] * inv1, phi, poff(r1, h * 64 + j0));
            }
        }
    }
    __syncthreads();

    // ---------------- PV: out_h = P_h @ v_h (V via ldmatrix.trans) ----------------
    float pacc[2][4][4];
    {
        #pragma unroll
        for (int h2 = 0; h2 < 2; ++h2)
            #pragma unroll
            for (int bk = 0; bk < 4; ++bk)
                #pragma unroll
                for (int j = 0; j < 4; ++j) pacc[h2][bk][j] = 0.f;

        #pragma unroll
        for (int h2 = 0; h2 < 2; ++h2) {
            const int h = cp * 2 + h2;
            #pragma unroll
            for (int kk = 0; kk < 4; ++kk) {
                uint32_t achunk = (uint32_t)(h * 8 + kk * 2 + (lane >> 4));
                uint32_t ao = (uint32_t)arow * 512 + ((achunk ^ axor) << 4);
                uint32_t ph_[4];
                ldsm4(ph_, phiA + ao);
                #pragma unroll
                for (int g = 0; g < 2; ++g) {
                    int vr = kk * 16 + ((lane >> 3) & 1) * 8 + (lane & 7);
                    uint32_t vchunk = (uint32_t)(h * 4 + g * 2 + (lane >> 4));
                    uint32_t vo = (uint32_t)vr * 256 + ((vchunk ^ (uint32_t)(vr & 7)) << 4);
                    uint32_t vh_[4];
                    ldsm4t(vh_, vhiA + vo);
                    mma_f16(pacc[h2][2 * g],     ph_, vh_[0], vh_[1]);
                    mma_f16(pacc[h2][2 * g + 1], ph_, vh_[2], vh_[3]);
                }
            }
        }
    }
    __syncthreads();   // v reads done -> k/v tiles reusable for attn-out

    // attn-out -> hi in khi, lo in vhi (A-side of proj, 2-term)
    {
        const int r0 = rb * 16 + (lane >> 2);
        #pragma unroll
        for (int h2 = 0; h2 < 2; ++h2) {
            const int h = cp * 2 + h2;
            #pragma unroll
            for (int bk = 0; bk < 4; ++bk) {
                int d0 = bk * 8 + (lane & 3) * 2;
                split_store2(pacc[h2][bk][0], pacc[h2][bk][1], khi, vhi, toff(r0, h * HD + d0));
                split_store2(pacc[h2][bk][2], pacc[h2][bk][3], khi, vhi, toff(r0 + 8, h * HD + d0));
            }
        }
    }
    __syncthreads();

    // ---------------- proj GEMM (A = attn-out hi/lo, B = b0) -> global ----------------
    {
        float acc[2][4][4];
        mma_tile_2t(khiA, vhiA, b0A, rb, cp, lane, acc);
        float* dstbase = out + (long long)b * (NT * DIMC);
        #pragma unroll
        for (int c = 0; c < 2; ++c) {
            #pragma unroll
            for (int blk = 0; blk < 4; ++blk) {
                int n0 = (cp * 2 + c) * 32 + blk * 8 + (lane & 3) * 2;
                int r0 = rb * 16 + (lane >> 2);
                const float bb0 = s_bias[3 * DIMC + n0];
                const float bb1 = s_bias[3 * DIMC + n0 + 1];
                if (r0 < NT) {
                    float* p = dstbase + r0 * DIMC + n0;
                    p[0] = acc[c][blk][0] + bb0;
                    p[1] = acc[c][blk][1] + bb1;
                }
                if (r0 + 8 < NT) {
                    float* p = dstbase + (r0 + 8) * DIMC + n0;
                    p[0] = acc[c][blk][2] + bb0;
                    p[1] = acc[c][blk][3] + bb1;
                }
            }
        }
    }
}

extern "C" void kernel_launch(void* const* d_in, const int* in_sizes, int n_in,
                              void* d_out, int out_size) {
    const float* x      = (const float*)d_in[0];
    const float* mask   = (const float*)d_in[1];
    const float* qkv_w  = (const float*)d_in[2];
    const float* qkv_b  = (const float*)d_in[3];
    const float* proj_w = (const float*)d_in[4];
    const float* proj_b = (const float*)d_in[5];
    const float* bt     = (const float*)d_in[6];
    float* out = (float*)d_out;

    const int B    = in_sizes[0] / (NT * DIMC);   // 4096
    const int nwin = in_sizes[1] / (NT * NT);     // 64

    cudaFuncSetAttribute(winattn_kernel,
                         cudaFuncAttributeMaxDynamicSharedMemorySize, SMEM_BYTES);
    winattn_kernel<<<B, THREADS, SMEM_BYTES>>>(x, mask, qkv_w, qkv_b, proj_w, proj_b, bt, out, B > 0 ? nwin : 1);
}

// round 13
// speedup vs baseline: 4.7421x; 1.2048x over previous
#include <cuda_runtime.h>
#include <cuda_fp16.h>
#include <cstdint>

// ---------------- problem constants ----------------
#define NT     49
#define DIMC   128
#define HEADS  4
#define HD     32
#define WS     7
#define SCALEF 0.17677669529663687f
#define THREADS 256

// ---------------- global scratch (static, allowed) ----------------
__device__ __align__(16) unsigned char g_wtile[4 * 32768];   // fp16 swizzled weight tiles
__device__ __align__(16) unsigned char g_maskh[64 * 5488];   // fp16 mask [64][49][56]
__device__ __align__(16) unsigned char g_rel[2416];          // u8 rel idx [49*49]

// ---------------- smem layout (float offsets) ----------------
#define M_STRIDE 56                    // halves; even -> aligned __half2
#define OFF_BIAS  0                    // 512
#define OFF_BT    512                  // 676
#define OFF_MASKH 1188                 // fp16[49][56] = 2744 halves -> 1372 floats
#define OFF_REL   2560                 // u8[2416] -> 604 floats
#define OFF_XHI   3200                 // 256B aligned; 64x128 fp16 tiles = 4096 floats
#define OFF_QHI   (OFF_XHI + 4096)
#define OFF_KHI   (OFF_QHI + 4096)
#define OFF_VHI   (OFF_KHI + 4096)
#define OFF_B0    (OFF_VHI + 4096)     // 128x128 fp16 = 8192 floats
#define SMEM_FLOATS (OFF_B0 + 8192)    // 27776
#define SMEM_BYTES  (SMEM_FLOATS * 4)  // 111104 (x2 CTAs = 217KB)
#define OFF_PHI  OFF_XHI               // P tile overlays dead x+q

static_assert(OFF_REL + 604 <= OFF_XHI, "smem overlap");
static_assert(OFF_QHI == OFF_XHI + 4096, "P overlay needs x,q contiguous");
static_assert((OFF_XHI * 4) % 256 == 0, "tile align");

// ---------------- helpers ----------------
__device__ __forceinline__ uint32_t smem_u32(const void* p) {
    uint32_t a;
    asm("{ .reg .u64 t; cvta.to.shared.u64 t, %1; cvt.u32.u64 %0, t; }" : "=r"(a) : "l"(p));
    return a;
}
__device__ __forceinline__ uint32_t toff(int r, int c) {       // 256B rows
    return (uint32_t)(r * 256 + ((((c >> 3) ^ (r & 7))) << 4) + ((c & 7) << 1));
}
__device__ __forceinline__ uint32_t poff(int r, int c) {       // 512B rows (P)
    return (uint32_t)(r * 512 + ((((c >> 3) ^ (r & 7))) << 4) + ((c & 7) << 1));
}
__device__ __forceinline__ uint32_t packh2(float a, float b) { // a->low, b->high
    __half2 h = __floats2half2_rn(a, b);
    return *reinterpret_cast<uint32_t*>(&h);
}
__device__ __forceinline__ float2 h2f2(uint32_t p) {
    __half2 h = *reinterpret_cast<__half2*>(&p);
    return __half22float2(h);
}
__device__ __forceinline__ void split_store2(float a, float b, char* hb, char* lb, uint32_t off) {
    uint32_t h = packh2(a, b);
    float2 hf = h2f2(h);
    uint32_t l = packh2(a - hf.x, b - hf.y);
    *(uint32_t*)(hb + off) = h;
    *(uint32_t*)(lb + off) = l;
}
__device__ __forceinline__ void store4(float4 v, char* hb, uint32_t off) {
    *(uint2*)(hb + off) = make_uint2(packh2(v.x, v.y), packh2(v.z, v.w));
}
__device__ __forceinline__ void store2(float a, float b, char* hb, uint32_t off) {
    *(uint32_t*)(hb + off) = packh2(a, b);
}
__device__ __forceinline__ void ldsm4(uint32_t r[4], uint32_t addr) {
    asm volatile("ldmatrix.sync.aligned.m8n8.x4.shared.b16 {%0,%1,%2,%3}, [%4];"
                 : "=r"(r[0]), "=r"(r[1]), "=r"(r[2]), "=r"(r[3]) : "r"(addr));
}
__device__ __forceinline__ void ldsm4t(uint32_t r[4], uint32_t addr) {
    asm volatile("ldmatrix.sync.aligned.m8n8.x4.trans.shared.b16 {%0,%1,%2,%3}, [%4];"
                 : "=r"(r[0]), "=r"(r[1]), "=r"(r[2]), "=r"(r[3]) : "r"(addr));
}
__device__ __forceinline__ void mma_f16(float d[4], const uint32_t a[4],
                                        uint32_t b0, uint32_t b1) {
    asm volatile("mma.sync.aligned.m16n8k16.row.col.f32.f16.f16.f32 "
                 "{%0,%1,%2,%3},{%4,%5,%6,%7},{%8,%9},{%0,%1,%2,%3};"
                 : "+f"(d[0]), "+f"(d[1]), "+f"(d[2]), "+f"(d[3])
                 : "r"(a[0]), "r"(a[1]), "r"(a[2]), "r"(a[3]), "r"(b0), "r"(b1));
}
#define CPA16(dst, src) \
    asm volatile("cp.async.cg.shared.global [%0], [%1], 16;" \
                 :: "r"((uint32_t)(dst)), "l"(src) : "memory")
#define CPA_COMMIT() asm volatile("cp.async.commit_group;" ::: "memory")
#define CPA_WAIT0()  asm volatile("cp.async.wait_group 0;" ::: "memory")

// ---------------- prep kernel: fp16 weight tiles (swizzled), fp16 mask, rel ----------------
__global__ void prep_kernel(const float* __restrict__ qkv_w,
                            const float* __restrict__ proj_w,
                            const float* __restrict__ mask,
                            int nwin)
{
    const int gt = blockIdx.x * blockDim.x + threadIdx.x;
    const int gsz = gridDim.x * blockDim.x;
    // weights: 4 tiles x 128 rows x 32 float4; q tile pre-scaled by SCALEF
    for (int idx = gt; idx < 16384; idx += gsz) {
        int t = idx >> 12, rem = idx & 4095;
        int r = rem >> 5, c = (rem & 31) << 2;
        const float* src = (t < 3) ? (qkv_w + t * 16384) : proj_w;
        float4 v = ((const float4*)src)[rem];
        float s = (t == 0) ? SCALEF : 1.0f;
        *(uint2*)(g_wtile + t * 32768 + toff(r, c)) =
            make_uint2(packh2(v.x * s, v.y * s), packh2(v.z * s, v.w * s));
    }
    // mask fp16 [nwin][49][56] (pad cols zero)
    for (int idx = gt; idx < nwin * 49 * 56; idx += gsz) {
        int w = idx / (49 * 56), rem = idx - w * (49 * 56);
        int i = rem / 56, j = rem - i * 56;
        float mv = (j < NT) ? mask[(w * NT + i) * NT + j] : 0.f;
        ((__half*)g_maskh)[idx] = __float2half(mv);
    }
    // rel u8
    for (int idx = gt; idx < 2416; idx += gsz) {
        uint8_t v = 0;
        if (idx < NT * NT) {
            int i = idx / NT, j = idx - (idx / NT) * NT;
            int ia = i / WS, ib = i - ia * WS;
            int ja = j / WS, jb = j - ja * WS;
            v = (uint8_t)((ia - ja + WS - 1) * (2 * WS - 1) + (ib - jb + WS - 1));
        }
        g_rel[idx] = v;
    }
}

// 64x128 @ (128x128)^T, single-term A, 2 col-blocks per warp.
__device__ __forceinline__ void mma_tile_1t(uint32_t aA, uint32_t bA,
                                            int rb, int cp, int lane, float acc[2][4][4])
{
    #pragma unroll
    for (int c = 0; c < 2; ++c)
        #pragma unroll
        for (int k = 0; k < 4; ++k)
            #pragma unroll
            for (int j = 0; j < 4; ++j) acc[c][k][j] = 0.f;

    const int arow = rb * 16 + (lane & 15);
    const int achk = lane >> 4;
    const uint32_t axor = (uint32_t)(arow & 7);
    const int bn0  = cp * 64 + (lane & 7) + ((lane >> 4) << 3);
    const int bchk = (lane >> 3) & 1;
    const uint32_t bxor = (uint32_t)(bn0 & 7);

    #pragma unroll
    for (int kk = 0; kk < 8; ++kk) {
        uint32_t ao = (uint32_t)arow * 256 + ((((uint32_t)(kk * 2 + achk)) ^ axor) << 4);
        uint32_t ah[4];
        ldsm4(ah, aA + ao);
        #pragma unroll
        for (int c = 0; c < 2; ++c) {
            uint32_t bo0 = (uint32_t)(bn0 + 32 * c) * 256
                         + ((((uint32_t)(kk * 2 + bchk)) ^ bxor) << 4);
            uint32_t bo1 = bo0 + 16 * 256;
            uint32_t bh0[4], bh1[4];
            ldsm4(bh0, bA + bo0);
            ldsm4(bh1, bA + bo1);
            mma_f16(acc[c][0], ah, bh0[0], bh0[1]);
            mma_f16(acc[c][1], ah, bh0[2], bh0[3]);
            mma_f16(acc[c][2], ah, bh1[0], bh1[1]);
            mma_f16(acc[c][3], ah, bh1[2], bh1[3]);
        }
    }
}

// 2-term A (hi/lo), 2 col-blocks per warp (final proj GEMM)
__device__ __forceinline__ void mma_tile_2t(uint32_t ahi, uint32_t alo, uint32_t bA,
                                            int rb, int cp, int lane, float acc[2][4][4])
{
    #pragma unroll
    for (int c = 0; c < 2; ++c)
        #pragma unroll
        for (int k = 0; k < 4; ++k)
            #pragma unroll
            for (int j = 0; j < 4; ++j) acc[c][k][j] = 0.f;

    const int arow = rb * 16 + (lane & 15);
    const int achk = lane >> 4;
    const uint32_t axor = (uint32_t)(arow & 7);
    const int bn0  = cp * 64 + (lane & 7) + ((lane >> 4) << 3);
    const int bchk = (lane >> 3) & 1;
    const uint32_t bxor = (uint32_t)(bn0 & 7);

    #pragma unroll
    for (int kk = 0; kk < 8; ++kk) {
        uint32_t ao = (uint32_t)arow * 256 + ((((uint32_t)(kk * 2 + achk)) ^ axor) << 4);
        uint32_t ah[4], al[4];
        ldsm4(ah, ahi + ao);
        ldsm4(al, alo + ao);
        #pragma unroll
        for (int c = 0; c < 2; ++c) {
            uint32_t bo0 = (uint32_t)(bn0 + 32 * c) * 256
                         + ((((uint32_t)(kk * 2 + bchk)) ^ bxor) << 4);
            uint32_t bo1 = bo0 + 16 * 256;
            uint32_t bh0[4], bh1[4];
            ldsm4(bh0, bA + bo0);
            ldsm4(bh1, bA + bo1);
            mma_f16(acc[c][0], ah, bh0[0], bh0[1]);
            mma_f16(acc[c][1], ah, bh0[2], bh0[3]);
            mma_f16(acc[c][2], ah, bh1[0], bh1[1]);
            mma_f16(acc[c][3], ah, bh1[2], bh1[3]);
            mma_f16(acc[c][0], al, bh0[0], bh0[1]);
            mma_f16(acc[c][1], al, bh0[2], bh0[3]);
            mma_f16(acc[c][2], al, bh1[0], bh1[1]);
            mma_f16(acc[c][3], al, bh1[2], bh1[3]);
        }
    }
}

__global__ void __launch_bounds__(THREADS, 2)
winattn_kernel(const float* __restrict__ x,
               const float* __restrict__ qkv_b,
               const float* __restrict__ proj_b,
               const float* __restrict__ bt,
               float* __restrict__ out,
               int nwin)
{
    extern __shared__ float sm[];
    const uint32_t smem_base = smem_u32(sm);
    float* s_bias = sm + OFF_BIAS;
    float* s_bt   = sm + OFF_BT;
    __half* s_maskh = (__half*)(sm + OFF_MASKH);
    uint8_t* s_rel = (uint8_t*)(sm + OFF_REL);
    char* base8 = (char*)sm;

    char* xhi = base8 + OFF_XHI * 4;
    char* qhi = base8 + OFF_QHI * 4;
    char* khi = base8 + OFF_KHI * 4;
    char* vhi = base8 + OFF_VHI * 4;
    char* phi = base8 + OFF_PHI * 4;

    const uint32_t xhiA = smem_base + OFF_XHI * 4;
    const uint32_t qhiA = smem_base + OFF_QHI * 4;
    const uint32_t khiA = smem_base + OFF_KHI * 4;
    const uint32_t vhiA = smem_base + OFF_VHI * 4;
    const uint32_t b0A  = smem_base + OFF_B0 * 4;
    const uint32_t mskA = smem_base + OFF_MASKH * 4;
    const uint32_t relA = smem_base + OFF_REL * 4;
    const uint32_t phiA = smem_base + OFF_PHI * 4;

    const int tid  = threadIdx.x;
    const int lane = tid & 31;
    const int wid  = tid >> 5;
    const int rb   = wid & 3;
    const int cp   = wid >> 2;
    const int b    = blockIdx.x;

    const float* xg = x + (long long)b * (NT * DIMC);

    // ---------------- prologue ----------------
    // cp.async: weight tile 0, mask, rel
    for (int idx = tid; idx < 2048; idx += THREADS)
        CPA16(b0A + idx * 16, g_wtile + idx * 16);
    {
        const unsigned char* msrc = g_maskh + (long long)(b % nwin) * 5488;
        for (int idx = tid; idx < 343; idx += THREADS)
            CPA16(mskA + idx * 16, msrc + idx * 16);
        if (tid < 151) CPA16(relA + tid * 16, g_rel + tid * 16);
    }
    CPA_COMMIT();
    // x -> fp16 (LDG + convert)
    for (int idx = tid; idx < NT * 32; idx += THREADS) {
        int r = idx >> 5, c = (idx & 31) << 2;
        store4(((const float4*)xg)[idx], xhi, toff(r, c));
    }
    for (int idx = tid; idx < 240; idx += THREADS)         // zero v pad rows 49-63
        *(uint4*)(vhi + 49 * 256 + idx * 16) = make_uint4(0, 0, 0, 0);
    for (int idx = tid; idx < 676; idx += THREADS) s_bt[idx] = bt[idx];
    for (int idx = tid; idx < 512; idx += THREADS) {
        float v = (idx < 3 * DIMC) ? qkv_b[idx] : proj_b[idx - 3 * DIMC];
        s_bias[idx] = (idx < DIMC) ? v * SCALEF : v;   // q bias pre-scaled
    }
    CPA_WAIT0();
    __syncthreads();

    // ---------------- QKV GEMM: tiles t=0(q),1(k),2(v) ----------------
    #pragma unroll 1
    for (int t = 0; t < 3; ++t) {
        float acc[2][4][4];
        mma_tile_1t(xhiA, b0A, rb, cp, lane, acc);

        #pragma unroll
        for (int c = 0; c < 2; ++c) {
            #pragma unroll
            for (int blk = 0; blk < 4; ++blk) {
                int n0 = (cp * 2 + c) * 32 + blk * 8 + (lane & 3) * 2;
                int r0 = rb * 16 + (lane >> 2);
                const float bb0 = s_bias[t * 128 + n0];
                const float bb1 = s_bias[t * 128 + n0 + 1];
                char* dst = (t == 0) ? qhi : ((t == 1) ? khi : vhi);
                if (r0 < NT)
                    store2(acc[c][blk][0] + bb0, acc[c][blk][1] + bb1, dst, toff(r0, n0));
                if (r0 + 8 < NT)
                    store2(acc[c][blk][2] + bb0, acc[c][blk][3] + bb1, dst, toff(r0 + 8, n0));
            }
        }
        __syncthreads();    // all B reads done
        for (int idx = tid; idx < 2048; idx += THREADS)
            CPA16(b0A + idx * 16, g_wtile + (t + 1) * 32768 + idx * 16);
        CPA_COMMIT();
        CPA_WAIT0();
        __syncthreads();    // B refilled
    }
    // b0 holds proj weights; q/k/v ready (q pre-scaled, biases folded)

    // ---------------- scores: S_h = q_h @ k_h^T for h in {cp*2, cp*2+1} ----------------
    const int arow = rb * 16 + (lane & 15);
    const uint32_t axor = (uint32_t)(arow & 7);
    float sacc[2][7][4];
    #pragma unroll
    for (int h2 = 0; h2 < 2; ++h2)
        #pragma unroll
        for (int bk = 0; bk < 7; ++bk)
            #pragma unroll
            for (int j = 0; j < 4; ++j) sacc[h2][bk][j] = 0.f;

    #pragma unroll
    for (int h2 = 0; h2 < 2; ++h2) {
        const int h = cp * 2 + h2;
        #pragma unroll
        for (int kk = 0; kk < 2; ++kk) {
            uint32_t achunk = (uint32_t)(h * 4 + kk * 2 + (lane >> 4));
            uint32_t ao = (uint32_t)arow * 256 + ((achunk ^ axor) << 4);
            uint32_t qh_[4];
            ldsm4(qh_, qhiA + ao);
            #pragma unroll
            for (int g = 0; g < 4; ++g) {
                int bn = g * 16 + (lane & 7) + ((lane >> 4) << 3);
                uint32_t bchunk = (uint32_t)(h * 4 + kk * 2 + ((lane >> 3) & 1));
                uint32_t bo = (uint32_t)bn * 256 + ((bchunk ^ (uint32_t)(bn & 7)) << 4);
                uint32_t kh_[4];
                ldsm4(kh_, khiA + bo);
                mma_f16(sacc[h2][2 * g], qh_, kh_[0], kh_[1]);
                if (2 * g + 1 < 7)
                    mma_f16(sacc[h2][2 * g + 1], qh_, kh_[2], kh_[3]);
            }
        }
    }
    __syncthreads();   // q/k reads done -> P tile (over x+q) writable

    // ---------------- softmax on fragments -> P (fp16) ----------------
    {
        {   // zero P pad cols 56-63 (256 threads cover 64 rows x 4 heads)
            int r = tid & 63, hh = tid >> 6;
            *(uint4*)(phi + poff(r, hh * 64 + 56)) = make_uint4(0, 0, 0, 0);
        }
        const int r0 = rb * 16 + (lane >> 2);
        const int r1 = r0 + 8;
        #pragma unroll
        for (int h2 = 0; h2 < 2; ++h2) {
            const int h = cp * 2 + h2;
            float sum0 = 0.f, sum1 = 0.f;
            #pragma unroll
            for (int bk = 0; bk < 7; ++bk) {
                int j0 = bk * 8 + (lane & 3) * 2;
                float e00 = 0.f, e01 = 0.f, e10 = 0.f, e11 = 0.f;
                if (j0 < NT) {
                    float2 m0 = __half22float2(*(const __half2*)&s_maskh[r0 * M_STRIDE + j0]);
                    float2 m1 = __half22float2(*(const __half2*)&s_maskh[r1 * M_STRIDE + j0]);
                    e00 = __expf(sacc[h2][bk][0] + s_bt[(int)s_rel[r0 * NT + j0] * HEADS + h] + m0.x);
                    e10 = __expf(sacc[h2][bk][2] + s_bt[(int)s_rel[r1 * NT + j0] * HEADS + h] + m1.x);
                    if (j0 + 1 < NT) {
                        e01 = __expf(sacc[h2][bk][1] + s_bt[(int)s_rel[r0 * NT + j0 + 1] * HEADS + h] + m0.y);
                        e11 = __expf(sacc[h2][bk][3] + s_bt[(int)s_rel[r1 * NT + j0 + 1] * HEADS + h] + m1.y);
                    }
                }
                sum0 += e00 + e01;
                sum1 += e10 + e11;
                sacc[h2][bk][0] = e00; sacc[h2][bk][1] = e01;
                sacc[h2][bk][2] = e10; sacc[h2][bk][3] = e11;
            }
            sum0 += __shfl_xor_sync(0xffffffffu, sum0, 1);
            sum0 += __shfl_xor_sync(0xffffffffu, sum0, 2);
            sum1 += __shfl_xor_sync(0xffffffffu, sum1, 1);
            sum1 += __shfl_xor_sync(0xffffffffu, sum1, 2);
            const float inv0 = 1.0f / sum0;
            const float inv1 = 1.0f / sum1;
            #pragma unroll
            for (int bk = 0; bk < 7; ++bk) {
                int j0 = bk * 8 + (lane & 3) * 2;
                store2(sacc[h2][bk][0] * inv0, sacc[h2][bk][1] * inv0, phi, poff(r0, h * 64 + j0));
                store2(sacc[h2][bk][2] * inv1, sacc[h2][bk][3] * inv1, phi, poff(r1, h * 64 + j0));
            }
        }
    }
    __syncthreads();

    // ---------------- PV: out_h = P_h @ v_h (V via ldmatrix.trans) ----------------
    float pacc[2][4][4];
    {
        #pragma unroll
        for (int h2 = 0; h2 < 2; ++h2)
            #pragma unroll
            for (int bk = 0; bk < 4; ++bk)
                #pragma unroll
                for (int j = 0; j < 4; ++j) pacc[h2][bk][j] = 0.f;

        #pragma unroll
        for (int h2 = 0; h2 < 2; ++h2) {
            const int h = cp * 2 + h2;
            #pragma unroll
            for (int kk = 0; kk < 4; ++kk) {
                uint32_t achunk = (uint32_t)(h * 8 + kk * 2 + (lane >> 4));
                uint32_t ao = (uint32_t)arow * 512 + ((achunk ^ axor) << 4);
                uint32_t ph_[4];
                ldsm4(ph_, phiA + ao);
                #pragma unroll
                for (int g = 0; g < 2; ++g) {
                    int vr = kk * 16 + ((lane >> 3) & 1) * 8 + (lane & 7);
                    uint32_t vchunk = (uint32_t)(h * 4 + g * 2 + (lane >> 4));
                    uint32_t vo = (uint32_t)vr * 256 + ((vchunk ^ (uint32_t)(vr & 7)) << 4);
                    uint32_t vh_[4];
                    ldsm4t(vh_, vhiA + vo);
                    mma_f16(pacc[h2][2 * g],     ph_, vh_[0], vh_[1]);
                    mma_f16(pacc[h2][2 * g + 1], ph_, vh_[2], vh_[3]);
                }
            }
        }
    }
    __syncthreads();   // v reads done -> k/v tiles reusable for attn-out

    // attn-out -> hi in khi, lo in vhi (A-side of proj, 2-term)
    {
        const int r0 = rb * 16 + (lane >> 2);
        #pragma unroll
        for (int h2 = 0; h2 < 2; ++h2) {
            const int h = cp * 2 + h2;
            #pragma unroll
            for (int bk = 0; bk < 4; ++bk) {
                int d0 = bk * 8 + (lane & 3) * 2;
                split_store2(pacc[h2][bk][0], pacc[h2][bk][1], khi, vhi, toff(r0, h * HD + d0));
                split_store2(pacc[h2][bk][2], pacc[h2][bk][3], khi, vhi, toff(r0 + 8, h * HD + d0));
            }
        }
    }
    __syncthreads();

    // ---------------- proj GEMM (A = attn-out hi/lo, B = b0) -> global ----------------
    {
        float acc[2][4][4];
        mma_tile_2t(khiA, vhiA, b0A, rb, cp, lane, acc);
        float* dstbase = out + (long long)b * (NT * DIMC);
        #pragma unroll
        for (int c = 0; c < 2; ++c) {
            #pragma unroll
            for (int blk = 0; blk < 4; ++blk) {
                int n0 = (cp * 2 + c) * 32 + blk * 8 + (lane & 3) * 2;
                int r0 = rb * 16 + (lane >> 2);
                const float bb0 = s_bias[3 * DIMC + n0];
                const float bb1 = s_bias[3 * DIMC + n0 + 1];
                if (r0 < NT) {
                    float* p = dstbase + r0 * DIMC + n0;
                    p[0] = acc[c][blk][0] + bb0;
                    p[1] = acc[c][blk][1] + bb1;
                }
                if (r0 + 8 < NT) {
                    float* p = dstbase + (r0 + 8) * DIMC + n0;
                    p[0] = acc[c][blk][2] + bb0;
                    p[1] = acc[c][blk][3] + bb1;
                }
            }
        }
    }
}

extern "C" void kernel_launch(void* const* d_in, const int* in_sizes, int n_in,
                              void* d_out, int out_size) {
    const float* x      = (const float*)d_in[0];
    const float* mask   = (const float*)d_in[1];
    const float* qkv_w  = (const float*)d_in[2];
    const float* qkv_b  = (const float*)d_in[3];
    const float* proj_w = (const float*)d_in[4];
    const float* proj_b = (const float*)d_in[5];
    const float* bt     = (const float*)d_in[6];
    float* out = (float*)d_out;

    const int B    = in_sizes[0] / (NT * DIMC);   // 4096
    const int nwin = in_sizes[1] / (NT * NT);     // 64

    prep_kernel<<<256, 256>>>(qkv_w, proj_w, mask, nwin > 0 ? nwin : 1);

    cudaFuncSetAttribute(winattn_kernel,
                         cudaFuncAttributeMaxDynamicSharedMemorySize, SMEM_BYTES);
    winattn_kernel<<<B, THREADS, SMEM_BYTES>>>(x, qkv_b, proj_b, bt, out, B > 0 ? nwin : 1);
}

// round 14
// speedup vs baseline: 5.3925x; 1.1371x over previous
#include <cuda_runtime.h>
#include <cuda_fp16.h>
#include <cstdint>

// ---------------- problem constants ----------------
#define NT     49
#define DIMC   128
#define HEADS  4
#define HD     32
#define WS     7
#define SCALEF 0.17677669529663687f
#define THREADS 256

// ---------------- global scratch (static, allowed) ----------------
__device__ __align__(16) unsigned char g_wtile[4 * 32768];       // fp16 swizzled weight tiles
__device__ __align__(16) unsigned char g_cm[64 * 28 * 256 * 4];  // fragment-ordered bias+mask (half2)

// ---------------- smem layout (float offsets) ----------------
#define OFF_BIAS  0                    // 512
#define OFF_XHI   512                  // 2048B -> 256B aligned; 64x128 fp16 tiles = 4096 floats
#define OFF_QHI   (OFF_XHI + 4096)
#define OFF_KHI   (OFF_QHI + 4096)
#define OFF_VHI   (OFF_KHI + 4096)
#define OFF_B0    (OFF_VHI + 4096)     // 128x128 fp16 = 8192 floats
#define SMEM_FLOATS (OFF_B0 + 8192)    // 25088
#define SMEM_BYTES  (SMEM_FLOATS * 4)  // 100352 (x2 CTAs = 196KB)
#define OFF_PHI  OFF_XHI               // P tile overlays dead x+q

static_assert(OFF_QHI == OFF_XHI + 4096, "P overlay needs x,q contiguous");
static_assert((OFF_XHI * 4) % 256 == 0, "tile align");

// ---------------- helpers ----------------
__device__ __forceinline__ uint32_t smem_u32(const void* p) {
    uint32_t a;
    asm("{ .reg .u64 t; cvta.to.shared.u64 t, %1; cvt.u32.u64 %0, t; }" : "=r"(a) : "l"(p));
    return a;
}
__device__ __forceinline__ uint32_t toff(int r, int c) {       // 256B rows
    return (uint32_t)(r * 256 + ((((c >> 3) ^ (r & 7))) << 4) + ((c & 7) << 1));
}
__device__ __forceinline__ uint32_t poff(int r, int c) {       // 512B rows (P)
    return (uint32_t)(r * 512 + ((((c >> 3) ^ (r & 7))) << 4) + ((c & 7) << 1));
}
__device__ __forceinline__ uint32_t packh2(float a, float b) { // a->low, b->high
    __half2 h = __floats2half2_rn(a, b);
    return *reinterpret_cast<uint32_t*>(&h);
}
__device__ __forceinline__ float2 h2f2(uint32_t p) {
    __half2 h = *reinterpret_cast<__half2*>(&p);
    return __half22float2(h);
}
__device__ __forceinline__ void split_store2(float a, float b, char* hb, char* lb, uint32_t off) {
    uint32_t h = packh2(a, b);
    float2 hf = h2f2(h);
    uint32_t l = packh2(a - hf.x, b - hf.y);
    *(uint32_t*)(hb + off) = h;
    *(uint32_t*)(lb + off) = l;
}
__device__ __forceinline__ void store4(float4 v, char* hb, uint32_t off) {
    *(uint2*)(hb + off) = make_uint2(packh2(v.x, v.y), packh2(v.z, v.w));
}
__device__ __forceinline__ void store2(float a, float b, char* hb, uint32_t off) {
    *(uint32_t*)(hb + off) = packh2(a, b);
}
__device__ __forceinline__ void ldsm4(uint32_t r[4], uint32_t addr) {
    asm volatile("ldmatrix.sync.aligned.m8n8.x4.shared.b16 {%0,%1,%2,%3}, [%4];"
                 : "=r"(r[0]), "=r"(r[1]), "=r"(r[2]), "=r"(r[3]) : "r"(addr));
}
__device__ __forceinline__ void ldsm4t(uint32_t r[4], uint32_t addr) {
    asm volatile("ldmatrix.sync.aligned.m8n8.x4.trans.shared.b16 {%0,%1,%2,%3}, [%4];"
                 : "=r"(r[0]), "=r"(r[1]), "=r"(r[2]), "=r"(r[3]) : "r"(addr));
}
__device__ __forceinline__ void mma_f16(float d[4], const uint32_t a[4],
                                        uint32_t b0, uint32_t b1) {
    asm volatile("mma.sync.aligned.m16n8k16.row.col.f32.f16.f16.f32 "
                 "{%0,%1,%2,%3},{%4,%5,%6,%7},{%8,%9},{%0,%1,%2,%3};"
                 : "+f"(d[0]), "+f"(d[1]), "+f"(d[2]), "+f"(d[3])
                 : "r"(a[0]), "r"(a[1]), "r"(a[2]), "r"(a[3]), "r"(b0), "r"(b1));
}
#define CPA16(dst, src) \
    asm volatile("cp.async.cg.shared.global [%0], [%1], 16;" \
                 :: "r"((uint32_t)(dst)), "l"(src) : "memory")
#define CPA_COMMIT() asm volatile("cp.async.commit_group;" ::: "memory")
#define CPA_WAIT0()  asm volatile("cp.async.wait_group 0;" ::: "memory")

// ---------------- prep kernel ----------------
__global__ void prep_kernel(const float* __restrict__ qkv_w,
                            const float* __restrict__ proj_w,
                            const float* __restrict__ mask,
                            const float* __restrict__ bt,
                            int nwin)
{
    const int gt = blockIdx.x * blockDim.x + threadIdx.x;
    const int gsz = gridDim.x * blockDim.x;
    // weights: 4 tiles x 128 rows x 32 float4; q tile pre-scaled by SCALEF
    for (int idx = gt; idx < 16384; idx += gsz) {
        int t = idx >> 12, rem = idx & 4095;
        int r = rem >> 5, c = (rem & 31) << 2;
        const float* src = (t < 3) ? (qkv_w + t * 16384) : proj_w;
        float4 v = ((const float4*)src)[rem];
        float s = (t == 0) ? SCALEF : 1.0f;
        *(uint2*)(g_wtile + t * 32768 + toff(r, c)) =
            make_uint2(packh2(v.x * s, v.y * s), packh2(v.z * s, v.w * s));
    }
    // cm table: [w][k][tid] half2, k = (h2*7+bk)*2 + rr
    for (int idx = gt; idx < nwin * 28 * 256; idx += gsz) {
        int w   = idx / (28 * 256);
        int rem = idx - w * 28 * 256;
        int k   = rem >> 8;
        int tid = rem & 255;
        int rr  = k & 1;
        int bk  = (k >> 1) % 7;
        int h2  = (k >> 1) / 7;
        int wid = tid >> 5, lane = tid & 31;
        int rb = wid & 3, cp = wid >> 2;
        int h  = cp * 2 + h2;
        int r  = rb * 16 + (lane >> 2) + rr * 8;
        int j0 = bk * 8 + (lane & 3) * 2;
        float v0 = -30000.f, v1 = -30000.f;
        if (r < NT) {
            int ia = r / WS, ib = r - ia * WS;
            if (j0 < NT) {
                int ja = j0 / WS, jb = j0 - ja * WS;
                int ridx = (ia - ja + WS - 1) * (2 * WS - 1) + (ib - jb + WS - 1);
                v0 = bt[ridx * HEADS + h] + mask[(w * NT + r) * NT + j0];
            }
            if (j0 + 1 < NT) {
                int j1 = j0 + 1;
                int ja = j1 / WS, jb = j1 - ja * WS;
                int ridx = (ia - ja + WS - 1) * (2 * WS - 1) + (ib - jb + WS - 1);
                v1 = bt[ridx * HEADS + h] + mask[(w * NT + r) * NT + j1];
            }
        }
        ((__half2*)g_cm)[idx] = __floats2half2_rn(v0, v1);
    }
}

// 64x128 @ (128x128)^T, single-term A, warp = 32 rows x 32 cols (wr=2, wc=4).
// warp (rb2, cq): rows rb2*32..+31, cols cq*32..+31.
__device__ __forceinline__ void mma_tile_1t(uint32_t aA, uint32_t bA,
                                            int rb2, int cq, int lane, float acc[2][4][4])
{
    #pragma unroll
    for (int f = 0; f < 2; ++f)
        #pragma unroll
        for (int n = 0; n < 4; ++n)
            #pragma unroll
            for (int j = 0; j < 4; ++j) acc[f][n][j] = 0.f;

    const int arow = rb2 * 32 + (lane & 15);
    const int achk = lane >> 4;
    const uint32_t axor = (uint32_t)(arow & 7);
    const int bn   = cq * 32 + (lane & 7) + ((lane >> 4) << 3);
    const int bchk = (lane >> 3) & 1;
    const uint32_t bxor = (uint32_t)(bn & 7);

    #pragma unroll
    for (int kk = 0; kk < 8; ++kk) {
        uint32_t ao  = (uint32_t)arow * 256 + ((((uint32_t)(kk * 2 + achk)) ^ axor) << 4);
        uint32_t bo0 = (uint32_t)bn * 256 + ((((uint32_t)(kk * 2 + bchk)) ^ bxor) << 4);
        uint32_t ah0[4], ah1[4], bh0[4], bh1[4];
        ldsm4(ah0, aA + ao);
        ldsm4(ah1, aA + ao + 16 * 256);     // (arow+16)&7 == arow&7
        ldsm4(bh0, bA + bo0);
        ldsm4(bh1, bA + bo0 + 16 * 256);
        mma_f16(acc[0][0], ah0, bh0[0], bh0[1]);
        mma_f16(acc[0][1], ah0, bh0[2], bh0[3]);
        mma_f16(acc[0][2], ah0, bh1[0], bh1[1]);
        mma_f16(acc[0][3], ah0, bh1[2], bh1[3]);
        mma_f16(acc[1][0], ah1, bh0[0], bh0[1]);
        mma_f16(acc[1][1], ah1, bh0[2], bh0[3]);
        mma_f16(acc[1][2], ah1, bh1[0], bh1[1]);
        mma_f16(acc[1][3], ah1, bh1[2], bh1[3]);
    }
}

// 2-term A (hi/lo), old layout: warp (rb,cp): rows rb*16..+15, cols cp*64..+63 (proj)
__device__ __forceinline__ void mma_tile_2t(uint32_t ahi, uint32_t alo, uint32_t bA,
                                            int rb, int cp, int lane, float acc[2][4][4])
{
    #pragma unroll
    for (int c = 0; c < 2; ++c)
        #pragma unroll
        for (int k = 0; k < 4; ++k)
            #pragma unroll
            for (int j = 0; j < 4; ++j) acc[c][k][j] = 0.f;

    const int arow = rb * 16 + (lane & 15);
    const int achk = lane >> 4;
    const uint32_t axor = (uint32_t)(arow & 7);
    const int bn0  = cp * 64 + (lane & 7) + ((lane >> 4) << 3);
    const int bchk = (lane >> 3) & 1;
    const uint32_t bxor = (uint32_t)(bn0 & 7);

    #pragma unroll
    for (int kk = 0; kk < 8; ++kk) {
        uint32_t ao = (uint32_t)arow * 256 + ((((uint32_t)(kk * 2 + achk)) ^ axor) << 4);
        uint32_t ah[4], al[4];
        ldsm4(ah, ahi + ao);
        ldsm4(al, alo + ao);
        #pragma unroll
        for (int c = 0; c < 2; ++c) {
            uint32_t bo0 = (uint32_t)(bn0 + 32 * c) * 256
                         + ((((uint32_t)(kk * 2 + bchk)) ^ bxor) << 4);
            uint32_t bo1 = bo0 + 16 * 256;
            uint32_t bh0[4], bh1[4];
            ldsm4(bh0, bA + bo0);
            ldsm4(bh1, bA + bo1);
            mma_f16(acc[c][0], ah, bh0[0], bh0[1]);
            mma_f16(acc[c][1], ah, bh0[2], bh0[3]);
            mma_f16(acc[c][2], ah, bh1[0], bh1[1]);
            mma_f16(acc[c][3], ah, bh1[2], bh1[3]);
            mma_f16(acc[c][0], al, bh0[0], bh0[1]);
            mma_f16(acc[c][1], al, bh0[2], bh0[3]);
            mma_f16(acc[c][2], al, bh1[0], bh1[1]);
            mma_f16(acc[c][3], al, bh1[2], bh1[3]);
        }
    }
}

__global__ void __launch_bounds__(THREADS, 2)
winattn_kernel(const float* __restrict__ x,
               const float* __restrict__ qkv_b,
               const float* __restrict__ proj_b,
               float* __restrict__ out,
               int nwin)
{
    extern __shared__ float sm[];
    const uint32_t smem_base = smem_u32(sm);
    float* s_bias = sm + OFF_BIAS;
    char* base8 = (char*)sm;

    char* xhi = base8 + OFF_XHI * 4;
    char* qhi = base8 + OFF_QHI * 4;
    char* khi = base8 + OFF_KHI * 4;
    char* vhi = base8 + OFF_VHI * 4;
    char* phi = base8 + OFF_PHI * 4;

    const uint32_t xhiA = smem_base + OFF_XHI * 4;
    const uint32_t qhiA = smem_base + OFF_QHI * 4;
    const uint32_t khiA = smem_base + OFF_KHI * 4;
    const uint32_t vhiA = smem_base + OFF_VHI * 4;
    const uint32_t b0A  = smem_base + OFF_B0 * 4;
    const uint32_t phiA = smem_base + OFF_PHI * 4;

    const int tid  = threadIdx.x;
    const int lane = tid & 31;
    const int wid  = tid >> 5;
    const int rb   = wid & 3;     // attention layout
    const int cp   = wid >> 2;
    const int rb2  = wid & 1;     // qkv GEMM layout (2x4)
    const int cq   = wid >> 1;
    const int b    = blockIdx.x;

    const float* xg = x + (long long)b * (NT * DIMC);

    // ---------------- prologue ----------------
    for (int idx = tid; idx < 2048; idx += THREADS)        // weight tile 0 (q)
        CPA16(b0A + idx * 16, g_wtile + idx * 16);
    CPA_COMMIT();
    for (int idx = tid; idx < NT * 32; idx += THREADS) {   // x -> fp16
        int r = idx >> 5, c = (idx & 31) << 2;
        store4(((const float4*)xg)[idx], xhi, toff(r, c));
    }
    {   // zero pad rows 49-63 of q/k/v
        char* tiles[3] = { qhi, khi, vhi };
        for (int idx = tid; idx < 3 * 240; idx += THREADS) {
            int tl = idx / 240, rem = idx - tl * 240;
            *(uint4*)(tiles[tl] + 49 * 256 + rem * 16) = make_uint4(0, 0, 0, 0);
        }
    }
    for (int idx = tid; idx < 512; idx += THREADS) {
        float v = (idx < 3 * DIMC) ? qkv_b[idx] : proj_b[idx - 3 * DIMC];
        s_bias[idx] = (idx < DIMC) ? v * SCALEF : v;   // q bias pre-scaled
    }
    CPA_WAIT0();
    __syncthreads();

    // ---------------- QKV GEMM: tiles t=0(q),1(k),2(v) ----------------
    #pragma unroll 1
    for (int t = 0; t < 3; ++t) {
        float acc[2][4][4];
        mma_tile_1t(xhiA, b0A, rb2, cq, lane, acc);

        char* dst = (t == 0) ? qhi : ((t == 1) ? khi : vhi);
        #pragma unroll
        for (int f = 0; f < 2; ++f) {
            #pragma unroll
            for (int nb = 0; nb < 4; ++nb) {
                int n0 = cq * 32 + nb * 8 + (lane & 3) * 2;
                int r0 = rb2 * 32 + f * 16 + (lane >> 2);
                const float bb0 = s_bias[t * 128 + n0];
                const float bb1 = s_bias[t * 128 + n0 + 1];
                if (r0 < NT)
                    store2(acc[f][nb][0] + bb0, acc[f][nb][1] + bb1, dst, toff(r0, n0));
                if (r0 + 8 < NT)
                    store2(acc[f][nb][2] + bb0, acc[f][nb][3] + bb1, dst, toff(r0 + 8, n0));
            }
        }
        __syncthreads();    // all B reads done
        for (int idx = tid; idx < 2048; idx += THREADS)
            CPA16(b0A + idx * 16, g_wtile + (t + 1) * 32768 + idx * 16);
        CPA_COMMIT();
        CPA_WAIT0();
        __syncthreads();    // B refilled
    }
    // b0 holds proj weights; q/k/v ready (q pre-scaled, biases folded)

    // ---------------- scores: S_h = q_h @ k_h^T for h in {cp*2, cp*2+1} ----------------
    const int arow = rb * 16 + (lane & 15);
    const uint32_t axor = (uint32_t)(arow & 7);
    float sacc[2][7][4];
    #pragma unroll
    for (int h2 = 0; h2 < 2; ++h2)
        #pragma unroll
        for (int bk = 0; bk < 7; ++bk)
            #pragma unroll
            for (int j = 0; j < 4; ++j) sacc[h2][bk][j] = 0.f;

    #pragma unroll
    for (int h2 = 0; h2 < 2; ++h2) {
        const int h = cp * 2 + h2;
        #pragma unroll
        for (int kk = 0; kk < 2; ++kk) {
            uint32_t achunk = (uint32_t)(h * 4 + kk * 2 + (lane >> 4));
            uint32_t ao = (uint32_t)arow * 256 + ((achunk ^ axor) << 4);
            uint32_t qh_[4];
            ldsm4(qh_, qhiA + ao);
            #pragma unroll
            for (int g = 0; g < 4; ++g) {
                int bn = g * 16 + (lane & 7) + ((lane >> 4) << 3);
                uint32_t bchunk = (uint32_t)(h * 4 + kk * 2 + ((lane >> 3) & 1));
                uint32_t bo = (uint32_t)bn * 256 + ((bchunk ^ (uint32_t)(bn & 7)) << 4);
                uint32_t kh_[4];
                ldsm4(kh_, khiA + bo);
                mma_f16(sacc[h2][2 * g], qh_, kh_[0], kh_[1]);
                if (2 * g + 1 < 7)
                    mma_f16(sacc[h2][2 * g + 1], qh_, kh_[2], kh_[3]);
            }
        }
    }
    __syncthreads();   // q/k reads done -> P tile (over x+q) writable

    // ---------------- softmax on fragments -> P (fp16), cm from baked table ----------------
    {
        {   // zero P pad cols 56-63 (256 threads cover 64 rows x 4 heads)
            int r = tid & 63, hh = tid >> 6;
            *(uint4*)(phi + poff(r, hh * 64 + 56)) = make_uint4(0, 0, 0, 0);
        }
        const __half2* cmw = reinterpret_cast<const __half2*>(g_cm)
                           + ((long long)(b % nwin) * 28) * 256 + tid;
        const int r0 = rb * 16 + (lane >> 2);
        const int r1 = r0 + 8;
        #pragma unroll
        for (int h2 = 0; h2 < 2; ++h2) {
            const int h = cp * 2 + h2;
            float sum0 = 0.f, sum1 = 0.f;
            #pragma unroll
            for (int bk = 0; bk < 7; ++bk) {
                float2 c0 = __half22float2(__ldg(&cmw[((h2 * 7 + bk) * 2 + 0) * 256]));
                float2 c1 = __half22float2(__ldg(&cmw[((h2 * 7 + bk) * 2 + 1) * 256]));
                float e00 = __expf(sacc[h2][bk][0] + c0.x);
                float e01 = __expf(sacc[h2][bk][1] + c0.y);
                float e10 = __expf(sacc[h2][bk][2] + c1.x);
                float e11 = __expf(sacc[h2][bk][3] + c1.y);
                sum0 += e00 + e01;
                sum1 += e10 + e11;
                sacc[h2][bk][0] = e00; sacc[h2][bk][1] = e01;
                sacc[h2][bk][2] = e10; sacc[h2][bk][3] = e11;
            }
            sum0 += __shfl_xor_sync(0xffffffffu, sum0, 1);
            sum0 += __shfl_xor_sync(0xffffffffu, sum0, 2);
            sum1 += __shfl_xor_sync(0xffffffffu, sum1, 1);
            sum1 += __shfl_xor_sync(0xffffffffu, sum1, 2);
            const float inv0 = 1.0f / sum0;
            const float inv1 = 1.0f / sum1;
            #pragma unroll
            for (int bk = 0; bk < 7; ++bk) {
                int j0 = bk * 8 + (lane & 3) * 2;
                store2(sacc[h2][bk][0] * inv0, sacc[h2][bk][1] * inv0, phi, poff(r0, h * 64 + j0));
                store2(sacc[h2][bk][2] * inv1, sacc[h2][bk][3] * inv1, phi, poff(r1, h * 64 + j0));
            }
        }
    }
    __syncthreads();

    // ---------------- PV: out_h = P_h @ v_h (V via ldmatrix.trans) ----------------
    float pacc[2][4][4];
    {
        #pragma unroll
        for (int h2 = 0; h2 < 2; ++h2)
            #pragma unroll
            for (int bk = 0; bk < 4; ++bk)
                #pragma unroll
                for (int j = 0; j < 4; ++j) pacc[h2][bk][j] = 0.f;

        #pragma unroll
        for (int h2 = 0; h2 < 2; ++h2) {
            const int h = cp * 2 + h2;
            #pragma unroll
            for (int kk = 0; kk < 4; ++kk) {
                uint32_t achunk = (uint32_t)(h * 8 + kk * 2 + (lane >> 4));
                uint32_t ao = (uint32_t)arow * 512 + ((achunk ^ axor) << 4);
                uint32_t ph_[4];
                ldsm4(ph_, phiA + ao);
                #pragma unroll
                for (int g = 0; g < 2; ++g) {
                    int vr = kk * 16 + ((lane >> 3) & 1) * 8 + (lane & 7);
                    uint32_t vchunk = (uint32_t)(h * 4 + g * 2 + (lane >> 4));
                    uint32_t vo = (uint32_t)vr * 256 + ((vchunk ^ (uint32_t)(vr & 7)) << 4);
                    uint32_t vh_[4];
                    ldsm4t(vh_, vhiA + vo);
                    mma_f16(pacc[h2][2 * g],     ph_, vh_[0], vh_[1]);
                    mma_f16(pacc[h2][2 * g + 1], ph_, vh_[2], vh_[3]);
                }
            }
        }
    }
    __syncthreads();   // v reads done -> k/v tiles reusable for attn-out

    // attn-out -> hi in khi, lo in vhi (A-side of proj, 2-term)
    {
        const int r0 = rb * 16 + (lane >> 2);
        #pragma unroll
        for (int h2 = 0; h2 < 2; ++h2) {
            const int h = cp * 2 + h2;
            #pragma unroll
            for (int bk = 0; bk < 4; ++bk) {
                int d0 = bk * 8 + (lane & 3) * 2;
                split_store2(pacc[h2][bk][0], pacc[h2][bk][1], khi, vhi, toff(r0, h * HD + d0));
                split_store2(pacc[h2][bk][2], pacc[h2][bk][3], khi, vhi, toff(r0 + 8, h * HD + d0));
            }
        }
    }
    __syncthreads();

    // ---------------- proj GEMM (A = attn-out hi/lo, B = b0) -> global ----------------
    {
        float acc[2][4][4];
        mma_tile_2t(khiA, vhiA, b0A, rb, cp, lane, acc);
        float* dstbase = out + (long long)b * (NT * DIMC);
        #pragma unroll
        for (int c = 0; c < 2; ++c) {
            #pragma unroll
            for (int blk = 0; blk < 4; ++blk) {
                int n0 = (cp * 2 + c) * 32 + blk * 8 + (lane & 3) * 2;
                int r0 = rb * 16 + (lane >> 2);
                const float bb0 = s_bias[3 * DIMC + n0];
                const float bb1 = s_bias[3 * DIMC + n0 + 1];
                if (r0 < NT) {
                    float* p = dstbase + r0 * DIMC + n0;
                    p[0] = acc[c][blk][0] + bb0;
                    p[1] = acc[c][blk][1] + bb1;
                }
                if (r0 + 8 < NT) {
                    float* p = dstbase + (r0 + 8) * DIMC + n0;
                    p[0] = acc[c][blk][2] + bb0;
                    p[1] = acc[c][blk][3] + bb1;
                }
            }
        }
    }
}

extern "C" void kernel_launch(void* const* d_in, const int* in_sizes, int n_in,
                              void* d_out, int out_size) {
    const float* x      = (const float*)d_in[0];
    const float* mask   = (const float*)d_in[1];
    const float* qkv_w  = (const float*)d_in[2];
    const float* qkv_b  = (const float*)d_in[3];
    const float* proj_w = (const float*)d_in[4];
    const float* proj_b = (const float*)d_in[5];
    const float* bt     = (const float*)d_in[6];
    float* out = (float*)d_out;

    const int B    = in_sizes[0] / (NT * DIMC);   // 4096
    const int nwin = in_sizes[1] / (NT * NT);     // 64

    prep_kernel<<<512, 256>>>(qkv_w, proj_w, mask, bt, nwin > 0 ? nwin : 1);

    cudaFuncSetAttribute(winattn_kernel,
                         cudaFuncAttributeMaxDynamicSharedMemorySize, SMEM_BYTES);
    winattn_kernel<<<B, THREADS, SMEM_BYTES>>>(x, qkv_b, proj_b, out, B > 0 ? nwin : 1);
}

// round 15
// speedup vs baseline: 6.0177x; 1.1160x over previous
#include <cuda_runtime.h>
#include <cuda_fp16.h>
#include <cstdint>

// ---------------- problem constants ----------------
#define NT     49
#define DIMC   128
#define HEADS  4
#define HD     32
#define WS     7
#define SCALEF 0.17677669529663687f
#define THREADS 256

// ---------------- global scratch (static, allowed) ----------------
__device__ __align__(16) unsigned char g_wtile[4 * 32768];       // fp16 swizzled weight tiles
__device__ __align__(16) unsigned char g_cm[64 * 28 * 256 * 4];  // fragment-ordered bias+mask (half2)

// ---------------- smem layout (float offsets) ----------------
#define OFF_BIAS  0                    // 512
#define OFF_XHI   512                  // 2048B -> 256B aligned; 64x128 fp16 tiles = 4096 floats
#define OFF_QHI   (OFF_XHI + 4096)
#define OFF_KHI   (OFF_QHI + 4096)
#define OFF_VHI   (OFF_KHI + 4096)
#define OFF_B0    (OFF_VHI + 4096)     // 128x128 fp16 = 8192 floats
#define SMEM_FLOATS (OFF_B0 + 8192)    // 25088
#define SMEM_BYTES  (SMEM_FLOATS * 4)  // 100352 (x2 CTAs = 196KB)

static_assert((OFF_XHI * 4) % 256 == 0, "tile align");

// ---------------- helpers ----------------
__device__ __forceinline__ uint32_t smem_u32(const void* p) {
    uint32_t a;
    asm("{ .reg .u64 t; cvta.to.shared.u64 t, %1; cvt.u32.u64 %0, t; }" : "=r"(a) : "l"(p));
    return a;
}
__device__ __forceinline__ uint32_t toff(int r, int c) {       // 256B rows
    return (uint32_t)(r * 256 + ((((c >> 3) ^ (r & 7))) << 4) + ((c & 7) << 1));
}
__device__ __forceinline__ uint32_t packh2(float a, float b) { // a->low, b->high
    __half2 h = __floats2half2_rn(a, b);
    return *reinterpret_cast<uint32_t*>(&h);
}
__device__ __forceinline__ void store4(float4 v, char* hb, uint32_t off) {
    *(uint2*)(hb + off) = make_uint2(packh2(v.x, v.y), packh2(v.z, v.w));
}
__device__ __forceinline__ void store2(float a, float b, char* hb, uint32_t off) {
    *(uint32_t*)(hb + off) = packh2(a, b);
}
__device__ __forceinline__ void ldsm4(uint32_t r[4], uint32_t addr) {
    asm volatile("ldmatrix.sync.aligned.m8n8.x4.shared.b16 {%0,%1,%2,%3}, [%4];"
                 : "=r"(r[0]), "=r"(r[1]), "=r"(r[2]), "=r"(r[3]) : "r"(addr));
}
__device__ __forceinline__ void ldsm4t(uint32_t r[4], uint32_t addr) {
    asm volatile("ldmatrix.sync.aligned.m8n8.x4.trans.shared.b16 {%0,%1,%2,%3}, [%4];"
                 : "=r"(r[0]), "=r"(r[1]), "=r"(r[2]), "=r"(r[3]) : "r"(addr));
}
__device__ __forceinline__ void mma_f16(float d[4], const uint32_t a[4],
                                        uint32_t b0, uint32_t b1) {
    asm volatile("mma.sync.aligned.m16n8k16.row.col.f32.f16.f16.f32 "
                 "{%0,%1,%2,%3},{%4,%5,%6,%7},{%8,%9},{%0,%1,%2,%3};"
                 : "+f"(d[0]), "+f"(d[1]), "+f"(d[2]), "+f"(d[3])
                 : "r"(a[0]), "r"(a[1]), "r"(a[2]), "r"(a[3]), "r"(b0), "r"(b1));
}
#define CPA16(dst, src) \
    asm volatile("cp.async.cg.shared.global [%0], [%1], 16;" \
                 :: "r"((uint32_t)(dst)), "l"(src) : "memory")
#define CPA_COMMIT() asm volatile("cp.async.commit_group;" ::: "memory")
#define CPA_WAIT0()  asm volatile("cp.async.wait_group 0;" ::: "memory")

// ---------------- prep kernel ----------------
__global__ void prep_kernel(const float* __restrict__ qkv_w,
                            const float* __restrict__ proj_w,
                            const float* __restrict__ mask,
                            const float* __restrict__ bt,
                            int nwin)
{
    const int gt = blockIdx.x * blockDim.x + threadIdx.x;
    const int gsz = gridDim.x * blockDim.x;
    // weights: 4 tiles x 128 rows x 32 float4; q tile pre-scaled by SCALEF
    for (int idx = gt; idx < 16384; idx += gsz) {
        int t = idx >> 12, rem = idx & 4095;
        int r = rem >> 5, c = (rem & 31) << 2;
        const float* src = (t < 3) ? (qkv_w + t * 16384) : proj_w;
        float4 v = ((const float4*)src)[rem];
        float s = (t == 0) ? SCALEF : 1.0f;
        *(uint2*)(g_wtile + t * 32768 + toff(r, c)) =
            make_uint2(packh2(v.x * s, v.y * s), packh2(v.z * s, v.w * s));
    }
    // cm table: [w][k][tid] half2, k = (h2*7+bk)*2 + rr
    for (int idx = gt; idx < nwin * 28 * 256; idx += gsz) {
        int w   = idx / (28 * 256);
        int rem = idx - w * 28 * 256;
        int k   = rem >> 8;
        int tid = rem & 255;
        int rr  = k & 1;
        int bk  = (k >> 1) % 7;
        int h2  = (k >> 1) / 7;
        int wid = tid >> 5, lane = tid & 31;
        int rb = wid & 3, cp = wid >> 2;
        int h  = cp * 2 + h2;
        int r  = rb * 16 + (lane >> 2) + rr * 8;
        int j0 = bk * 8 + (lane & 3) * 2;
        float v0 = -30000.f, v1 = -30000.f;
        if (r < NT) {
            int ia = r / WS, ib = r - ia * WS;
            if (j0 < NT) {
                int ja = j0 / WS, jb = j0 - ja * WS;
                int ridx = (ia - ja + WS - 1) * (2 * WS - 1) + (ib - jb + WS - 1);
                v0 = bt[ridx * HEADS + h] + mask[(w * NT + r) * NT + j0];
            }
            if (j0 + 1 < NT) {
                int j1 = j0 + 1;
                int ja = j1 / WS, jb = j1 - ja * WS;
                int ridx = (ia - ja + WS - 1) * (2 * WS - 1) + (ib - jb + WS - 1);
                v1 = bt[ridx * HEADS + h] + mask[(w * NT + r) * NT + j1];
            }
        }
        ((__half2*)g_cm)[idx] = __floats2half2_rn(v0, v1);
    }
}

// 64x128 @ (128x128)^T, single-term A, warp = 32 rows x 32 cols (wr=2, wc=4).
__device__ __forceinline__ void mma_tile_1t(uint32_t aA, uint32_t bA,
                                            int rb2, int cq, int lane, float acc[2][4][4])
{
    #pragma unroll
    for (int f = 0; f < 2; ++f)
        #pragma unroll
        for (int n = 0; n < 4; ++n)
            #pragma unroll
            for (int j = 0; j < 4; ++j) acc[f][n][j] = 0.f;

    const int arow = rb2 * 32 + (lane & 15);
    const int achk = lane >> 4;
    const uint32_t axor = (uint32_t)(arow & 7);
    const int bn   = cq * 32 + (lane & 7) + ((lane >> 4) << 3);
    const int bchk = (lane >> 3) & 1;
    const uint32_t bxor = (uint32_t)(bn & 7);

    #pragma unroll
    for (int kk = 0; kk < 8; ++kk) {
        uint32_t ao  = (uint32_t)arow * 256 + ((((uint32_t)(kk * 2 + achk)) ^ axor) << 4);
        uint32_t bo0 = (uint32_t)bn * 256 + ((((uint32_t)(kk * 2 + bchk)) ^ bxor) << 4);
        uint32_t ah0[4], ah1[4], bh0[4], bh1[4];
        ldsm4(ah0, aA + ao);
        ldsm4(ah1, aA + ao + 16 * 256);     // (arow+16)&7 == arow&7
        ldsm4(bh0, bA + bo0);
        ldsm4(bh1, bA + bo0 + 16 * 256);
        mma_f16(acc[0][0], ah0, bh0[0], bh0[1]);
        mma_f16(acc[0][1], ah0, bh0[2], bh0[3]);
        mma_f16(acc[0][2], ah0, bh1[0], bh1[1]);
        mma_f16(acc[0][3], ah0, bh1[2], bh1[3]);
        mma_f16(acc[1][0], ah1, bh0[0], bh0[1]);
        mma_f16(acc[1][1], ah1, bh0[2], bh0[3]);
        mma_f16(acc[1][2], ah1, bh1[0], bh1[1]);
        mma_f16(acc[1][3], ah1, bh1[2], bh1[3]);
    }
}

__global__ void __launch_bounds__(THREADS, 2)
winattn_kernel(const float* __restrict__ x,
               const float* __restrict__ qkv_b,
               const float* __restrict__ proj_b,
               float* __restrict__ out,
               int nwin)
{
    extern __shared__ float sm[];
    const uint32_t smem_base = smem_u32(sm);
    float* s_bias = sm + OFF_BIAS;
    char* base8 = (char*)sm;

    char* xhi = base8 + OFF_XHI * 4;
    char* qhi = base8 + OFF_QHI * 4;
    char* khi = base8 + OFF_KHI * 4;
    char* vhi = base8 + OFF_VHI * 4;

    const uint32_t xhiA = smem_base + OFF_XHI * 4;
    const uint32_t qhiA = smem_base + OFF_QHI * 4;
    const uint32_t khiA = smem_base + OFF_KHI * 4;
    const uint32_t vhiA = smem_base + OFF_VHI * 4;
    const uint32_t b0A  = smem_base + OFF_B0 * 4;

    const int tid  = threadIdx.x;
    const int lane = tid & 31;
    const int wid  = tid >> 5;
    const int rb   = wid & 3;     // attention layout (4 row groups x 2 head pairs)
    const int cp   = wid >> 2;
    const int rb2  = wid & 1;     // GEMM layout (2x4)
    const int cq   = wid >> 1;
    const int b    = blockIdx.x;

    const float* xg = x + (long long)b * (NT * DIMC);

    // ---------------- prologue ----------------
    for (int idx = tid; idx < 2048; idx += THREADS)        // weight tile 0 (q)
        CPA16(b0A + idx * 16, g_wtile + idx * 16);
    CPA_COMMIT();
    for (int idx = tid; idx < NT * 32; idx += THREADS) {   // x -> fp16
        int r = idx >> 5, c = (idx & 31) << 2;
        store4(((const float4*)xg)[idx], xhi, toff(r, c));
    }
    {   // zero pad rows 49-63 of q/k/v
        char* tiles[3] = { qhi, khi, vhi };
        for (int idx = tid; idx < 3 * 240; idx += THREADS) {
            int tl = idx / 240, rem = idx - tl * 240;
            *(uint4*)(tiles[tl] + 49 * 256 + rem * 16) = make_uint4(0, 0, 0, 0);
        }
    }
    for (int idx = tid; idx < 512; idx += THREADS) {
        float v = (idx < 3 * DIMC) ? qkv_b[idx] : proj_b[idx - 3 * DIMC];
        s_bias[idx] = (idx < DIMC) ? v * SCALEF : v;   // q bias pre-scaled
    }
    CPA_WAIT0();
    __syncthreads();

    // ---------------- QKV GEMM: tiles t=0(q),1(k),2(v) ----------------
    #pragma unroll 1
    for (int t = 0; t < 3; ++t) {
        float acc[2][4][4];
        mma_tile_1t(xhiA, b0A, rb2, cq, lane, acc);

        char* dst = (t == 0) ? qhi : ((t == 1) ? khi : vhi);
        #pragma unroll
        for (int f = 0; f < 2; ++f) {
            #pragma unroll
            for (int nb = 0; nb < 4; ++nb) {
                int n0 = cq * 32 + nb * 8 + (lane & 3) * 2;
                int r0 = rb2 * 32 + f * 16 + (lane >> 2);
                const float bb0 = s_bias[t * 128 + n0];
                const float bb1 = s_bias[t * 128 + n0 + 1];
                if (r0 < NT)
                    store2(acc[f][nb][0] + bb0, acc[f][nb][1] + bb1, dst, toff(r0, n0));
                if (r0 + 8 < NT)
                    store2(acc[f][nb][2] + bb0, acc[f][nb][3] + bb1, dst, toff(r0 + 8, n0));
            }
        }
        __syncthreads();    // all B reads done
        for (int idx = tid; idx < 2048; idx += THREADS)
            CPA16(b0A + idx * 16, g_wtile + (t + 1) * 32768 + idx * 16);
        CPA_COMMIT();
        CPA_WAIT0();
        __syncthreads();    // B refilled
    }
    // b0 holds proj weights; q/k/v ready (q pre-scaled, biases folded)

    // ---------------- attention: per-h2 register pipeline ----------------
    // scores MMA -> softmax (cm table) -> PV with register-direct P fragments.
    // attn-out (hi) staged into xhi (dead after qkv GEMMs; not read here).
    const int arow = rb * 16 + (lane & 15);
    const uint32_t axor = (uint32_t)(arow & 7);
    const __half2* cmw = reinterpret_cast<const __half2*>(g_cm)
                       + ((long long)(b % nwin) * 28) * 256 + tid;
    const int r0l = rb * 16 + (lane >> 2);

    #pragma unroll
    for (int h2 = 0; h2 < 2; ++h2) {
        const int h = cp * 2 + h2;

        // -- scores --
        float sacc[7][4];
        #pragma unroll
        for (int bk = 0; bk < 7; ++bk)
            #pragma unroll
            for (int j = 0; j < 4; ++j) sacc[bk][j] = 0.f;
        #pragma unroll
        for (int kk = 0; kk < 2; ++kk) {
            uint32_t achunk = (uint32_t)(h * 4 + kk * 2 + (lane >> 4));
            uint32_t ao = (uint32_t)arow * 256 + ((achunk ^ axor) << 4);
            uint32_t qh_[4];
            ldsm4(qh_, qhiA + ao);
            #pragma unroll
            for (int g = 0; g < 4; ++g) {
                int bn = g * 16 + (lane & 7) + ((lane >> 4) << 3);
                uint32_t bchunk = (uint32_t)(h * 4 + kk * 2 + ((lane >> 3) & 1));
                uint32_t bo = (uint32_t)bn * 256 + ((bchunk ^ (uint32_t)(bn & 7)) << 4);
                uint32_t kh_[4];
                ldsm4(kh_, khiA + bo);
                mma_f16(sacc[2 * g], qh_, kh_[0], kh_[1]);
                if (2 * g + 1 < 7)
                    mma_f16(sacc[2 * g + 1], qh_, kh_[2], kh_[3]);
            }
        }

        // -- softmax (fragment-local, cm from baked table) --
        float sum0 = 0.f, sum1 = 0.f;
        #pragma unroll
        for (int bk = 0; bk < 7; ++bk) {
            float2 c0 = __half22float2(__ldg(&cmw[((h2 * 7 + bk) * 2 + 0) * 256]));
            float2 c1 = __half22float2(__ldg(&cmw[((h2 * 7 + bk) * 2 + 1) * 256]));
            float e00 = __expf(sacc[bk][0] + c0.x);
            float e01 = __expf(sacc[bk][1] + c0.y);
            float e10 = __expf(sacc[bk][2] + c1.x);
            float e11 = __expf(sacc[bk][3] + c1.y);
            sum0 += e00 + e01;
            sum1 += e10 + e11;
            sacc[bk][0] = e00; sacc[bk][1] = e01;
            sacc[bk][2] = e10; sacc[bk][3] = e11;
        }
        sum0 += __shfl_xor_sync(0xffffffffu, sum0, 1);
        sum0 += __shfl_xor_sync(0xffffffffu, sum0, 2);
        sum1 += __shfl_xor_sync(0xffffffffu, sum1, 1);
        sum1 += __shfl_xor_sync(0xffffffffu, sum1, 2);
        const float inv0 = 1.0f / sum0;
        const float inv1 = 1.0f / sum1;

        // -- PV: A = P fragments built in registers (D-frag == A-frag layout) --
        float pacc[4][4];
        #pragma unroll
        for (int nb = 0; nb < 4; ++nb)
            #pragma unroll
            for (int j = 0; j < 4; ++j) pacc[nb][j] = 0.f;

        #pragma unroll
        for (int kc = 0; kc < 4; ++kc) {
            uint32_t pa[4];
            pa[0] = packh2(sacc[2 * kc][0] * inv0, sacc[2 * kc][1] * inv0);
            pa[1] = packh2(sacc[2 * kc][2] * inv1, sacc[2 * kc][3] * inv1);
            if (2 * kc + 1 < 7) {
                pa[2] = packh2(sacc[2 * kc + 1][0] * inv0, sacc[2 * kc + 1][1] * inv0);
                pa[3] = packh2(sacc[2 * kc + 1][2] * inv1, sacc[2 * kc + 1][3] * inv1);
            } else {
                pa[2] = 0u; pa[3] = 0u;      // j in [56,64): padded, P = 0
            }
            #pragma unroll
            for (int g = 0; g < 2; ++g) {
                int vr = kc * 16 + ((lane >> 3) & 1) * 8 + (lane & 7);
                uint32_t vchunk = (uint32_t)(h * 4 + g * 2 + (lane >> 4));
                uint32_t vo = (uint32_t)vr * 256 + ((vchunk ^ (uint32_t)(vr & 7)) << 4);
                uint32_t vh_[4];
                ldsm4t(vh_, vhiA + vo);
                mma_f16(pacc[2 * g],     pa, vh_[0], vh_[1]);
                mma_f16(pacc[2 * g + 1], pa, vh_[2], vh_[3]);
            }
        }

        // -- attn-out (hi only) -> xhi --
        #pragma unroll
        for (int nb = 0; nb < 4; ++nb) {
            int d0 = nb * 8 + (lane & 3) * 2;
            store2(pacc[nb][0], pacc[nb][1], xhi, toff(r0l,     h * HD + d0));
            store2(pacc[nb][2], pacc[nb][3], xhi, toff(r0l + 8, h * HD + d0));
        }
    }
    __syncthreads();   // attn-out visible

    // ---------------- proj GEMM (A = attn-out in xhi, 1-term; B = b0) -> global ----------------
    {
        float acc[2][4][4];
        mma_tile_1t(xhiA, b0A, rb2, cq, lane, acc);
        float* dstbase = out + (long long)b * (NT * DIMC);
        #pragma unroll
        for (int f = 0; f < 2; ++f) {
            #pragma unroll
            for (int nb = 0; nb < 4; ++nb) {
                int n0 = cq * 32 + nb * 8 + (lane & 3) * 2;
                int r0 = rb2 * 32 + f * 16 + (lane >> 2);
                const float bb0 = s_bias[3 * DIMC + n0];
                const float bb1 = s_bias[3 * DIMC + n0 + 1];
                if (r0 < NT) {
                    float* p = dstbase + r0 * DIMC + n0;
                    p[0] = acc[f][nb][0] + bb0;
                    p[1] = acc[f][nb][1] + bb1;
                }
                if (r0 + 8 < NT) {
                    float* p = dstbase + (r0 + 8) * DIMC + n0;
                    p[0] = acc[f][nb][2] + bb0;
                    p[1] = acc[f][nb][3] + bb1;
                }
            }
        }
    }
}

extern "C" void kernel_launch(void* const* d_in, const int* in_sizes, int n_in,
                              void* d_out, int out_size) {
    const float* x      = (const float*)d_in[0];
    const float* mask   = (const float*)d_in[1];
    const float* qkv_w  = (const float*)d_in[2];
    const float* qkv_b  = (const float*)d_in[3];
    const float* proj_w = (const float*)d_in[4];
    const float* proj_b = (const float*)d_in[5];
    const float* bt     = (const float*)d_in[6];
    float* out = (float*)d_out;

    const int B    = in_sizes[0] / (NT * DIMC);   // 4096
    const int nwin = in_sizes[1] / (NT * NT);     // 64

    prep_kernel<<<512, 256>>>(qkv_w, proj_w, mask, bt, nwin > 0 ? nwin : 1);

    cudaFuncSetAttribute(winattn_kernel,
                         cudaFuncAttributeMaxDynamicSharedMemorySize, SMEM_BYTES);
    winattn_kernel<<<B, THREADS, SMEM_BYTES>>>(x, qkv_b, proj_b, out, B > 0 ? nwin : 1);
}

// round 16
// speedup vs baseline: 6.0633x; 1.0076x over previous
#include <cuda_runtime.h>
#include <cuda_fp16.h>
#include <cstdint>

// ---------------- problem constants ----------------
#define NT     49
#define DIMC   128
#define HEADS  4
#define HD     32
#define WS     7
#define SCALEF 0.17677669529663687f
#define THREADS 256

// ---------------- global scratch (static, allowed) ----------------
__device__ __align__(16) unsigned char g_wtile[4 * 32768];       // fp16 swizzled weight tiles
__device__ __align__(16) unsigned char g_cm[64 * 28 * 256 * 4];  // fragment-ordered bias+mask (half2)

// ---------------- smem layout (float offsets) ----------------
#define OFF_BIAS  0                    // 512 floats
#define OFF_MBAR  512                  // 2 floats (8B mbarrier)
#define OFF_XHI   576                  // 2304B -> 256B aligned; 64x128 fp16 tiles = 4096 floats
#define OFF_QHI   (OFF_XHI + 4096)
#define OFF_KHI   (OFF_QHI + 4096)
#define OFF_VHI   (OFF_KHI + 4096)
#define OFF_B0    (OFF_VHI + 4096)     // 128x128 fp16 = 8192 floats
#define SMEM_FLOATS (OFF_B0 + 8192)    // 25152
#define SMEM_BYTES  (SMEM_FLOATS * 4)  // 100608 (x2 CTAs = 197KB)

static_assert((OFF_XHI * 4) % 256 == 0, "tile align");

// ---------------- helpers ----------------
__device__ __forceinline__ uint32_t smem_u32(const void* p) {
    uint32_t a;
    asm("{ .reg .u64 t; cvta.to.shared.u64 t, %1; cvt.u32.u64 %0, t; }" : "=r"(a) : "l"(p));
    return a;
}
__device__ __forceinline__ uint32_t toff(int r, int c) {       // 256B rows
    return (uint32_t)(r * 256 + ((((c >> 3) ^ (r & 7))) << 4) + ((c & 7) << 1));
}
__device__ __forceinline__ uint32_t packh2(float a, float b) { // a->low, b->high
    __half2 h = __floats2half2_rn(a, b);
    return *reinterpret_cast<uint32_t*>(&h);
}
__device__ __forceinline__ void store4(float4 v, char* hb, uint32_t off) {
    *(uint2*)(hb + off) = make_uint2(packh2(v.x, v.y), packh2(v.z, v.w));
}
__device__ __forceinline__ void store2(float a, float b, char* hb, uint32_t off) {
    *(uint32_t*)(hb + off) = packh2(a, b);
}
__device__ __forceinline__ void ldsm4(uint32_t r[4], uint32_t addr) {
    asm volatile("ldmatrix.sync.aligned.m8n8.x4.shared.b16 {%0,%1,%2,%3}, [%4];"
                 : "=r"(r[0]), "=r"(r[1]), "=r"(r[2]), "=r"(r[3]) : "r"(addr));
}
__device__ __forceinline__ void ldsm4t(uint32_t r[4], uint32_t addr) {
    asm volatile("ldmatrix.sync.aligned.m8n8.x4.trans.shared.b16 {%0,%1,%2,%3}, [%4];"
                 : "=r"(r[0]), "=r"(r[1]), "=r"(r[2]), "=r"(r[3]) : "r"(addr));
}
__device__ __forceinline__ void mma_f16(float d[4], const uint32_t a[4],
                                        uint32_t b0, uint32_t b1) {
    asm volatile("mma.sync.aligned.m16n8k16.row.col.f32.f16.f16.f32 "
                 "{%0,%1,%2,%3},{%4,%5,%6,%7},{%8,%9},{%0,%1,%2,%3};"
                 : "+f"(d[0]), "+f"(d[1]), "+f"(d[2]), "+f"(d[3])
                 : "r"(a[0]), "r"(a[1]), "r"(a[2]), "r"(a[3]), "r"(b0), "r"(b1));
}
#define CPA16(dst, src) \
    asm volatile("cp.async.cg.shared.global [%0], [%1], 16;" \
                 :: "r"((uint32_t)(dst)), "l"(src) : "memory")
#define CPA_COMMIT() asm volatile("cp.async.commit_group;" ::: "memory")
#define CPA_WAIT0()  asm volatile("cp.async.wait_group 0;" ::: "memory")

#define MBARRIER_INIT(mb, n) \
    asm volatile("mbarrier.init.shared.b64 [%0], %1;" :: "r"((uint32_t)(mb)), "r"((uint32_t)(n)) : "memory")
#define MBARRIER_EXPECT_TX(mb, tx) \
    asm volatile("mbarrier.arrive.expect_tx.shared.b64 _, [%0], %1;" \
                 :: "r"((uint32_t)(mb)), "r"((uint32_t)(tx)) : "memory")
#define CPA_BULK(dst, src, bytes, mb) \
    asm volatile("cp.async.bulk.shared::cta.global.mbarrier::complete_tx::bytes [%0], [%1], %2, [%3];" \
                 :: "r"((uint32_t)(dst)), "l"(src), "r"((uint32_t)(bytes)), "r"((uint32_t)(mb)) : "memory")
#define MBARRIER_WAIT_PARITY(mb, ph) do {                                          \
    uint32_t _m = (uint32_t)(mb), _p = (uint32_t)(ph), _d;                         \
    asm volatile("{ .reg .pred p; mbarrier.try_wait.parity.acquire.cta.shared::cta.b64 p, [%1], %2;" \
                 " selp.b32 %0,1,0,p; }" : "=r"(_d) : "r"(_m), "r"(_p) : "memory");\
    if (!_d) {                                                                     \
        asm volatile("{ .reg .pred P1; WL_%=:"                                     \
                     " mbarrier.try_wait.parity.acquire.cta.shared::cta.b64 P1, [%0], %1, 0x989680;" \
                     " @P1 bra.uni WD_%=; bra.uni WL_%=; WD_%=: }"                 \
                     :: "r"(_m), "r"(_p) : "memory");                              \
    }                                                                              \
} while (0)

// ---------------- prep kernel ----------------
__global__ void prep_kernel(const float* __restrict__ qkv_w,
                            const float* __restrict__ proj_w,
                            const float* __restrict__ mask,
                            const float* __restrict__ bt,
                            int nwin)
{
    const int gt = blockIdx.x * blockDim.x + threadIdx.x;
    const int gsz = gridDim.x * blockDim.x;
    // weights: 4 tiles x 128 rows x 32 float4; q tile pre-scaled by SCALEF
    for (int idx = gt; idx < 16384; idx += gsz) {
        int t = idx >> 12, rem = idx & 4095;
        int r = rem >> 5, c = (rem & 31) << 2;
        const float* src = (t < 3) ? (qkv_w + t * 16384) : proj_w;
        float4 v = ((const float4*)src)[rem];
        float s = (t == 0) ? SCALEF : 1.0f;
        *(uint2*)(g_wtile + t * 32768 + toff(r, c)) =
            make_uint2(packh2(v.x * s, v.y * s), packh2(v.z * s, v.w * s));
    }
    // cm table: [w][k][tid] half2, k = (h2*7+bk)*2 + rr
    for (int idx = gt; idx < nwin * 28 * 256; idx += gsz) {
        int w   = idx / (28 * 256);
        int rem = idx - w * 28 * 256;
        int k   = rem >> 8;
        int tid = rem & 255;
        int rr  = k & 1;
        int bk  = (k >> 1) % 7;
        int h2  = (k >> 1) / 7;
        int wid = tid >> 5, lane = tid & 31;
        int rb = wid & 3, cp = wid >> 2;
        int h  = cp * 2 + h2;
        int r  = rb * 16 + (lane >> 2) + rr * 8;
        int j0 = bk * 8 + (lane & 3) * 2;
        float v0 = -30000.f, v1 = -30000.f;
        if (r < NT) {
            int ia = r / WS, ib = r - ia * WS;
            if (j0 < NT) {
                int ja = j0 / WS, jb = j0 - ja * WS;
                int ridx = (ia - ja + WS - 1) * (2 * WS - 1) + (ib - jb + WS - 1);
                v0 = bt[ridx * HEADS + h] + mask[(w * NT + r) * NT + j0];
            }
            if (j0 + 1 < NT) {
                int j1 = j0 + 1;
                int ja = j1 / WS, jb = j1 - ja * WS;
                int ridx = (ia - ja + WS - 1) * (2 * WS - 1) + (ib - jb + WS - 1);
                v1 = bt[ridx * HEADS + h] + mask[(w * NT + r) * NT + j1];
            }
        }
        ((__half2*)g_cm)[idx] = __floats2half2_rn(v0, v1);
    }
}

// 64x128 @ (128x128)^T, single-term A, warp = 32 rows x 32 cols (wr=2, wc=4).
__device__ __forceinline__ void mma_tile_1t(uint32_t aA, uint32_t bA,
                                            int rb2, int cq, int lane, float acc[2][4][4])
{
    #pragma unroll
    for (int f = 0; f < 2; ++f)
        #pragma unroll
        for (int n = 0; n < 4; ++n)
            #pragma unroll
            for (int j = 0; j < 4; ++j) acc[f][n][j] = 0.f;

    const int arow = rb2 * 32 + (lane & 15);
    const int achk = lane >> 4;
    const uint32_t axor = (uint32_t)(arow & 7);
    const int bn   = cq * 32 + (lane & 7) + ((lane >> 4) << 3);
    const int bchk = (lane >> 3) & 1;
    const uint32_t bxor = (uint32_t)(bn & 7);

    #pragma unroll
    for (int kk = 0; kk < 8; ++kk) {
        uint32_t ao  = (uint32_t)arow * 256 + ((((uint32_t)(kk * 2 + achk)) ^ axor) << 4);
        uint32_t bo0 = (uint32_t)bn * 256 + ((((uint32_t)(kk * 2 + bchk)) ^ bxor) << 4);
        uint32_t ah0[4], ah1[4], bh0[4], bh1[4];
        ldsm4(ah0, aA + ao);
        ldsm4(ah1, aA + ao + 16 * 256);     // (arow+16)&7 == arow&7
        ldsm4(bh0, bA + bo0);
        ldsm4(bh1, bA + bo0 + 16 * 256);
        mma_f16(acc[0][0], ah0, bh0[0], bh0[1]);
        mma_f16(acc[0][1], ah0, bh0[2], bh0[3]);
        mma_f16(acc[0][2], ah0, bh1[0], bh1[1]);
        mma_f16(acc[0][3], ah0, bh1[2], bh1[3]);
        mma_f16(acc[1][0], ah1, bh0[0], bh0[1]);
        mma_f16(acc[1][1], ah1, bh0[2], bh0[3]);
        mma_f16(acc[1][2], ah1, bh1[0], bh1[1]);
        mma_f16(acc[1][3], ah1, bh1[2], bh1[3]);
    }
}

__global__ void __launch_bounds__(THREADS, 2)
winattn_kernel(const float* __restrict__ x,
               const float* __restrict__ qkv_b,
               const float* __restrict__ proj_b,
               float* __restrict__ out,
               int nwin)
{
    extern __shared__ float sm[];
    const uint32_t smem_base = smem_u32(sm);
    float* s_bias = sm + OFF_BIAS;
    char* base8 = (char*)sm;

    char* xhi = base8 + OFF_XHI * 4;
    char* qhi = base8 + OFF_QHI * 4;
    char* khi = base8 + OFF_KHI * 4;
    char* vhi = base8 + OFF_VHI * 4;

    const uint32_t xhiA = smem_base + OFF_XHI * 4;
    const uint32_t qhiA = smem_base + OFF_QHI * 4;
    const uint32_t khiA = smem_base + OFF_KHI * 4;
    const uint32_t vhiA = smem_base + OFF_VHI * 4;
    const uint32_t b0A  = smem_base + OFF_B0 * 4;
    const uint32_t mbar = smem_base + OFF_MBAR * 4;

    const int tid  = threadIdx.x;
    const int lane = tid & 31;
    const int wid  = tid >> 5;
    const int rb   = wid & 3;     // attention layout (4 row groups x 2 head pairs)
    const int cp   = wid >> 2;
    const int rb2  = wid & 1;     // GEMM layout (2x4)
    const int cq   = wid >> 1;
    const int b    = blockIdx.x;

    const float* xg = x + (long long)b * (NT * DIMC);

    // ---------------- prologue ----------------
    if (tid == 0) MBARRIER_INIT(mbar, 1);
    for (int idx = tid; idx < 2048; idx += THREADS)        // weight tile 0 (q) via LDGSTS
        CPA16(b0A + idx * 16, g_wtile + idx * 16);
    CPA_COMMIT();
    for (int idx = tid; idx < NT * 32; idx += THREADS) {   // x -> fp16
        int r = idx >> 5, c = (idx & 31) << 2;
        store4(((const float4*)xg)[idx], xhi, toff(r, c));
    }
    {   // zero pad rows 49-63 of q/k/v
        char* tiles[3] = { qhi, khi, vhi };
        for (int idx = tid; idx < 3 * 240; idx += THREADS) {
            int tl = idx / 240, rem = idx - tl * 240;
            *(uint4*)(tiles[tl] + 49 * 256 + rem * 16) = make_uint4(0, 0, 0, 0);
        }
    }
    for (int idx = tid; idx < 512; idx += THREADS) {
        float v = (idx < 3 * DIMC) ? qkv_b[idx] : proj_b[idx - 3 * DIMC];
        s_bias[idx] = (idx < DIMC) ? v * SCALEF : v;   // q bias pre-scaled
    }
    CPA_WAIT0();
    __syncthreads();   // tile0 + prologue STS + mbarrier init all visible

    // ---------------- QKV GEMM: tiles t=0(q),1(k),2(v); bulk-load next tile ----------------
    #pragma unroll 1
    for (int t = 0; t < 3; ++t) {
        float acc[2][4][4];
        mma_tile_1t(xhiA, b0A, rb2, cq, lane, acc);

        char* dst = (t == 0) ? qhi : ((t == 1) ? khi : vhi);
        #pragma unroll
        for (int f = 0; f < 2; ++f) {
            #pragma unroll
            for (int nb = 0; nb < 4; ++nb) {
                int n0 = cq * 32 + nb * 8 + (lane & 3) * 2;
                int r0 = rb2 * 32 + f * 16 + (lane >> 2);
                const float bb0 = s_bias[t * 128 + n0];
                const float bb1 = s_bias[t * 128 + n0 + 1];
                if (r0 < NT)
                    store2(acc[f][nb][0] + bb0, acc[f][nb][1] + bb1, dst, toff(r0, n0));
                if (r0 + 8 < NT)
                    store2(acc[f][nb][2] + bb0, acc[f][nb][3] + bb1, dst, toff(r0 + 8, n0));
            }
        }
        __syncthreads();    // all b0 reads + epilogue STS done
        if (tid == 0) {     // bulk-load next tile (t=2 -> proj, wait deferred past attention)
            MBARRIER_EXPECT_TX(mbar, 32768);
            CPA_BULK(b0A, g_wtile + (t + 1) * 32768, 32768, mbar);
        }
        if (t < 2) MBARRIER_WAIT_PARITY(mbar, t & 1);   // acquire: b0 visible to all
    }
    // q/k/v ready (q pre-scaled, biases folded); proj bulk in flight

    // ---------------- attention: per-h2 register pipeline ----------------
    const int arow = rb * 16 + (lane & 15);
    const uint32_t axor = (uint32_t)(arow & 7);
    const __half2* cmw = reinterpret_cast<const __half2*>(g_cm)
                       + ((long long)(b % nwin) * 28) * 256 + tid;
    const int r0l = rb * 16 + (lane >> 2);

    #pragma unroll
    for (int h2 = 0; h2 < 2; ++h2) {
        const int h = cp * 2 + h2;

        // -- scores --
        float sacc[7][4];
        #pragma unroll
        for (int bk = 0; bk < 7; ++bk)
            #pragma unroll
            for (int j = 0; j < 4; ++j) sacc[bk][j] = 0.f;
        #pragma unroll
        for (int kk = 0; kk < 2; ++kk) {
            uint32_t achunk = (uint32_t)(h * 4 + kk * 2 + (lane >> 4));
            uint32_t ao = (uint32_t)arow * 256 + ((achunk ^ axor) << 4);
            uint32_t qh_[4];
            ldsm4(qh_, qhiA + ao);
            #pragma unroll
            for (int g = 0; g < 4; ++g) {
                int bn = g * 16 + (lane & 7) + ((lane >> 4) << 3);
                uint32_t bchunk = (uint32_t)(h * 4 + kk * 2 + ((lane >> 3) & 1));
                uint32_t bo = (uint32_t)bn * 256 + ((bchunk ^ (uint32_t)(bn & 7)) << 4);
                uint32_t kh_[4];
                ldsm4(kh_, khiA + bo);
                mma_f16(sacc[2 * g], qh_, kh_[0], kh_[1]);
                if (2 * g + 1 < 7)
                    mma_f16(sacc[2 * g + 1], qh_, kh_[2], kh_[3]);
            }
        }

        // -- softmax (fragment-local, cm from baked table) --
        float sum0 = 0.f, sum1 = 0.f;
        #pragma unroll
        for (int bk = 0; bk < 7; ++bk) {
            float2 c0 = __half22float2(__ldg(&cmw[((h2 * 7 + bk) * 2 + 0) * 256]));
            float2 c1 = __half22float2(__ldg(&cmw[((h2 * 7 + bk) * 2 + 1) * 256]));
            float e00 = __expf(sacc[bk][0] + c0.x);
            float e01 = __expf(sacc[bk][1] + c0.y);
            float e10 = __expf(sacc[bk][2] + c1.x);
            float e11 = __expf(sacc[bk][3] + c1.y);
            sum0 += e00 + e01;
            sum1 += e10 + e11;
            sacc[bk][0] = e00; sacc[bk][1] = e01;
            sacc[bk][2] = e10; sacc[bk][3] = e11;
        }
        sum0 += __shfl_xor_sync(0xffffffffu, sum0, 1);
        sum0 += __shfl_xor_sync(0xffffffffu, sum0, 2);
        sum1 += __shfl_xor_sync(0xffffffffu, sum1, 1);
        sum1 += __shfl_xor_sync(0xffffffffu, sum1, 2);
        const float inv0 = 1.0f / sum0;
        const float inv1 = 1.0f / sum1;

        // -- PV: A = P fragments built in registers (D-frag == A-frag layout) --
        float pacc[4][4];
        #pragma unroll
        for (int nb = 0; nb < 4; ++nb)
            #pragma unroll
            for (int j = 0; j < 4; ++j) pacc[nb][j] = 0.f;

        #pragma unroll
        for (int kc = 0; kc < 4; ++kc) {
            uint32_t pa[4];
            pa[0] = packh2(sacc[2 * kc][0] * inv0, sacc[2 * kc][1] * inv0);
            pa[1] = packh2(sacc[2 * kc][2] * inv1, sacc[2 * kc][3] * inv1);
            if (2 * kc + 1 < 7) {
                pa[2] = packh2(sacc[2 * kc + 1][0] * inv0, sacc[2 * kc + 1][1] * inv0);
                pa[3] = packh2(sacc[2 * kc + 1][2] * inv1, sacc[2 * kc + 1][3] * inv1);
            } else {
                pa[2] = 0u; pa[3] = 0u;      // j in [56,64): padded, P = 0
            }
            #pragma unroll
            for (int g = 0; g < 2; ++g) {
                int vr = kc * 16 + ((lane >> 3) & 1) * 8 + (lane & 7);
                uint32_t vchunk = (uint32_t)(h * 4 + g * 2 + (lane >> 4));
                uint32_t vo = (uint32_t)vr * 256 + ((vchunk ^ (uint32_t)(vr & 7)) << 4);
                uint32_t vh_[4];
                ldsm4t(vh_, vhiA + vo);
                mma_f16(pacc[2 * g],     pa, vh_[0], vh_[1]);
                mma_f16(pacc[2 * g + 1], pa, vh_[2], vh_[3]);
            }
        }

        // -- attn-out (hi only) -> xhi (dead after qkv GEMMs) --
        #pragma unroll
        for (int nb = 0; nb < 4; ++nb) {
            int d0 = nb * 8 + (lane & 3) * 2;
            store2(pacc[nb][0], pacc[nb][1], xhi, toff(r0l,     h * HD + d0));
            store2(pacc[nb][2], pacc[nb][3], xhi, toff(r0l + 8, h * HD + d0));
        }
    }
    __syncthreads();                       // attn-out visible
    MBARRIER_WAIT_PARITY(mbar, 0);         // proj weights landed (acquire)

    // ---------------- proj GEMM (A = attn-out in xhi, 1-term; B = b0) -> global ----------------
    {
        float acc[2][4][4];
        mma_tile_1t(xhiA, b0A, rb2, cq, lane, acc);
        float* dstbase = out + (long long)b * (NT * DIMC);
        #pragma unroll
        for (int f = 0; f < 2; ++f) {
            #pragma unroll
            for (int nb = 0; nb < 4; ++nb) {
                int n0 = cq * 32 + nb * 8 + (lane & 3) * 2;
                int r0 = rb2 * 32 + f * 16 + (lane >> 2);
                const float bb0 = s_bias[3 * DIMC + n0];
                const float bb1 = s_bias[3 * DIMC + n0 + 1];
                if (r0 < NT) {
                    float* p = dstbase + r0 * DIMC + n0;
                    p[0] = acc[f][nb][0] + bb0;
                    p[1] = acc[f][nb][1] + bb1;
                }
                if (r0 + 8 < NT) {
                    float* p = dstbase + (r0 + 8) * DIMC + n0;
                    p[0] = acc[f][nb][2] + bb0;
                    p[1] = acc[f][nb][3] + bb1;
                }
            }
        }
    }
}

extern "C" void kernel_launch(void* const* d_in, const int* in_sizes, int n_in,
                              void* d_out, int out_size) {
    const float* x      = (const float*)d_in[0];
    const float* mask   = (const float*)d_in[1];
    const float* qkv_w  = (const float*)d_in[2];
    const float* qkv_b  = (const float*)d_in[3];
    const float* proj_w = (const float*)d_in[4];
    const float* proj_b = (const float*)d_in[5];
    const float* bt     = (const float*)d_in[6];
    float* out = (float*)d_out;

    const int B    = in_sizes[0] / (NT * DIMC);   // 4096
    const int nwin = in_sizes[1] / (NT * NT);     // 64

    prep_kernel<<<512, 256>>>(qkv_w, proj_w, mask, bt, nwin > 0 ? nwin : 1);

    cudaFuncSetAttribute(winattn_kernel,
                         cudaFuncAttributeMaxDynamicSharedMemorySize, SMEM_BYTES);
    winattn_kernel<<<B, THREADS, SMEM_BYTES>>>(x, qkv_b, proj_b, out, B > 0 ? nwin : 1);
}

// round 17
// speedup vs baseline: 6.3027x; 1.0395x over previous
#include <cuda_runtime.h>
#include <cuda_fp16.h>
#include <cstdint>

// ---------------- problem constants ----------------
#define NT     49
#define DIMC   128
#define HEADS  4
#define HD     32
#define WS     7
#define SCALEF 0.17677669529663687f
#define THREADS 256

// ---------------- global scratch (static, allowed) ----------------
// weight tiles stored as 2 K-halves each: [tile][half][r:128][chunk:8 x 16B] (xor-swizzled)
__device__ __align__(16) unsigned char g_wtile[4 * 32768];
__device__ __align__(16) unsigned char g_cm[64 * 28 * 256 * 4];  // fragment-ordered bias+mask (half2)

// ---------------- smem layout (float offsets) ----------------
#define OFF_BIAS  0                    // 512 floats
#define OFF_MBAR  512                  // 4 floats (2 x 8B mbarriers)
#define OFF_XHI   576                  // 2304B, 256B aligned; 64x128 fp16 tiles = 4096 floats
#define OFF_QHI   (OFF_XHI + 4096)
#define OFF_KHI   (OFF_QHI + 4096)
#define OFF_VHI   (OFF_KHI + 4096)
#define OFF_BH0   (OFF_VHI + 4096)     // 16KB weight K-half buffer
#define OFF_BH1   (OFF_BH0 + 4096)     // 16KB weight K-half buffer
#define SMEM_FLOATS (OFF_BH1 + 4096)   // 25152
#define SMEM_BYTES  (SMEM_FLOATS * 4)  // 100608 (x2 CTAs = 197KB)

static_assert((OFF_XHI * 4) % 256 == 0, "tile align");

// ---------------- helpers ----------------
__device__ __forceinline__ uint32_t smem_u32(const void* p) {
    uint32_t a;
    asm("{ .reg .u64 t; cvta.to.shared.u64 t, %1; cvt.u32.u64 %0, t; }" : "=r"(a) : "l"(p));
    return a;
}
__device__ __forceinline__ uint32_t toff(int r, int c) {       // 256B rows (A-side tiles)
    return (uint32_t)(r * 256 + ((((c >> 3) ^ (r & 7))) << 4) + ((c & 7) << 1));
}
__device__ __forceinline__ uint32_t packh2(float a, float b) { // a->low, b->high
    __half2 h = __floats2half2_rn(a, b);
    return *reinterpret_cast<uint32_t*>(&h);
}
__device__ __forceinline__ void store4(float4 v, char* hb, uint32_t off) {
    *(uint2*)(hb + off) = make_uint2(packh2(v.x, v.y), packh2(v.z, v.w));
}
__device__ __forceinline__ void store2(float a, float b, char* hb, uint32_t off) {
    *(uint32_t*)(hb + off) = packh2(a, b);
}
__device__ __forceinline__ void ldsm4(uint32_t r[4], uint32_t addr) {
    asm volatile("ldmatrix.sync.aligned.m8n8.x4.shared.b16 {%0,%1,%2,%3}, [%4];"
                 : "=r"(r[0]), "=r"(r[1]), "=r"(r[2]), "=r"(r[3]) : "r"(addr));
}
__device__ __forceinline__ void ldsm4t(uint32_t r[4], uint32_t addr) {
    asm volatile("ldmatrix.sync.aligned.m8n8.x4.trans.shared.b16 {%0,%1,%2,%3}, [%4];"
                 : "=r"(r[0]), "=r"(r[1]), "=r"(r[2]), "=r"(r[3]) : "r"(addr));
}
__device__ __forceinline__ void mma_f16(float d[4], const uint32_t a[4],
                                        uint32_t b0, uint32_t b1) {
    asm volatile("mma.sync.aligned.m16n8k16.row.col.f32.f16.f16.f32 "
                 "{%0,%1,%2,%3},{%4,%5,%6,%7},{%8,%9},{%0,%1,%2,%3};"
                 : "+f"(d[0]), "+f"(d[1]), "+f"(d[2]), "+f"(d[3])
                 : "r"(a[0]), "r"(a[1]), "r"(a[2]), "r"(a[3]), "r"(b0), "r"(b1));
}

#define MBARRIER_INIT(mb, n) \
    asm volatile("mbarrier.init.shared.b64 [%0], %1;" :: "r"((uint32_t)(mb)), "r"((uint32_t)(n)) : "memory")
#define MBARRIER_EXPECT_TX(mb, tx) \
    asm volatile("mbarrier.arrive.expect_tx.shared.b64 _, [%0], %1;" \
                 :: "r"((uint32_t)(mb)), "r"((uint32_t)(tx)) : "memory")
#define CPA_BULK(dst, src, bytes, mb) \
    asm volatile("cp.async.bulk.shared::cta.global.mbarrier::complete_tx::bytes [%0], [%1], %2, [%3];" \
                 :: "r"((uint32_t)(dst)), "l"(src), "r"((uint32_t)(bytes)), "r"((uint32_t)(mb)) : "memory")
#define FENCE_PROXY_ASYNC() asm volatile("fence.proxy.async.shared::cta;" ::: "memory")
#define MBARRIER_WAIT_PARITY(mb, ph) do {                                          \
    uint32_t _m = (uint32_t)(mb), _p = (uint32_t)(ph), _d;                         \
    asm volatile("{ .reg .pred p; mbarrier.try_wait.parity.acquire.cta.shared::cta.b64 p, [%1], %2;" \
                 " selp.b32 %0,1,0,p; }" : "=r"(_d) : "r"(_m), "r"(_p) : "memory");\
    if (!_d) {                                                                     \
        asm volatile("{ .reg .pred P1; WL_%=:"                                     \
                     " mbarrier.try_wait.parity.acquire.cta.shared::cta.b64 P1, [%0], %1, 0x989680;" \
                     " @P1 bra.uni WD_%=; bra.uni WL_%=; WD_%=: }"                 \
                     :: "r"(_m), "r"(_p) : "memory");                              \
    }                                                                              \
} while (0)

// ---------------- prep kernel ----------------
__global__ void prep_kernel(const float* __restrict__ qkv_w,
                            const float* __restrict__ proj_w,
                            const float* __restrict__ mask,
                            const float* __restrict__ bt,
                            int nwin)
{
    const int gt = blockIdx.x * blockDim.x + threadIdx.x;
    const int gsz = gridDim.x * blockDim.x;
    // weights: 4 tiles x 128 rows x 32 float4; stored as 2 K-half blocks per tile
    // (128B rows, xor-swizzled over 8 chunks). q tile pre-scaled by SCALEF.
    for (int idx = gt; idx < 16384; idx += gsz) {
        int t = idx >> 12, rem = idx & 4095;
        int r = rem >> 5, c4 = rem & 31;
        int k0 = c4 * 4;
        int half = k0 >> 6;
        int ch   = (k0 & 63) >> 3;
        int sub  = (k0 & 4) ? 8 : 0;
        const float* src = (t < 3) ? (qkv_w + t * 16384) : proj_w;
        float4 v = ((const float4*)src)[rem];
        float s = (t == 0) ? SCALEF : 1.0f;
        uint32_t off = (uint32_t)(t * 32768 + half * 16384 + r * 128
                                  + ((ch ^ (r & 7)) << 4) + sub);
        *(uint2*)(g_wtile + off) =
            make_uint2(packh2(v.x * s, v.y * s), packh2(v.z * s, v.w * s));
    }
    // cm table: [w][k][tid] half2, k = (h2*7+bk)*2 + rr
    for (int idx = gt; idx < nwin * 28 * 256; idx += gsz) {
        int w   = idx / (28 * 256);
        int rem = idx - w * 28 * 256;
        int k   = rem >> 8;
        int tid = rem & 255;
        int rr  = k & 1;
        int bk  = (k >> 1) % 7;
        int h2  = (k >> 1) / 7;
        int wid = tid >> 5, lane = tid & 31;
        int rb = wid & 3, cp = wid >> 2;
        int h  = cp * 2 + h2;
        int r  = rb * 16 + (lane >> 2) + rr * 8;
        int j0 = bk * 8 + (lane & 3) * 2;
        float v0 = -30000.f, v1 = -30000.f;
        if (r < NT) {
            int ia = r / WS, ib = r - ia * WS;
            if (j0 < NT) {
                int ja = j0 / WS, jb = j0 - ja * WS;
                int ridx = (ia - ja + WS - 1) * (2 * WS - 1) + (ib - jb + WS - 1);
                v0 = bt[ridx * HEADS + h] + mask[(w * NT + r) * NT + j0];
            }
            if (j0 + 1 < NT) {
                int j1 = j0 + 1;
                int ja = j1 / WS, jb = j1 - ja * WS;
                int ridx = (ia - ja + WS - 1) * (2 * WS - 1) + (ib - jb + WS - 1);
                v1 = bt[ridx * HEADS + h] + mask[(w * NT + r) * NT + j1];
            }
        }
        ((__half2*)g_cm)[idx] = __floats2half2_rn(v0, v1);
    }
}

// one K-half (k = khalf*64 .. +63) of 64x128 @ (128x128)^T; accumulates into acc.
// A: 256B-row tile; B: 128B-row K-half buffer. warp = 32 rows x 32 cols (2x4 grid).
__device__ __forceinline__ void mma_half(uint32_t aA, uint32_t bH, int khalf,
                                         int rb2, int cq, int lane, float acc[2][4][4])
{
    const int arow = rb2 * 32 + (lane & 15);
    const int achk = lane >> 4;
    const uint32_t axor = (uint32_t)(arow & 7);
    const int bn   = cq * 32 + (lane & 7) + ((lane >> 4) << 3);
    const int bchk = (lane >> 3) & 1;
    const uint32_t bxor = (uint32_t)(bn & 7);

    #pragma unroll
    for (int kk = 0; kk < 4; ++kk) {
        const int kg = khalf * 4 + kk;
        uint32_t ao  = (uint32_t)arow * 256 + ((((uint32_t)(kg * 2 + achk)) ^ axor) << 4);
        uint32_t bo0 = (uint32_t)bn * 128 + ((((uint32_t)(kk * 2 + bchk)) ^ bxor) << 4);
        uint32_t ah0[4], ah1[4], bh0[4], bh1[4];
        ldsm4(ah0, aA + ao);
        ldsm4(ah1, aA + ao + 16 * 256);     // (arow+16)&7 == arow&7
        ldsm4(bh0, bH + bo0);
        ldsm4(bh1, bH + bo0 + 16 * 128);    // (bn+16)&7 == bn&7
        mma_f16(acc[0][0], ah0, bh0[0], bh0[1]);
        mma_f16(acc[0][1], ah0, bh0[2], bh0[3]);
        mma_f16(acc[0][2], ah0, bh1[0], bh1[1]);
        mma_f16(acc[0][3], ah0, bh1[2], bh1[3]);
        mma_f16(acc[1][0], ah1, bh0[0], bh0[1]);
        mma_f16(acc[1][1], ah1, bh0[2], bh0[3]);
        mma_f16(acc[1][2], ah1, bh1[0], bh1[1]);
        mma_f16(acc[1][3], ah1, bh1[2], bh1[3]);
    }
}

__global__ void __launch_bounds__(THREADS, 2)
winattn_kernel(const float* __restrict__ x,
               const float* __restrict__ qkv_b,
               const float* __restrict__ proj_b,
               float* __restrict__ out,
               int nwin)
{
    extern __shared__ float sm[];
    const uint32_t smem_base = smem_u32(sm);
    float* s_bias = sm + OFF_BIAS;
    char* base8 = (char*)sm;

    char* xhi = base8 + OFF_XHI * 4;
    char* qhi = base8 + OFF_QHI * 4;
    char* khi = base8 + OFF_KHI * 4;
    char* vhi = base8 + OFF_VHI * 4;

    const uint32_t xhiA = smem_base + OFF_XHI * 4;
    const uint32_t qhiA = smem_base + OFF_QHI * 4;
    const uint32_t khiA = smem_base + OFF_KHI * 4;
    const uint32_t vhiA = smem_base + OFF_VHI * 4;
    const uint32_t bH0A = smem_base + OFF_BH0 * 4;
    const uint32_t bH1A = smem_base + OFF_BH1 * 4;
    const uint32_t mb0  = smem_base + OFF_MBAR * 4;
    const uint32_t mb1  = mb0 + 8;

    const int tid  = threadIdx.x;
    const int lane = tid & 31;
    const int wid  = tid >> 5;
    const int rb   = wid & 3;     // attention layout (4 row groups x 2 head pairs)
    const int cp   = wid >> 2;
    const int rb2  = wid & 1;     // GEMM layout (2x4)
    const int cq   = wid >> 1;
    const int b    = blockIdx.x;

    const float* xg = x + (long long)b * (NT * DIMC);

    // ---------------- prologue ----------------
    if (tid == 0) {
        MBARRIER_INIT(mb0, 1);
        MBARRIER_INIT(mb1, 1);
        FENCE_PROXY_ASYNC();
        MBARRIER_EXPECT_TX(mb0, 16384);
        CPA_BULK(bH0A, g_wtile, 16384, mb0);
        MBARRIER_EXPECT_TX(mb1, 16384);
        CPA_BULK(bH1A, g_wtile + 16384, 16384, mb1);
    }
    for (int idx = tid; idx < NT * 32; idx += THREADS) {   // x -> fp16
        int r = idx >> 5, c = (idx & 31) << 2;
        store4(((const float4*)xg)[idx], xhi, toff(r, c));
    }
    {   // zero pad rows 49-63 of q/k/v
        char* tiles[3] = { qhi, khi, vhi };
        for (int idx = tid; idx < 3 * 240; idx += THREADS) {
            int tl = idx / 240, rem = idx - tl * 240;
            *(uint4*)(tiles[tl] + 49 * 256 + rem * 16) = make_uint4(0, 0, 0, 0);
        }
    }
    for (int idx = tid; idx < 512; idx += THREADS) {
        float v = (idx < 3 * DIMC) ? qkv_b[idx] : proj_b[idx - 3 * DIMC];
        s_bias[idx] = (idx < DIMC) ? v * SCALEF : v;   // q bias pre-scaled
    }
    __syncthreads();   // prologue STS + mbarrier init visible to all

    // ---------------- QKV GEMM: tiles t=0(q),1(k),2(v), pipelined K-half bulks ----------------
    #pragma unroll 1
    for (int t = 0; t < 3; ++t) {
        float acc[2][4][4];
        #pragma unroll
        for (int f = 0; f < 2; ++f)
            #pragma unroll
            for (int n = 0; n < 4; ++n)
                #pragma unroll
                for (int j = 0; j < 4; ++j) acc[f][n][j] = 0.f;

        MBARRIER_WAIT_PARITY(mb0, t & 1);
        mma_half(xhiA, bH0A, 0, rb2, cq, lane, acc);
        __syncthreads();   // all H0 reads done
        if (tid == 0) {    // next tile's k-half0 (t=2 -> proj.h0); overlaps H1 compute
            MBARRIER_EXPECT_TX(mb0, 16384);
            CPA_BULK(bH0A, g_wtile + (t + 1) * 32768, 16384, mb0);
        }
        MBARRIER_WAIT_PARITY(mb1, t & 1);
        mma_half(xhiA, bH1A, 1, rb2, cq, lane, acc);

        char* dst = (t == 0) ? qhi : ((t == 1) ? khi : vhi);
        #pragma unroll
        for (int f = 0; f < 2; ++f) {
            #pragma unroll
            for (int nb = 0; nb < 4; ++nb) {
                int n0 = cq * 32 + nb * 8 + (lane & 3) * 2;
                int r0 = rb2 * 32 + f * 16 + (lane >> 2);
                const float bb0 = s_bias[t * 128 + n0];
                const float bb1 = s_bias[t * 128 + n0 + 1];
                if (r0 < NT)
                    store2(acc[f][nb][0] + bb0, acc[f][nb][1] + bb1, dst, toff(r0, n0));
                if (r0 + 8 < NT)
                    store2(acc[f][nb][2] + bb0, acc[f][nb][3] + bb1, dst, toff(r0 + 8, n0));
            }
        }
        __syncthreads();   // H1 reads + epilogue STS done
        if (tid == 0) {    // next tile's k-half1 (t=2 -> proj.h1); overlaps next compute
            MBARRIER_EXPECT_TX(mb1, 16384);
            CPA_BULK(bH1A, g_wtile + (t + 1) * 32768 + 16384, 16384, mb1);
        }
    }
    // q/k/v ready (q pre-scaled, biases folded); proj halves in flight

    // ---------------- attention: per-h2 register pipeline ----------------
    const int arow = rb * 16 + (lane & 15);
    const uint32_t axor = (uint32_t)(arow & 7);
    const __half2* cmw = reinterpret_cast<const __half2*>(g_cm)
                       + ((long long)(b % nwin) * 28) * 256 + tid;
    const int r0l = rb * 16 + (lane >> 2);

    #pragma unroll
    for (int h2 = 0; h2 < 2; ++h2) {
        const int h = cp * 2 + h2;

        // -- scores --
        float sacc[7][4];
        #pragma unroll
        for (int bk = 0; bk < 7; ++bk)
            #pragma unroll
            for (int j = 0; j < 4; ++j) sacc[bk][j] = 0.f;
        #pragma unroll
        for (int kk = 0; kk < 2; ++kk) {
            uint32_t achunk = (uint32_t)(h * 4 + kk * 2 + (lane >> 4));
            uint32_t ao = (uint32_t)arow * 256 + ((achunk ^ axor) << 4);
            uint32_t qh_[4];
            ldsm4(qh_, qhiA + ao);
            #pragma unroll
            for (int g = 0; g < 4; ++g) {
                int bn = g * 16 + (lane & 7) + ((lane >> 4) << 3);
                uint32_t bchunk = (uint32_t)(h * 4 + kk * 2 + ((lane >> 3) & 1));
                uint32_t bo = (uint32_t)bn * 256 + ((bchunk ^ (uint32_t)(bn & 7)) << 4);
                uint32_t kh_[4];
                ldsm4(kh_, khiA + bo);
                mma_f16(sacc[2 * g], qh_, kh_[0], kh_[1]);
                if (2 * g + 1 < 7)
                    mma_f16(sacc[2 * g + 1], qh_, kh_[2], kh_[3]);
            }
        }

        // -- softmax (fragment-local, cm from baked table) --
        float sum0 = 0.f, sum1 = 0.f;
        #pragma unroll
        for (int bk = 0; bk < 7; ++bk) {
            float2 c0 = __half22float2(__ldg(&cmw[((h2 * 7 + bk) * 2 + 0) * 256]));
            float2 c1 = __half22float2(__ldg(&cmw[((h2 * 7 + bk) * 2 + 1) * 256]));
            float e00 = __expf(sacc[bk][0] + c0.x);
            float e01 = __expf(sacc[bk][1] + c0.y);
            float e10 = __expf(sacc[bk][2] + c1.x);
            float e11 = __expf(sacc[bk][3] + c1.y);
            sum0 += e00 + e01;
            sum1 += e10 + e11;
            sacc[bk][0] = e00; sacc[bk][1] = e01;
            sacc[bk][2] = e10; sacc[bk][3] = e11;
        }
        sum0 += __shfl_xor_sync(0xffffffffu, sum0, 1);
        sum0 += __shfl_xor_sync(0xffffffffu, sum0, 2);
        sum1 += __shfl_xor_sync(0xffffffffu, sum1, 1);
        sum1 += __shfl_xor_sync(0xffffffffu, sum1, 2);
        const float inv0 = 1.0f / sum0;
        const float inv1 = 1.0f / sum1;

        // -- PV: A = P fragments built in registers (D-frag == A-frag layout) --
        float pacc[4][4];
        #pragma unroll
        for (int nb = 0; nb < 4; ++nb)
            #pragma unroll
            for (int j = 0; j < 4; ++j) pacc[nb][j] = 0.f;

        #pragma unroll
        for (int kc = 0; kc < 4; ++kc) {
            uint32_t pa[4];
            pa[0] = packh2(sacc[2 * kc][0] * inv0, sacc[2 * kc][1] * inv0);
            pa[1] = packh2(sacc[2 * kc][2] * inv1, sacc[2 * kc][3] * inv1);
            if (2 * kc + 1 < 7) {
                pa[2] = packh2(sacc[2 * kc + 1][0] * inv0, sacc[2 * kc + 1][1] * inv0);
                pa[3] = packh2(sacc[2 * kc + 1][2] * inv1, sacc[2 * kc + 1][3] * inv1);
            } else {
                pa[2] = 0u; pa[3] = 0u;      // j in [56,64): padded, P = 0
            }
            #pragma unroll
            for (int g = 0; g < 2; ++g) {
                int vr = kc * 16 + ((lane >> 3) & 1) * 8 + (lane & 7);
                uint32_t vchunk = (uint32_t)(h * 4 + g * 2 + (lane >> 4));
                uint32_t vo = (uint32_t)vr * 256 + ((vchunk ^ (uint32_t)(vr & 7)) << 4);
                uint32_t vh_[4];
                ldsm4t(vh_, vhiA + vo);
                mma_f16(pacc[2 * g],     pa, vh_[0], vh_[1]);
                mma_f16(pacc[2 * g + 1], pa, vh_[2], vh_[3]);
            }
        }

        // -- attn-out (hi only) -> xhi (dead after qkv GEMMs) --
        #pragma unroll
        for (int nb = 0; nb < 4; ++nb) {
            int d0 = nb * 8 + (lane & 3) * 2;
            store2(pacc[nb][0], pacc[nb][1], xhi, toff(r0l,     h * HD + d0));
            store2(pacc[nb][2], pacc[nb][3], xhi, toff(r0l + 8, h * HD + d0));
        }
    }
    __syncthreads();   // attn-out visible

    // ---------------- proj GEMM (A = attn-out in xhi, 1-term) -> global ----------------
    {
        float acc[2][4][4];
        #pragma unroll
        for (int f = 0; f < 2; ++f)
            #pragma unroll
            for (int n = 0; n < 4; ++n)
                #pragma unroll
                for (int j = 0; j < 4; ++j) acc[f][n][j] = 0.f;

        MBARRIER_WAIT_PARITY(mb0, 1);      // proj k-half0 landed (4th wait)
        mma_half(xhiA, bH0A, 0, rb2, cq, lane, acc);
        MBARRIER_WAIT_PARITY(mb1, 1);      // proj k-half1 landed
        mma_half(xhiA, bH1A, 1, rb2, cq, lane, acc);

        float* dstbase = out + (long long)b * (NT * DIMC);
        #pragma unroll
        for (int f = 0; f < 2; ++f) {
            #pragma unroll
            for (int nb = 0; nb < 4; ++nb) {
                int n0 = cq * 32 + nb * 8 + (lane & 3) * 2;
                int r0 = rb2 * 32 + f * 16 + (lane >> 2);
                const float bb0 = s_bias[3 * DIMC + n0];
                const float bb1 = s_bias[3 * DIMC + n0 + 1];
                if (r0 < NT) {
                    float* p = dstbase + r0 * DIMC + n0;
                    p[0] = acc[f][nb][0] + bb0;
                    p[1] = acc[f][nb][1] + bb1;
                }
                if (r0 + 8 < NT) {
                    float* p = dstbase + (r0 + 8) * DIMC + n0;
                    p[0] = acc[f][nb][2] + bb0;
                    p[1] = acc[f][nb][3] + bb1;
                }
            }
        }
    }
}

extern "C" void kernel_launch(void* const* d_in, const int* in_sizes, int n_in,
                              void* d_out, int out_size) {
    const float* x      = (const float*)d_in[0];
    const float* mask   = (const float*)d_in[1];
    const float* qkv_w  = (const float*)d_in[2];
    const float* qkv_b  = (const float*)d_in[3];
    const float* proj_w = (const float*)d_in[4];
    const float* proj_b = (const float*)d_in[5];
    const float* bt     = (const float*)d_in[6];
    float* out = (float*)d_out;

    const int B    = in_sizes[0] / (NT * DIMC);   // 4096
    const int nwin = in_sizes[1] / (NT * NT);     // 64

    prep_kernel<<<512, 256>>>(qkv_w, proj_w, mask, bt, nwin > 0 ? nwin : 1);

    cudaFuncSetAttribute(winattn_kernel,
                         cudaFuncAttributeMaxDynamicSharedMemorySize, SMEM_BYTES);
    winattn_kernel<<<B, THREADS, SMEM_BYTES>>>(x, qkv_b, proj_b, out, B > 0 ? nwin : 1);
}